// round 1
// baseline (speedup 1.0000x reference)
#include <cuda_runtime.h>

// Problem constants
#define NTOT 2304      // H*W
#define BDIM 4
#define CDIM 512
#define DQD  64
#define HW   48

// GEMM tile config: 128x64 tile, BK=16, 256 threads, 8x4 per thread
#define BM 128
#define BN 64
#define BK 16
#define PAD 4

// ---------------- scratch (device globals; no allocation) ----------------
__device__ float g_q [BDIM*DQD*NTOT];
__device__ float g_k [BDIM*DQD*NTOT];
__device__ float g_v [BDIM*CDIM*NTOT];
__device__ float g_p [(size_t)BDIM*NTOT*NTOT];   // exp(e - rowmax), in place
__device__ float g_inv0[BDIM*NTOT];
__device__ float g_inv1[BDIM*NTOT];
__device__ float g_inv2[BDIM*NTOT];
__device__ float g_y [BDIM*CDIM*NTOT];   // residual-added attention output
__device__ float g_t1[BDIM*CDIM*NTOT];   // conv1 output
__device__ float g_t2[BDIM*CDIM*NTOT];   // conv2 output
__device__ float g_gt[BDIM*CDIM*NTOT];   // sigmoid gemm output
__device__ float g_s [BDIM*CDIM*NTOT];   // gated features

// ---------------- GEMM: C[i,j] = sum_k A[i,k]*B[k,j] + bias[i] ----------------
// A row-major [M,K], B k-major [K, NTOT] per batch, C [M, NTOT] per batch.
__global__ __launch_bounds__(256) void gemm_nn_bias(
    const float* __restrict__ A, const float* __restrict__ B,
    const float* __restrict__ bias, float* __restrict__ Cout,
    int M, int K, size_t strideB, size_t strideC)
{
    __shared__ float As[BK][BM+PAD];
    __shared__ float Bs[BK][BN+PAD];
    const int tid = threadIdx.x;
    const int ty = tid >> 4, tx = tid & 15;
    const float* Bp = B + (size_t)blockIdx.z * strideB;
    float* Cp = Cout + (size_t)blockIdx.z * strideC;
    const int rowBase = blockIdx.y * BM;
    const int colBase = blockIdx.x * BN;

    float acc[8][4];
#pragma unroll
    for (int i = 0; i < 8; i++)
#pragma unroll
        for (int j = 0; j < 4; j++) acc[i][j] = 0.f;

    for (int k0 = 0; k0 < K; k0 += BK) {
#pragma unroll
        for (int s = 0; s < 8; s++) {
            int idx = tid + s * 256;
            int kk = idx & 15, ii = idx >> 4;
            int gr = rowBase + ii;
            As[kk][ii] = (gr < M) ? A[(size_t)gr * K + k0 + kk] : 0.f;
        }
#pragma unroll
        for (int s = 0; s < 4; s++) {
            int idx = tid + s * 256;
            int jj = idx & 63, kk = idx >> 6;
            Bs[kk][jj] = Bp[(size_t)(k0 + kk) * NTOT + colBase + jj];
        }
        __syncthreads();
#pragma unroll
        for (int kk = 0; kk < BK; kk++) {
            float a[8], bb[4];
            *(float4*)&a[0] = *(const float4*)&As[kk][ty * 8];
            *(float4*)&a[4] = *(const float4*)&As[kk][ty * 8 + 4];
            *(float4*)&bb[0] = *(const float4*)&Bs[kk][tx * 4];
#pragma unroll
            for (int i = 0; i < 8; i++)
#pragma unroll
                for (int j = 0; j < 4; j++) acc[i][j] = fmaf(a[i], bb[j], acc[i][j]);
        }
        __syncthreads();
    }
#pragma unroll
    for (int i = 0; i < 8; i++) {
        int gr = rowBase + ty * 8 + i;
        if (gr < M) {
            float bv = bias ? bias[gr] : 0.f;
            size_t base = (size_t)gr * NTOT + colBase + tx * 4;
#pragma unroll
            for (int j = 0; j < 4; j++) Cp[base + j] = acc[i][j] + bv;
        }
    }
}

// ---------------- GEMM TN: C[m,n] = sum_d A[d,m]*B[d,n]  (energy) ----------------
__global__ __launch_bounds__(256) void gemm_tn(
    const float* __restrict__ A, const float* __restrict__ B, float* __restrict__ Cout,
    int M, int K, size_t strideA, size_t strideB, size_t strideC)
{
    __shared__ float As[BK][BM+PAD];
    __shared__ float Bs[BK][BN+PAD];
    const int tid = threadIdx.x;
    const int ty = tid >> 4, tx = tid & 15;
    const float* Ap = A + (size_t)blockIdx.z * strideA;
    const float* Bp = B + (size_t)blockIdx.z * strideB;
    float* Cp = Cout + (size_t)blockIdx.z * strideC;
    const int rowBase = blockIdx.y * BM;
    const int colBase = blockIdx.x * BN;

    float acc[8][4];
#pragma unroll
    for (int i = 0; i < 8; i++)
#pragma unroll
        for (int j = 0; j < 4; j++) acc[i][j] = 0.f;

    for (int k0 = 0; k0 < K; k0 += BK) {
#pragma unroll
        for (int s = 0; s < 8; s++) {
            int idx = tid + s * 256;
            int ii = idx & 127, kk = idx >> 7;
            As[kk][ii] = Ap[(size_t)(k0 + kk) * M + rowBase + ii];
        }
#pragma unroll
        for (int s = 0; s < 4; s++) {
            int idx = tid + s * 256;
            int jj = idx & 63, kk = idx >> 6;
            Bs[kk][jj] = Bp[(size_t)(k0 + kk) * NTOT + colBase + jj];
        }
        __syncthreads();
#pragma unroll
        for (int kk = 0; kk < BK; kk++) {
            float a[8], bb[4];
            *(float4*)&a[0] = *(const float4*)&As[kk][ty * 8];
            *(float4*)&a[4] = *(const float4*)&As[kk][ty * 8 + 4];
            *(float4*)&bb[0] = *(const float4*)&Bs[kk][tx * 4];
#pragma unroll
            for (int i = 0; i < 8; i++)
#pragma unroll
                for (int j = 0; j < 4; j++) acc[i][j] = fmaf(a[i], bb[j], acc[i][j]);
        }
        __syncthreads();
    }
#pragma unroll
    for (int i = 0; i < 8; i++) {
        int gr = rowBase + ty * 8 + i;
        size_t base = (size_t)gr * NTOT + colBase + tx * 4;
#pragma unroll
        for (int j = 0; j < 4; j++) Cp[base + j] = acc[i][j];
    }
}

// ------- softmax rows: in-place exp(e-max), three masked reciprocal sums -------
__global__ __launch_bounds__(256) void softmax_rows(
    float* __restrict__ P, float* __restrict__ inv0,
    float* __restrict__ inv1, float* __restrict__ inv2)
{
    __shared__ float red[256];
    const int row = blockIdx.x, b = blockIdx.y, tid = threadIdx.x;
    float* p = P + ((size_t)b * NTOT + row) * NTOT;

    float mx = -1e30f;
    for (int n = tid; n < NTOT; n += 256) mx = fmaxf(mx, p[n]);
    red[tid] = mx; __syncthreads();
    for (int s = 128; s > 0; s >>= 1) { if (tid < s) red[tid] = fmaxf(red[tid], red[tid + s]); __syncthreads(); }
    mx = red[0];
    __syncthreads();

    const int rm = row / HW, cm = row - rm * HW;
    float s0 = 0.f, s1 = 0.f, s2 = 0.f;
    for (int n = tid; n < NTOT; n += 256) {
        float e = __expf(p[n] - mx);
        p[n] = e;
        s0 += e;
        int rn = n / HW, cn = n - rn * HW;
        int dr = rm - rn; dr = dr < 0 ? -dr : dr;
        int dc = cm - cn; dc = dc < 0 ? -dc : dc;
        int d = dr > dc ? dr : dc;
        if (d <= 12) { s2 += e; if (d <= 6) s1 += e; }
    }
    red[tid] = s0; __syncthreads();
    for (int s = 128; s > 0; s >>= 1) { if (tid < s) red[tid] += red[tid + s]; __syncthreads(); }
    if (tid == 0) inv0[(size_t)b * NTOT + row] = 1.f / red[0];
    __syncthreads();
    red[tid] = s1; __syncthreads();
    for (int s = 128; s > 0; s >>= 1) { if (tid < s) red[tid] += red[tid + s]; __syncthreads(); }
    if (tid == 0) inv1[(size_t)b * NTOT + row] = 1.f / red[0];
    __syncthreads();
    red[tid] = s2; __syncthreads();
    for (int s = 128; s > 0; s >>= 1) { if (tid < s) red[tid] += red[tid + s]; __syncthreads(); }
    if (tid == 0) inv2[(size_t)b * NTOT + row] = 1.f / red[0];
}

// ---- attention output GEMM (NT): Out[c,m] = gamma*inv[m]*sum_n A[c,n]*P[m,n] + Res[c,m]
// RADIUS < 0: dense.  RADIUS >= 0: banded k-loop + on-the-fly Chebyshev mask.
template<int RADIUS>
__global__ __launch_bounds__(256) void gemm_nt_attn(
    const float* __restrict__ A,      // [B, C, N]
    const float* __restrict__ P,      // [B, N, N]
    const float* __restrict__ invsum, // [B, N]
    const float* __restrict__ gammaPtr,
    const float* __restrict__ Res,    // [B, C, N]
    float* __restrict__ Out)          // [B, C, N]
{
    __shared__ float As[BK][BM+PAD];
    __shared__ float Bs[BK][BN+PAD];
    const int tid = threadIdx.x;
    const int ty = tid >> 4, tx = tid & 15;
    const int b = blockIdx.z;
    const float* Ap = A + (size_t)b * CDIM * NTOT;
    const float* Pp = P + (size_t)b * NTOT * NTOT;
    const float* Rp = Res + (size_t)b * CDIM * NTOT;
    float* Op = Out + (size_t)b * CDIM * NTOT;
    const int rowBase = blockIdx.y * BM;   // c
    const int colBase = blockIdx.x * BN;   // m

    int kStart = 0, kEnd = NTOT;
    if (RADIUS >= 0) {
        int rmLo = colBase / HW;
        int rmHi = (colBase + BN - 1) / HW;
        int rlo = rmLo - RADIUS; if (rlo < 0) rlo = 0;
        int rhi = rmHi + RADIUS; if (rhi > HW - 1) rhi = HW - 1;
        kStart = rlo * HW; kEnd = (rhi + 1) * HW;
    }

    float acc[8][4];
#pragma unroll
    for (int i = 0; i < 8; i++)
#pragma unroll
        for (int j = 0; j < 4; j++) acc[i][j] = 0.f;

    for (int k0 = kStart; k0 < kEnd; k0 += BK) {
#pragma unroll
        for (int s = 0; s < 8; s++) {
            int idx = tid + s * 256;
            int kk = idx & 15, ii = idx >> 4;
            As[kk][ii] = Ap[(size_t)(rowBase + ii) * NTOT + k0 + kk];
        }
#pragma unroll
        for (int s = 0; s < 4; s++) {
            int idx = tid + s * 256;
            int kk = idx & 15, jj = idx >> 4;
            int gm = colBase + jj, gn = k0 + kk;
            float val = Pp[(size_t)gm * NTOT + gn];
            if (RADIUS >= 0) {
                int dr = gm / HW - gn / HW; dr = dr < 0 ? -dr : dr;
                int dc = gm % HW - gn % HW; dc = dc < 0 ? -dc : dc;
                int d = dr > dc ? dr : dc;
                if (d > RADIUS) val = 0.f;
            }
            Bs[kk][jj] = val;
        }
        __syncthreads();
#pragma unroll
        for (int kk = 0; kk < BK; kk++) {
            float a[8], bb[4];
            *(float4*)&a[0] = *(const float4*)&As[kk][ty * 8];
            *(float4*)&a[4] = *(const float4*)&As[kk][ty * 8 + 4];
            *(float4*)&bb[0] = *(const float4*)&Bs[kk][tx * 4];
#pragma unroll
            for (int i = 0; i < 8; i++)
#pragma unroll
                for (int j = 0; j < 4; j++) acc[i][j] = fmaf(a[i], bb[j], acc[i][j]);
        }
        __syncthreads();
    }

    const float g = *gammaPtr;
    float sc[4];
#pragma unroll
    for (int j = 0; j < 4; j++) sc[j] = g * invsum[(size_t)b * NTOT + colBase + tx * 4 + j];
#pragma unroll
    for (int i = 0; i < 8; i++) {
        int gr = rowBase + ty * 8 + i;
        size_t base = (size_t)gr * NTOT + colBase + tx * 4;
#pragma unroll
        for (int j = 0; j < 4; j++) Op[base + j] = acc[i][j] * sc[j] + Rp[base + j];
    }
}

// ------ conv3x3 (SAME) + BN + ReLU as implicit GEMM: M=512, K=4608, N=2304 ------
__global__ __launch_bounds__(256) void conv3x3_bn_relu(
    const float* __restrict__ Wt,   // [512, 512*9] (OIHW flattened)
    const float* __restrict__ X,    // [B, 512, 48, 48]
    const float* __restrict__ bnw, const float* __restrict__ bnb,
    const float* __restrict__ bnm, const float* __restrict__ bnv,
    float* __restrict__ Out)
{
    __shared__ float As[BK][BM+PAD];
    __shared__ float Bs[BK][BN+PAD];
    const int tid = threadIdx.x;
    const int ty = tid >> 4, tx = tid & 15;
    const float* Xp = X + (size_t)blockIdx.z * CDIM * NTOT;
    float* Op = Out + (size_t)blockIdx.z * CDIM * NTOT;
    const int rowBase = blockIdx.y * BM;
    const int colBase = blockIdx.x * BN;
    const int K = CDIM * 9;

    float acc[8][4];
#pragma unroll
    for (int i = 0; i < 8; i++)
#pragma unroll
        for (int j = 0; j < 4; j++) acc[i][j] = 0.f;

    for (int k0 = 0; k0 < K; k0 += BK) {
#pragma unroll
        for (int s = 0; s < 8; s++) {
            int idx = tid + s * 256;
            int kk = idx & 15, ii = idx >> 4;
            As[kk][ii] = Wt[(size_t)(rowBase + ii) * K + k0 + kk];
        }
#pragma unroll
        for (int s = 0; s < 4; s++) {
            int idx = tid + s * 256;
            int jj = idx & 63, kk = idx >> 6;
            int kidx = k0 + kk;
            int ic = kidx / 9;
            int t  = kidx - ic * 9;
            int ky = t / 3, kx = t - ky * 3;
            int jpix = colBase + jj;
            int py = jpix / HW, px = jpix - py * HW;
            int iy = py + ky - 1, ix = px + kx - 1;
            float v = 0.f;
            if ((unsigned)iy < HW && (unsigned)ix < HW)
                v = Xp[(size_t)ic * NTOT + iy * HW + ix];
            Bs[kk][jj] = v;
        }
        __syncthreads();
#pragma unroll
        for (int kk = 0; kk < BK; kk++) {
            float a[8], bb[4];
            *(float4*)&a[0] = *(const float4*)&As[kk][ty * 8];
            *(float4*)&a[4] = *(const float4*)&As[kk][ty * 8 + 4];
            *(float4*)&bb[0] = *(const float4*)&Bs[kk][tx * 4];
#pragma unroll
            for (int i = 0; i < 8; i++)
#pragma unroll
                for (int j = 0; j < 4; j++) acc[i][j] = fmaf(a[i], bb[j], acc[i][j]);
        }
        __syncthreads();
    }
#pragma unroll
    for (int i = 0; i < 8; i++) {
        int oc = rowBase + ty * 8 + i;
        float scale = bnw[oc] * rsqrtf(bnv[oc] + 1e-5f);
        float shift = bnb[oc] - bnm[oc] * scale;
        size_t base = (size_t)oc * NTOT + colBase + tx * 4;
#pragma unroll
        for (int j = 0; j < 4; j++)
            Op[base + j] = fmaxf(acc[i][j] * scale + shift, 0.f);
    }
}

// ------------- s = t * sigmoid(g) -------------
__global__ __launch_bounds__(256) void gate_kernel(
    const float* __restrict__ g, const float* __restrict__ t,
    float* __restrict__ s, int total)
{
    int i = blockIdx.x * blockDim.x + threadIdx.x;
    if (i < total) {
        float gv = g[i];
        s[i] = t[i] * (1.f / (1.f + __expf(-gv)));
    }
}

// ---------------- launch ----------------
extern "C" void kernel_launch(void* const* d_in, const int* in_sizes, int n_in,
                              void* d_out, int out_size)
{
    const float* x       = (const float*)d_in[0];
    const float* Wq      = (const float*)d_in[1];
    const float* bq      = (const float*)d_in[2];
    const float* Wk      = (const float*)d_in[3];
    const float* bk      = (const float*)d_in[4];
    const float* Wv      = (const float*)d_in[5];
    const float* bv      = (const float*)d_in[6];
    const float* conv1_w = (const float*)d_in[7];
    const float* bn1_w   = (const float*)d_in[8];
    const float* bn1_b   = (const float*)d_in[9];
    const float* bn1_m   = (const float*)d_in[10];
    const float* bn1_v   = (const float*)d_in[11];
    const float* conv2_w = (const float*)d_in[12];
    const float* bn2_w   = (const float*)d_in[13];
    const float* bn2_b   = (const float*)d_in[14];
    const float* bn2_m   = (const float*)d_in[15];
    const float* bn2_v   = (const float*)d_in[16];
    const float* sig1_w  = (const float*)d_in[17];
    const float* sig1_b  = (const float*)d_in[18];
    const float* sig2_w  = (const float*)d_in[19];
    const float* sig2_b  = (const float*)d_in[20];
    const float* gamma   = (const float*)d_in[21];
    const float* gamma1  = (const float*)d_in[22];
    const float* gamma2  = (const float*)d_in[23];
    // masks (d_in[24], d_in[25]) intentionally unused: recomputed on the fly

    float *q, *k, *v, *p, *i0, *i1, *i2, *y, *t1, *t2, *gt, *s;
    cudaGetSymbolAddress((void**)&q,  g_q);
    cudaGetSymbolAddress((void**)&k,  g_k);
    cudaGetSymbolAddress((void**)&v,  g_v);
    cudaGetSymbolAddress((void**)&p,  g_p);
    cudaGetSymbolAddress((void**)&i0, g_inv0);
    cudaGetSymbolAddress((void**)&i1, g_inv1);
    cudaGetSymbolAddress((void**)&i2, g_inv2);
    cudaGetSymbolAddress((void**)&y,  g_y);
    cudaGetSymbolAddress((void**)&t1, g_t1);
    cudaGetSymbolAddress((void**)&t2, g_t2);
    cudaGetSymbolAddress((void**)&gt, g_gt);
    cudaGetSymbolAddress((void**)&s,  g_s);

    const dim3 blk(256);
    const dim3 gSmall(NTOT / BN, 1, BDIM);              // M=64
    const dim3 gFull (NTOT / BN, CDIM / BM, BDIM);      // M=512
    const dim3 gEnergy(NTOT / BN, NTOT / BM, BDIM);     // M=2304
    const size_t sX = (size_t)CDIM * NTOT;
    const size_t sQ = (size_t)DQD * NTOT;
    const size_t sP = (size_t)NTOT * NTOT;
    const int total = BDIM * CDIM * NTOT;

    // q, k, v projections
    gemm_nn_bias<<<gSmall, blk>>>(Wq, x, bq, q, DQD, CDIM, sX, sQ);
    gemm_nn_bias<<<gSmall, blk>>>(Wk, x, bk, k, DQD, CDIM, sX, sQ);
    gemm_nn_bias<<<gFull,  blk>>>(Wv, x, bv, v, CDIM, CDIM, sX, sX);

    // energy = q^T k
    gemm_tn<<<gEnergy, blk>>>(q, k, p, NTOT, DQD, sQ, sQ, sP);

    // exp + three masked reciprocal sums
    softmax_rows<<<dim3(NTOT, BDIM), blk>>>(p, i0, i1, i2);

    // stage 0: dense attention + residual
    gemm_nt_attn<-1><<<gFull, blk>>>(v, p, i0, gamma, x, y);
    conv3x3_bn_relu<<<gFull, blk>>>(conv1_w, y, bn1_w, bn1_b, bn1_m, bn1_v, t1);

    // stage 1: gate, banded attention (R=6) + residual
    gemm_nn_bias<<<gFull, blk>>>(sig1_w, t1, sig1_b, gt, CDIM, CDIM, sX, sX);
    gate_kernel<<<(total + 255) / 256, blk>>>(gt, t1, s, total);
    gemm_nt_attn<6><<<gFull, blk>>>(s, p, i1, gamma1, t1, y);
    conv3x3_bn_relu<<<gFull, blk>>>(conv2_w, y, bn2_w, bn2_b, bn2_m, bn2_v, t2);

    // stage 2: gate, banded attention (R=12) + residual -> output
    gemm_nn_bias<<<gFull, blk>>>(sig2_w, t2, sig2_b, gt, CDIM, CDIM, sX, sX);
    gate_kernel<<<(total + 255) / 256, blk>>>(gt, t2, s, total);
    gemm_nt_attn<12><<<gFull, blk>>>(s, p, i2, gamma2, t2, (float*)d_out);
}

// round 3
// speedup vs baseline: 2.3885x; 2.3885x over previous
#include <cuda_runtime.h>
#include <stdint.h>

#define NTOT 2304
#define BDIM 4
#define CDIM 512
#define DQD  64
#define HW   48

// ---------------- fp32 tile config (small kernels) ----------------
#define BM 128
#define BN 64
#define BK 16
#define PAD 4

// ---------------- mma.sync tf32 tile config ----------------
#define TCM 128
#define TCN 128
#define TCK 32                       // k floats per chunk (=128B row)
#define TILE_BYTES (TCM * TCK * 4)   // 16384
#define SMEM_TC_SZ (2048 + 4 * TILE_BYTES)

#define SWZ(off) ((off) ^ (((off) >> 3) & 0x70))

// ---------------- scratch ----------------
__device__ float g_q [BDIM*DQD*NTOT];
__device__ float g_k [BDIM*DQD*NTOT];
__device__ float g_v [BDIM*CDIM*NTOT];
__device__ float g_p [(size_t)BDIM*NTOT*NTOT];
__device__ float g_inv0[BDIM*NTOT];
__device__ float g_inv1[BDIM*NTOT];
__device__ float g_inv2[BDIM*NTOT];
__device__ float g_y [BDIM*CDIM*NTOT];
__device__ float g_t1[BDIM*CDIM*NTOT];
__device__ float g_t2[BDIM*CDIM*NTOT];
__device__ float g_s [BDIM*CDIM*NTOT];

// ---------------- helpers ----------------
__device__ __forceinline__ uint32_t smem_u32(const void* p) {
    return (uint32_t)__cvta_generic_to_shared(p);
}
__device__ __forceinline__ uint32_t cvt_tf32(float v) {
    uint32_t o;
    asm("cvt.rna.tf32.f32 %0, %1;" : "=r"(o) : "f"(v));
    return o;
}
__device__ __forceinline__ uint4 cvt_tf32x4(float4 v) {
    uint4 o;
    o.x = cvt_tf32(v.x); o.y = cvt_tf32(v.y);
    o.z = cvt_tf32(v.z); o.w = cvt_tf32(v.w);
    return o;
}
__device__ __forceinline__ void ldsm4(uint32_t* r, uint32_t addr) {
    asm volatile("ldmatrix.sync.aligned.m8n8.x4.shared.b16 {%0,%1,%2,%3}, [%4];"
        : "=r"(r[0]), "=r"(r[1]), "=r"(r[2]), "=r"(r[3]) : "r"(addr));
}
__device__ __forceinline__ void mma1688(float* c, const uint32_t* a, const uint32_t* b) {
    asm volatile("mma.sync.aligned.m16n8k8.row.col.f32.tf32.tf32.f32 "
        "{%0,%1,%2,%3}, {%4,%5,%6,%7}, {%8,%9}, {%0,%1,%2,%3};"
        : "+f"(c[0]), "+f"(c[1]), "+f"(c[2]), "+f"(c[3])
        : "r"(a[0]), "r"(a[1]), "r"(a[2]), "r"(a[3]), "r"(b[0]), "r"(b[1]));
}

// compute one 128x128x32 chunk: acc[mt][nt][4] += A_tile * B_tile^T
__device__ __forceinline__ void mma_chunk(
    uint32_t aT, uint32_t bT,
    const uint32_t aRow[2], const uint32_t bRow[4],
    uint32_t aKsel, uint32_t bKsel, uint32_t xorv,
    float (&acc)[2][8][4])
{
#pragma unroll
    for (int kk = 0; kk < 4; kk++) {
        uint32_t kbA = ((uint32_t)(kk * 32 + aKsel)) ^ xorv;
        uint32_t kbB = ((uint32_t)(kk * 32 + bKsel)) ^ xorv;
        uint32_t af[2][4];
#pragma unroll
        for (int mt = 0; mt < 2; mt++) ldsm4(af[mt], aT + aRow[mt] + kbA);
#pragma unroll
        for (int p = 0; p < 4; p++) {
            uint32_t bf[4];
            ldsm4(bf, bT + bRow[p] + kbB);
#pragma unroll
            for (int mt = 0; mt < 2; mt++) {
                mma1688(acc[mt][2 * p],     af[mt], bf);
                mma1688(acc[mt][2 * p + 1], af[mt], bf + 2);
            }
        }
    }
}

// Common per-thread precompute (4x2 warp grid, warp tile 32x64)
#define MMA_PRECOMP() \
    const int lane = tid & 31, wid = tid >> 5; \
    const int wm = wid >> 1, wn = wid & 1; \
    const int jj = lane >> 3, rr = lane & 7; \
    const uint32_t xorv = rr * 16; \
    uint32_t aRow[2], bRow[4]; \
    aRow[0] = (wm * 32 +      (jj & 1) * 8 + rr) * 128; \
    aRow[1] = aRow[0] + 16 * 128; \
    const uint32_t aKsel = (jj >> 1) * 16; \
    const uint32_t bKsel = (jj & 1) * 16; \
    bRow[0] = (wn * 64 +      (jj >> 1) * 8 + rr) * 128; \
    bRow[1] = bRow[0] + 16 * 128; \
    bRow[2] = bRow[0] + 32 * 128; \
    bRow[3] = bRow[0] + 48 * 128; \
    const int col4 = tid & 7; \
    const int iiBase = tid >> 3; \
    float acc[2][8][4]; \
_Pragma("unroll") \
    for (int i = 0; i < 2; i++) \
_Pragma("unroll") \
        for (int j = 0; j < 8; j++) \
_Pragma("unroll") \
            for (int e = 0; e < 4; e++) acc[i][j][e] = 0.f;

// ================= tc_attn: Out[c,m] = g*inv[m]*sum_n A[c,n]*mask(P[m,n]) + Res[c,m] =================
template<int RADIUS>
__global__ __launch_bounds__(256) void tc_attn(
    const float* __restrict__ A, const float* __restrict__ P,
    const float* __restrict__ invsum, const float* __restrict__ gammaPtr,
    const float* __restrict__ Res, float* __restrict__ Out)
{
    extern __shared__ char smem[];
    uint32_t sb = smem_u32(smem);
    float* smf = (float*)smem;          // inv cache: 128 floats at offset 0
    const int tid = threadIdx.x;
    const int bz = blockIdx.z;
    const float* Ap = A + (size_t)bz * CDIM * NTOT;
    const float* Pp = P + (size_t)bz * NTOT * NTOT;
    const float* Rp = Res + (size_t)bz * CDIM * NTOT;
    float* Op = Out + (size_t)bz * CDIM * NTOT;
    const int rowBase = blockIdx.y * TCM;
    const int colBase = blockIdx.x * TCN;

    uint32_t tilesAddr = (sb + 1024 + 1023) & ~1023u;
    char* tiles = smem + (tilesAddr - sb);
    const uint32_t aT[2] = { tilesAddr,              tilesAddr + 2 * TILE_BYTES };
    const uint32_t bT[2] = { tilesAddr + TILE_BYTES, tilesAddr + 3 * TILE_BYTES };

    MMA_PRECOMP();

    if (tid < TCN) smf[tid] = invsum[(size_t)bz * NTOT + colBase + tid];

    int kStart = 0, kEnd = NTOT;
    if (RADIUS >= 0) {
        int rmLo = colBase / HW, rmHi = (colBase + TCN - 1) / HW;
        int rlo = rmLo - RADIUS; if (rlo < 0) rlo = 0;
        int rhi = rmHi + RADIUS; if (rhi > HW - 1) rhi = HW - 1;
        kStart = (rlo * HW) & ~(TCK - 1);
        kEnd = ((rhi + 1) * HW + TCK - 1) & ~(TCK - 1);
        if (kEnd > NTOT) kEnd = NTOT;
    }
    const int NC = (kEnd - kStart) / TCK;

    float4 aR[4], bR[4];
    // loader for chunk ci into regs
    auto loadRegs = [&](int ci) {
        const int k0 = kStart + ci * TCK;
#pragma unroll
        for (int s = 0; s < 4; s++) {
            int ii = iiBase + s * 32;
            aR[s] = *(const float4*)&Ap[(size_t)(rowBase + ii) * NTOT + k0 + col4 * 4];
        }
#pragma unroll
        for (int s = 0; s < 4; s++) {
            int j = iiBase + s * 32;
            int gm = colBase + j;
            float4 vb = *(const float4*)&Pp[(size_t)gm * NTOT + k0 + col4 * 4];
            if (RADIUS >= 0) {
                int rm = gm / HW, cm = gm - rm * HW;
                int gn0 = k0 + col4 * 4;
                float* pe = (float*)&vb;
#pragma unroll
                for (int e = 0; e < 4; e++) {
                    int gn = gn0 + e;
                    int rn = gn / HW, cn = gn - rn * HW;
                    int dr = rm - rn; dr = dr < 0 ? -dr : dr;
                    int dc = cm - cn; dc = dc < 0 ? -dc : dc;
                    if ((dr > dc ? dr : dc) > RADIUS) pe[e] = 0.f;
                }
            }
            bR[s] = vb;
        }
    };
    auto stsRegs = [&](int buf) {
        char* ta = tiles + (buf ? 2 * TILE_BYTES : 0);
        char* tb = ta + TILE_BYTES;
#pragma unroll
        for (int s = 0; s < 4; s++) {
            int ii = iiBase + s * 32;
            *(uint4*)(ta + SWZ(ii * 128 + col4 * 16)) = cvt_tf32x4(aR[s]);
            *(uint4*)(tb + SWZ(ii * 128 + col4 * 16)) = cvt_tf32x4(bR[s]);
        }
    };

    loadRegs(0); stsRegs(0);
    __syncthreads();
    for (int ci = 0; ci < NC; ci++) {
        const int cur = ci & 1;
        if (ci + 1 < NC) loadRegs(ci + 1);
        mma_chunk(aT[cur], bT[cur], aRow, bRow, aKsel, bKsel, xorv, acc);
        if (ci + 1 < NC) { stsRegs(cur ^ 1); __syncthreads(); }
    }

    const float g = *gammaPtr;
#pragma unroll
    for (int mt = 0; mt < 2; mt++) {
        int mloc = wm * 32 + mt * 16 + (lane >> 2);
#pragma unroll
        for (int half = 0; half < 2; half++) {
            int c = rowBase + mloc + half * 8;
            size_t ro = (size_t)c * NTOT;
#pragma unroll
            for (int nt = 0; nt < 8; nt++) {
                int nl = wn * 64 + nt * 8 + (lane & 3) * 2;
                int n = colBase + nl;
                float2 res = *(const float2*)&Rp[ro + n];
                float2 o;
                o.x = acc[mt][nt][half * 2 + 0] * (g * smf[nl])     + res.x;
                o.y = acc[mt][nt][half * 2 + 1] * (g * smf[nl + 1]) + res.y;
                *(float2*)&Op[ro + n] = o;
            }
        }
    }
}

// ================= tc_conv: conv3x3 SAME + BN + ReLU, implicit GEMM K=4608 =================
__global__ __launch_bounds__(256) void tc_conv(
    const float* __restrict__ Wt, const float* __restrict__ X,
    const float* __restrict__ bnw, const float* __restrict__ bnb,
    const float* __restrict__ bnm, const float* __restrict__ bnv,
    float* __restrict__ Out)
{
    extern __shared__ char smem[];
    uint32_t sb = smem_u32(smem);
    const int tid = threadIdx.x;
    const float* Xp = X + (size_t)blockIdx.z * CDIM * NTOT;
    float* Op = Out + (size_t)blockIdx.z * CDIM * NTOT;
    const int rowBase = blockIdx.y * TCM;
    const int colBase = blockIdx.x * TCN;
    const int K = CDIM * 9;

    uint32_t tilesAddr = (sb + 1024 + 1023) & ~1023u;
    char* tiles = smem + (tilesAddr - sb);
    const uint32_t aT[2] = { tilesAddr,              tilesAddr + 2 * TILE_BYTES };
    const uint32_t bT[2] = { tilesAddr + TILE_BYTES, tilesAddr + 3 * TILE_BYTES };

    MMA_PRECOMP();

    // im2col loader hoists
    const int j = tid & 127;
    const int h = tid >> 7;                 // 0/1: which 16-k half
    const int pix = colBase + j;
    const int py = pix / HW, px = pix - py * HW;

    const int NC = K / TCK;   // 144
    float4 aR[4], bR[4];

    auto loadRegs = [&](int ci) {
        const int k0 = ci * TCK;
#pragma unroll
        for (int s = 0; s < 4; s++) {
            int ii = iiBase + s * 32;
            aR[s] = *(const float4*)&Wt[(size_t)(rowBase + ii) * K + k0 + col4 * 4];
        }
#pragma unroll
        for (int t4 = 0; t4 < 4; t4++) {
            int kk0 = 16 * h + t4 * 4;
            float* pe = (float*)&bR[t4];
#pragma unroll
            for (int e = 0; e < 4; e++) {
                int kidx = k0 + kk0 + e;
                int ic = kidx / 9;
                int tt = kidx - ic * 9;
                int ky = tt / 3, kx = tt - ky * 3;
                int iy = py + ky - 1, ix = px + kx - 1;
                float v = 0.f;
                if ((unsigned)iy < HW && (unsigned)ix < HW)
                    v = Xp[(size_t)ic * NTOT + iy * HW + ix];
                pe[e] = v;
            }
        }
    };
    auto stsRegs = [&](int buf) {
        char* ta = tiles + (buf ? 2 * TILE_BYTES : 0);
        char* tb = ta + TILE_BYTES;
#pragma unroll
        for (int s = 0; s < 4; s++) {
            int ii = iiBase + s * 32;
            *(uint4*)(ta + SWZ(ii * 128 + col4 * 16)) = cvt_tf32x4(aR[s]);
        }
#pragma unroll
        for (int t4 = 0; t4 < 4; t4++) {
            int kk0 = 16 * h + t4 * 4;
            *(uint4*)(tb + SWZ(j * 128 + kk0 * 4)) = cvt_tf32x4(bR[t4]);
        }
    };

    loadRegs(0); stsRegs(0);
    __syncthreads();
    for (int ci = 0; ci < NC; ci++) {
        const int cur = ci & 1;
        if (ci + 1 < NC) loadRegs(ci + 1);
        mma_chunk(aT[cur], bT[cur], aRow, bRow, aKsel, bKsel, xorv, acc);
        if (ci + 1 < NC) { stsRegs(cur ^ 1); __syncthreads(); }
    }

#pragma unroll
    for (int mt = 0; mt < 2; mt++) {
        int mloc = wm * 32 + mt * 16 + (lane >> 2);
#pragma unroll
        for (int half = 0; half < 2; half++) {
            int oc = rowBase + mloc + half * 8;
            float scale = bnw[oc] * rsqrtf(bnv[oc] + 1e-5f);
            float shift = bnb[oc] - bnm[oc] * scale;
            size_t ro = (size_t)oc * NTOT;
#pragma unroll
            for (int nt = 0; nt < 8; nt++) {
                int n = colBase + wn * 64 + nt * 8 + (lane & 3) * 2;
                float2 o;
                o.x = fmaxf(acc[mt][nt][half * 2 + 0] * scale + shift, 0.f);
                o.y = fmaxf(acc[mt][nt][half * 2 + 1] * scale + shift, 0.f);
                *(float2*)&Op[ro + n] = o;
            }
        }
    }
}

// ====== tc_nn: C[d,m] = sum_c W[d,c]*X[c,m] + bias[d]; optional fused sigmoid gate ======
__global__ __launch_bounds__(256) void tc_nn(
    const float* __restrict__ W, const float* __restrict__ X,
    const float* __restrict__ bias, const float* __restrict__ gateSrc,
    float* __restrict__ Out, int K)
{
    extern __shared__ char smem[];
    uint32_t sb = smem_u32(smem);
    const int tid = threadIdx.x;
    const float* Xp = X + (size_t)blockIdx.z * K * NTOT;
    const float* Gp = gateSrc ? gateSrc + (size_t)blockIdx.z * CDIM * NTOT : (const float*)0;
    float* Op = Out + (size_t)blockIdx.z * CDIM * NTOT;
    const int rowBase = blockIdx.y * TCM;
    const int colBase = blockIdx.x * TCN;

    uint32_t tilesAddr = (sb + 1024 + 1023) & ~1023u;
    char* tiles = smem + (tilesAddr - sb);
    const uint32_t aT[2] = { tilesAddr,              tilesAddr + 2 * TILE_BYTES };
    const uint32_t bT[2] = { tilesAddr + TILE_BYTES, tilesAddr + 3 * TILE_BYTES };

    MMA_PRECOMP();

    const int kk0 = (tid >> 5) * 4;   // per-warp k-col block for transpose loader
    const int NC = K / TCK;
    float4 aR[4], bR[4];

    auto loadRegs = [&](int ci) {
        const int k0 = ci * TCK;
#pragma unroll
        for (int s = 0; s < 4; s++) {
            int ii = iiBase + s * 32;
            aR[s] = *(const float4*)&W[(size_t)(rowBase + ii) * K + k0 + col4 * 4];
        }
#pragma unroll
        for (int mq = 0; mq < 4; mq++) {
            int jr = lane + 32 * mq;
            bR[mq].x = Xp[(size_t)(k0 + kk0 + 0) * NTOT + colBase + jr];
            bR[mq].y = Xp[(size_t)(k0 + kk0 + 1) * NTOT + colBase + jr];
            bR[mq].z = Xp[(size_t)(k0 + kk0 + 2) * NTOT + colBase + jr];
            bR[mq].w = Xp[(size_t)(k0 + kk0 + 3) * NTOT + colBase + jr];
        }
    };
    auto stsRegs = [&](int buf) {
        char* ta = tiles + (buf ? 2 * TILE_BYTES : 0);
        char* tb = ta + TILE_BYTES;
#pragma unroll
        for (int s = 0; s < 4; s++) {
            int ii = iiBase + s * 32;
            *(uint4*)(ta + SWZ(ii * 128 + col4 * 16)) = cvt_tf32x4(aR[s]);
        }
#pragma unroll
        for (int mq = 0; mq < 4; mq++) {
            int jr = lane + 32 * mq;
            *(uint4*)(tb + SWZ(jr * 128 + kk0 * 4)) = cvt_tf32x4(bR[mq]);
        }
    };

    loadRegs(0); stsRegs(0);
    __syncthreads();
    for (int ci = 0; ci < NC; ci++) {
        const int cur = ci & 1;
        if (ci + 1 < NC) loadRegs(ci + 1);
        mma_chunk(aT[cur], bT[cur], aRow, bRow, aKsel, bKsel, xorv, acc);
        if (ci + 1 < NC) { stsRegs(cur ^ 1); __syncthreads(); }
    }

#pragma unroll
    for (int mt = 0; mt < 2; mt++) {
        int mloc = wm * 32 + mt * 16 + (lane >> 2);
#pragma unroll
        for (int half = 0; half < 2; half++) {
            int d = rowBase + mloc + half * 8;
            float bv = bias[d];
            size_t ro = (size_t)d * NTOT;
#pragma unroll
            for (int nt = 0; nt < 8; nt++) {
                int n = colBase + wn * 64 + nt * 8 + (lane & 3) * 2;
                float2 o;
                o.x = acc[mt][nt][half * 2 + 0] + bv;
                o.y = acc[mt][nt][half * 2 + 1] + bv;
                if (Gp) {
                    float2 gv = *(const float2*)&Gp[ro + n];
                    o.x = gv.x * (1.f / (1.f + __expf(-o.x)));
                    o.y = gv.y * (1.f / (1.f + __expf(-o.y)));
                }
                *(float2*)&Op[ro + n] = o;
            }
        }
    }
}

// ---------------- fp32 kernels kept: q/k projections, energy, softmax ----------------
__global__ __launch_bounds__(256) void gemm_nn_bias(
    const float* __restrict__ A, const float* __restrict__ B,
    const float* __restrict__ bias, float* __restrict__ Cout,
    int M, int K, size_t strideB, size_t strideC)
{
    __shared__ float As[BK][BM+PAD];
    __shared__ float Bs[BK][BN+PAD];
    const int tid = threadIdx.x;
    const int ty = tid >> 4, tx = tid & 15;
    const float* Bp = B + (size_t)blockIdx.z * strideB;
    float* Cp = Cout + (size_t)blockIdx.z * strideC;
    const int rowBase = blockIdx.y * BM;
    const int colBase = blockIdx.x * BN;
    float acc[8][4];
#pragma unroll
    for (int i = 0; i < 8; i++)
#pragma unroll
        for (int j = 0; j < 4; j++) acc[i][j] = 0.f;
    for (int k0 = 0; k0 < K; k0 += BK) {
#pragma unroll
        for (int s = 0; s < 8; s++) {
            int idx = tid + s * 256;
            int kk = idx & 15, ii = idx >> 4;
            int gr = rowBase + ii;
            As[kk][ii] = (gr < M) ? A[(size_t)gr * K + k0 + kk] : 0.f;
        }
#pragma unroll
        for (int s = 0; s < 4; s++) {
            int idx = tid + s * 256;
            int jj = idx & 63, kk = idx >> 6;
            Bs[kk][jj] = Bp[(size_t)(k0 + kk) * NTOT + colBase + jj];
        }
        __syncthreads();
#pragma unroll
        for (int kk = 0; kk < BK; kk++) {
            float a[8], bb[4];
            *(float4*)&a[0] = *(const float4*)&As[kk][ty * 8];
            *(float4*)&a[4] = *(const float4*)&As[kk][ty * 8 + 4];
            *(float4*)&bb[0] = *(const float4*)&Bs[kk][tx * 4];
#pragma unroll
            for (int i = 0; i < 8; i++)
#pragma unroll
                for (int j = 0; j < 4; j++) acc[i][j] = fmaf(a[i], bb[j], acc[i][j]);
        }
        __syncthreads();
    }
#pragma unroll
    for (int i = 0; i < 8; i++) {
        int gr = rowBase + ty * 8 + i;
        if (gr < M) {
            float bv = bias[gr];
            size_t base = (size_t)gr * NTOT + colBase + tx * 4;
#pragma unroll
            for (int j = 0; j < 4; j++) Cp[base + j] = acc[i][j] + bv;
        }
    }
}

__global__ __launch_bounds__(256) void gemm_tn(
    const float* __restrict__ A, const float* __restrict__ B, float* __restrict__ Cout,
    int M, int K, size_t strideA, size_t strideB, size_t strideC)
{
    __shared__ float As[BK][BM+PAD];
    __shared__ float Bs[BK][BN+PAD];
    const int tid = threadIdx.x;
    const int ty = tid >> 4, tx = tid & 15;
    const float* Ap = A + (size_t)blockIdx.z * strideA;
    const float* Bp = B + (size_t)blockIdx.z * strideB;
    float* Cp = Cout + (size_t)blockIdx.z * strideC;
    const int rowBase = blockIdx.y * BM;
    const int colBase = blockIdx.x * BN;
    float acc[8][4];
#pragma unroll
    for (int i = 0; i < 8; i++)
#pragma unroll
        for (int j = 0; j < 4; j++) acc[i][j] = 0.f;
    for (int k0 = 0; k0 < K; k0 += BK) {
#pragma unroll
        for (int s = 0; s < 8; s++) {
            int idx = tid + s * 256;
            int ii = idx & 127, kk = idx >> 7;
            As[kk][ii] = Ap[(size_t)(k0 + kk) * M + rowBase + ii];
        }
#pragma unroll
        for (int s = 0; s < 4; s++) {
            int idx = tid + s * 256;
            int jj = idx & 63, kk = idx >> 6;
            Bs[kk][jj] = Bp[(size_t)(k0 + kk) * NTOT + colBase + jj];
        }
        __syncthreads();
#pragma unroll
        for (int kk = 0; kk < BK; kk++) {
            float a[8], bb[4];
            *(float4*)&a[0] = *(const float4*)&As[kk][ty * 8];
            *(float4*)&a[4] = *(const float4*)&As[kk][ty * 8 + 4];
            *(float4*)&bb[0] = *(const float4*)&Bs[kk][tx * 4];
#pragma unroll
            for (int i = 0; i < 8; i++)
#pragma unroll
                for (int j = 0; j < 4; j++) acc[i][j] = fmaf(a[i], bb[j], acc[i][j]);
        }
        __syncthreads();
    }
#pragma unroll
    for (int i = 0; i < 8; i++) {
        int gr = rowBase + ty * 8 + i;
        size_t base = (size_t)gr * NTOT + colBase + tx * 4;
#pragma unroll
        for (int j = 0; j < 4; j++) Cp[base + j] = acc[i][j];
    }
}

__global__ __launch_bounds__(256) void softmax_rows(
    float* __restrict__ P, float* __restrict__ inv0,
    float* __restrict__ inv1, float* __restrict__ inv2)
{
    __shared__ float red[256];
    const int row = blockIdx.x, b = blockIdx.y, tid = threadIdx.x;
    float* p = P + ((size_t)b * NTOT + row) * NTOT;
    float mx = -1e30f;
    for (int n = tid; n < NTOT; n += 256) mx = fmaxf(mx, p[n]);
    red[tid] = mx; __syncthreads();
    for (int s = 128; s > 0; s >>= 1) { if (tid < s) red[tid] = fmaxf(red[tid], red[tid + s]); __syncthreads(); }
    mx = red[0];
    __syncthreads();
    const int rm = row / HW, cm = row - rm * HW;
    float s0 = 0.f, s1 = 0.f, s2 = 0.f;
    for (int n = tid; n < NTOT; n += 256) {
        float e = __expf(p[n] - mx);
        p[n] = e;
        s0 += e;
        int rn = n / HW, cn = n - rn * HW;
        int dr = rm - rn; dr = dr < 0 ? -dr : dr;
        int dc = cm - cn; dc = dc < 0 ? -dc : dc;
        int d = dr > dc ? dr : dc;
        if (d <= 12) { s2 += e; if (d <= 6) s1 += e; }
    }
    red[tid] = s0; __syncthreads();
    for (int s = 128; s > 0; s >>= 1) { if (tid < s) red[tid] += red[tid + s]; __syncthreads(); }
    if (tid == 0) inv0[(size_t)b * NTOT + row] = 1.f / red[0];
    __syncthreads();
    red[tid] = s1; __syncthreads();
    for (int s = 128; s > 0; s >>= 1) { if (tid < s) red[tid] += red[tid + s]; __syncthreads(); }
    if (tid == 0) inv1[(size_t)b * NTOT + row] = 1.f / red[0];
    __syncthreads();
    red[tid] = s2; __syncthreads();
    for (int s = 128; s > 0; s >>= 1) { if (tid < s) red[tid] += red[tid + s]; __syncthreads(); }
    if (tid == 0) inv2[(size_t)b * NTOT + row] = 1.f / red[0];
}

// ---------------- launch ----------------
extern "C" void kernel_launch(void* const* d_in, const int* in_sizes, int n_in,
                              void* d_out, int out_size)
{
    const float* x       = (const float*)d_in[0];
    const float* Wq      = (const float*)d_in[1];
    const float* bq      = (const float*)d_in[2];
    const float* Wk      = (const float*)d_in[3];
    const float* bk      = (const float*)d_in[4];
    const float* Wv      = (const float*)d_in[5];
    const float* bv      = (const float*)d_in[6];
    const float* conv1_w = (const float*)d_in[7];
    const float* bn1_w   = (const float*)d_in[8];
    const float* bn1_b   = (const float*)d_in[9];
    const float* bn1_m   = (const float*)d_in[10];
    const float* bn1_v   = (const float*)d_in[11];
    const float* conv2_w = (const float*)d_in[12];
    const float* bn2_w   = (const float*)d_in[13];
    const float* bn2_b   = (const float*)d_in[14];
    const float* bn2_m   = (const float*)d_in[15];
    const float* bn2_v   = (const float*)d_in[16];
    const float* sig1_w  = (const float*)d_in[17];
    const float* sig1_b  = (const float*)d_in[18];
    const float* sig2_w  = (const float*)d_in[19];
    const float* sig2_b  = (const float*)d_in[20];
    const float* gamma   = (const float*)d_in[21];
    const float* gamma1  = (const float*)d_in[22];
    const float* gamma2  = (const float*)d_in[23];

    float *q, *k, *v, *p, *i0, *i1, *i2, *y, *t1, *t2, *s;
    cudaGetSymbolAddress((void**)&q,  g_q);
    cudaGetSymbolAddress((void**)&k,  g_k);
    cudaGetSymbolAddress((void**)&v,  g_v);
    cudaGetSymbolAddress((void**)&p,  g_p);
    cudaGetSymbolAddress((void**)&i0, g_inv0);
    cudaGetSymbolAddress((void**)&i1, g_inv1);
    cudaGetSymbolAddress((void**)&i2, g_inv2);
    cudaGetSymbolAddress((void**)&y,  g_y);
    cudaGetSymbolAddress((void**)&t1, g_t1);
    cudaGetSymbolAddress((void**)&t2, g_t2);
    cudaGetSymbolAddress((void**)&s,  g_s);

    cudaFuncSetAttribute(tc_attn<-1>, cudaFuncAttributeMaxDynamicSharedMemorySize, SMEM_TC_SZ);
    cudaFuncSetAttribute(tc_attn<6>,  cudaFuncAttributeMaxDynamicSharedMemorySize, SMEM_TC_SZ);
    cudaFuncSetAttribute(tc_attn<12>, cudaFuncAttributeMaxDynamicSharedMemorySize, SMEM_TC_SZ);
    cudaFuncSetAttribute(tc_conv,     cudaFuncAttributeMaxDynamicSharedMemorySize, SMEM_TC_SZ);
    cudaFuncSetAttribute(tc_nn,       cudaFuncAttributeMaxDynamicSharedMemorySize, SMEM_TC_SZ);

    const dim3 blk(256);
    const dim3 gSmall(NTOT / BN, 1, BDIM);
    const dim3 gEnergy(NTOT / BN, NTOT / BM, BDIM);
    const dim3 gTC(NTOT / TCN, CDIM / TCM, BDIM);   // (18, 4, 4)
    const size_t sX = (size_t)CDIM * NTOT;
    const size_t sQ = (size_t)DQD * NTOT;
    const size_t sP = (size_t)NTOT * NTOT;

    // q, k (fp32 small), v (tensor core)
    gemm_nn_bias<<<gSmall, blk>>>(Wq, x, bq, q, DQD, CDIM, sX, sQ);
    gemm_nn_bias<<<gSmall, blk>>>(Wk, x, bk, k, DQD, CDIM, sX, sQ);
    tc_nn<<<gTC, blk, SMEM_TC_SZ>>>(Wv, x, bv, (const float*)0, v, CDIM);

    // energy + softmax
    gemm_tn<<<gEnergy, blk>>>(q, k, p, NTOT, DQD, sQ, sQ, sP);
    softmax_rows<<<dim3(NTOT, BDIM), blk>>>(p, i0, i1, i2);

    // stage 0
    tc_attn<-1><<<gTC, blk, SMEM_TC_SZ>>>(v, p, i0, gamma, x, y);
    tc_conv<<<gTC, blk, SMEM_TC_SZ>>>(conv1_w, y, bn1_w, bn1_b, bn1_m, bn1_v, t1);

    // stage 1 (sigmoid-gate fused into tc_nn epilogue)
    tc_nn<<<gTC, blk, SMEM_TC_SZ>>>(sig1_w, t1, sig1_b, t1, s, CDIM);
    tc_attn<6><<<gTC, blk, SMEM_TC_SZ>>>(s, p, i1, gamma1, t1, y);
    tc_conv<<<gTC, blk, SMEM_TC_SZ>>>(conv2_w, y, bn2_w, bn2_b, bn2_m, bn2_v, t2);

    // stage 2
    tc_nn<<<gTC, blk, SMEM_TC_SZ>>>(sig2_w, t2, sig2_b, t2, s, CDIM);
    tc_attn<12><<<gTC, blk, SMEM_TC_SZ>>>(s, p, i2, gamma2, t2, (float*)d_out);
}

// round 5
// speedup vs baseline: 3.0901x; 1.2938x over previous
#include <cuda_runtime.h>
#include <cuda_fp16.h>
#include <stdint.h>

#define NTOT 2304
#define BDIM 4
#define CDIM 512
#define DQD  64
#define HW   48

// ---------------- fp32 tile config (small kernels) ----------------
#define BM 128
#define BN 64
#define BK 16
#define PAD 4

// ---------------- fp16 mma tile config ----------------
#define TCM 128
#define TCN 128
#define TCK 64                          // k halves per chunk (=128B row)
#define TILE16 (TCM * TCK * 2)          // 16384 bytes
#define SMEM_TC_SZ (2048 + 4 * TILE16)  // 67584

#define SWZ(off) ((off) ^ (((off) >> 3) & 0x70))

// ---------------- scratch ----------------
__device__ float  g_q [BDIM*DQD*NTOT];
__device__ float  g_k [BDIM*DQD*NTOT];
__device__ float  g_p [(size_t)BDIM*NTOT*NTOT];      // energy (fp32)
__device__ __half g_ph0[(size_t)BDIM*NTOT*NTOT];     // exp(e-rowmax)
__device__ __half g_ph1[(size_t)BDIM*NTOT*NTOT];     // exp(e-band6max)*mask6
__device__ __half g_ph2[(size_t)BDIM*NTOT*NTOT];     // exp(e-band12max)*mask12
__device__ __half g_v [BDIM*CDIM*NTOT];
__device__ __half g_s [BDIM*CDIM*NTOT];
__device__ float  g_inv0[BDIM*NTOT];
__device__ float  g_inv1[BDIM*NTOT];
__device__ float  g_inv2[BDIM*NTOT];
__device__ float  g_y [BDIM*CDIM*NTOT];
__device__ float  g_t1[BDIM*CDIM*NTOT];
__device__ float  g_t2[BDIM*CDIM*NTOT];

// ---------------- helpers ----------------
__device__ __forceinline__ uint32_t smem_u32(const void* p) {
    return (uint32_t)__cvta_generic_to_shared(p);
}
__device__ __forceinline__ void ldsm4(uint32_t* r, uint32_t addr) {
    asm volatile("ldmatrix.sync.aligned.m8n8.x4.shared.b16 {%0,%1,%2,%3}, [%4];"
        : "=r"(r[0]), "=r"(r[1]), "=r"(r[2]), "=r"(r[3]) : "r"(addr));
}
__device__ __forceinline__ void mma16816(float* c, const uint32_t* a, const uint32_t* b) {
    asm volatile("mma.sync.aligned.m16n8k16.row.col.f32.f16.f16.f32 "
        "{%0,%1,%2,%3}, {%4,%5,%6,%7}, {%8,%9}, {%0,%1,%2,%3};"
        : "+f"(c[0]), "+f"(c[1]), "+f"(c[2]), "+f"(c[3])
        : "r"(a[0]), "r"(a[1]), "r"(a[2]), "r"(a[3]), "r"(b[0]), "r"(b[1]));
}
__device__ __forceinline__ uint4 pack8h(float4 a, float4 b) {
    uint4 o;
    ((__half2*)&o)[0] = __floats2half2_rn(a.x, a.y);
    ((__half2*)&o)[1] = __floats2half2_rn(a.z, a.w);
    ((__half2*)&o)[2] = __floats2half2_rn(b.x, b.y);
    ((__half2*)&o)[3] = __floats2half2_rn(b.z, b.w);
    return o;
}
__device__ __forceinline__ uint4 pack8s(const float* f) {
    uint4 o;
    ((__half2*)&o)[0] = __floats2half2_rn(f[0], f[1]);
    ((__half2*)&o)[1] = __floats2half2_rn(f[2], f[3]);
    ((__half2*)&o)[2] = __floats2half2_rn(f[4], f[5]);
    ((__half2*)&o)[3] = __floats2half2_rn(f[6], f[7]);
    return o;
}

// one 128x128x64 chunk of fp16 mma
__device__ __forceinline__ void mma_chunk16(
    uint32_t aT, uint32_t bT,
    const uint32_t aOff[2], const uint32_t bOff[4],
    uint32_t aColSel, uint32_t bColSel, uint32_t xorv,
    float (&acc)[2][8][4])
{
#pragma unroll
    for (int g = 0; g < 4; g++) {
        uint32_t ka = ((uint32_t)(g * 32) + aColSel) ^ xorv;
        uint32_t kb = ((uint32_t)(g * 32) + bColSel) ^ xorv;
        uint32_t af[2][4];
        ldsm4(af[0], aT + aOff[0] + ka);
        ldsm4(af[1], aT + aOff[1] + ka);
#pragma unroll
        for (int p = 0; p < 4; p++) {
            uint32_t bf[4];
            ldsm4(bf, bT + bOff[p] + kb);
            mma16816(acc[0][2 * p],     af[0], bf);
            mma16816(acc[0][2 * p + 1], af[0], bf + 2);
            mma16816(acc[1][2 * p],     af[1], bf);
            mma16816(acc[1][2 * p + 1], af[1], bf + 2);
        }
    }
}

// per-thread precompute: 4x2 warp grid, warp tile 32x64
#define MMA_PRECOMP16() \
    const int lane = tid & 31, wid = tid >> 5; \
    const int wm = wid >> 1, wn = wid & 1; \
    const int j8 = lane >> 3, rr = lane & 7; \
    const uint32_t xorv = rr * 16; \
    const uint32_t aColSel = (j8 >> 1) * 16; \
    const uint32_t bColSel = (j8 & 1) * 16; \
    uint32_t aOff[2], bOff[4]; \
    aOff[0] = (wm * 32 +      (j8 & 1) * 8 + rr) * 128; \
    aOff[1] = aOff[0] + 16 * 128; \
    bOff[0] = (wn * 64 +      (j8 >> 1) * 8 + rr) * 128; \
    bOff[1] = bOff[0] + 16 * 128; \
    bOff[2] = bOff[0] + 32 * 128; \
    bOff[3] = bOff[0] + 48 * 128; \
    const int col8 = tid & 7; \
    const int row0 = tid >> 3; \
    float acc[2][8][4]; \
_Pragma("unroll") \
    for (int i_ = 0; i_ < 2; i_++) \
_Pragma("unroll") \
        for (int j_ = 0; j_ < 8; j_++) \
_Pragma("unroll") \
            for (int e_ = 0; e_ < 4; e_++) acc[i_][j_][e_] = 0.f;

// ========== tc_attn: Out[c,m] = g*inv[m]*sum_n A[c,n]*P[m,n] + Res[c,m] ==========
// mask baked into P; RADIUS only limits the k-range
template<int RADIUS>
__global__ __launch_bounds__(256) void tc_attn(
    const __half* __restrict__ A, const __half* __restrict__ P,
    const float* __restrict__ invsum, const float* __restrict__ gammaPtr,
    const float* __restrict__ Res, float* __restrict__ Out)
{
    extern __shared__ char smem[];
    uint32_t sb = smem_u32(smem);
    float* smf = (float*)smem;          // inv cache: 128 floats
    const int tid = threadIdx.x;
    const int bz = blockIdx.z;
    const __half* Ap = A + (size_t)bz * CDIM * NTOT;
    const __half* Pp = P + (size_t)bz * NTOT * NTOT;
    const float* Rp = Res + (size_t)bz * CDIM * NTOT;
    float* Op = Out + (size_t)bz * CDIM * NTOT;
    const int rowBase = blockIdx.y * TCM;
    const int colBase = blockIdx.x * TCN;

    uint32_t tilesAddr = (sb + 1024 + 1023) & ~1023u;
    char* tiles = smem + (tilesAddr - sb);
    const uint32_t aT[2] = { tilesAddr,          tilesAddr + 2 * TILE16 };
    const uint32_t bT[2] = { tilesAddr + TILE16, tilesAddr + 3 * TILE16 };

    MMA_PRECOMP16();

    if (tid < TCN) smf[tid] = invsum[(size_t)bz * NTOT + colBase + tid];

    int kStart = 0, kEnd = NTOT;
    if (RADIUS >= 0) {
        int rmLo = colBase / HW, rmHi = (colBase + TCN - 1) / HW;
        int rlo = rmLo - RADIUS; if (rlo < 0) rlo = 0;
        int rhi = rmHi + RADIUS; if (rhi > HW - 1) rhi = HW - 1;
        kStart = (rlo * HW) & ~(TCK - 1);
        kEnd = ((rhi + 1) * HW + TCK - 1) & ~(TCK - 1);
        if (kEnd > NTOT) kEnd = NTOT;
    }
    const int NC = (kEnd - kStart) / TCK;

    uint4 aH[4], bH[4];
    auto loadRegs = [&](int ci) {
        const int k0 = kStart + ci * TCK;
#pragma unroll
        for (int s = 0; s < 4; s++) {
            int row = row0 + s * 32;
            aH[s] = *(const uint4*)&Ap[(size_t)(rowBase + row) * NTOT + k0 + col8 * 8];
            bH[s] = *(const uint4*)&Pp[(size_t)(colBase + row) * NTOT + k0 + col8 * 8];
        }
    };
    auto stsRegs = [&](int buf) {
        char* ta = tiles + (buf ? 2 * TILE16 : 0);
        char* tb = ta + TILE16;
#pragma unroll
        for (int s = 0; s < 4; s++) {
            int row = row0 + s * 32;
            *(uint4*)(ta + SWZ(row * 128 + col8 * 16)) = aH[s];
            *(uint4*)(tb + SWZ(row * 128 + col8 * 16)) = bH[s];
        }
    };

    loadRegs(0); stsRegs(0);
    __syncthreads();
    for (int ci = 0; ci < NC; ci++) {
        const int cur = ci & 1;
        if (ci + 1 < NC) loadRegs(ci + 1);
        mma_chunk16(aT[cur], bT[cur], aOff, bOff, aColSel, bColSel, xorv, acc);
        if (ci + 1 < NC) { stsRegs(cur ^ 1); __syncthreads(); }
    }

    const float g = *gammaPtr;
#pragma unroll
    for (int mt = 0; mt < 2; mt++) {
        int mloc = wm * 32 + mt * 16 + (lane >> 2);
#pragma unroll
        for (int half = 0; half < 2; half++) {
            int c = rowBase + mloc + half * 8;
            size_t ro = (size_t)c * NTOT;
#pragma unroll
            for (int nt = 0; nt < 8; nt++) {
                int nl = wn * 64 + nt * 8 + (lane & 3) * 2;
                int n = colBase + nl;
                float2 res = *(const float2*)&Rp[ro + n];
                float2 o;
                o.x = acc[mt][nt][half * 2 + 0] * (g * smf[nl])     + res.x;
                o.y = acc[mt][nt][half * 2 + 1] * (g * smf[nl + 1]) + res.y;
                *(float2*)&Op[ro + n] = o;
            }
        }
    }
}

// ========== tc_conv: conv3x3 SAME + BN + ReLU, implicit GEMM K=4608 ==========
__global__ __launch_bounds__(256) void tc_conv(
    const float* __restrict__ Wt, const float* __restrict__ X,
    const float* __restrict__ bnw, const float* __restrict__ bnb,
    const float* __restrict__ bnm, const float* __restrict__ bnv,
    float* __restrict__ Out)
{
    extern __shared__ char smem[];
    uint32_t sb = smem_u32(smem);
    const int tid = threadIdx.x;
    const float* Xp = X + (size_t)blockIdx.z * CDIM * NTOT;
    float* Op = Out + (size_t)blockIdx.z * CDIM * NTOT;
    const int rowBase = blockIdx.y * TCM;
    const int colBase = blockIdx.x * TCN;
    const int K = CDIM * 9;

    uint32_t tilesAddr = (sb + 1024 + 1023) & ~1023u;
    char* tiles = smem + (tilesAddr - sb);
    const uint32_t aT[2] = { tilesAddr,          tilesAddr + 2 * TILE16 };
    const uint32_t bT[2] = { tilesAddr + TILE16, tilesAddr + 3 * TILE16 };

    MMA_PRECOMP16();

    // im2col hoists: one pixel per thread
    const int j = tid & 127;
    const int h2 = tid >> 7;                 // 0/1: 32-k half
    const int pix = colBase + j;
    const int py = pix / HW, px = pix - py * HW;

    const int NC = K / TCK;   // 72
    uint4 aH[4], bH[4];

    auto loadRegs = [&](int ci) {
        const int k0 = ci * TCK;
#pragma unroll
        for (int s = 0; s < 4; s++) {
            int row = row0 + s * 32;
            const float* src = &Wt[(size_t)(rowBase + row) * K + k0 + col8 * 8];
            aH[s] = pack8h(*(const float4*)src, *(const float4*)(src + 4));
        }
#pragma unroll
        for (int t4 = 0; t4 < 4; t4++) {
            float f[8];
#pragma unroll
            for (int e = 0; e < 8; e++) {
                int kidx = k0 + 32 * h2 + t4 * 8 + e;
                int ic = kidx / 9;
                int tt = kidx - ic * 9;
                int ky = tt / 3, kx = tt - ky * 3;
                int iy = py + ky - 1, ix = px + kx - 1;
                float v = 0.f;
                if ((unsigned)iy < HW && (unsigned)ix < HW)
                    v = Xp[(size_t)ic * NTOT + iy * HW + ix];
                f[e] = v;
            }
            bH[t4] = pack8s(f);
        }
    };
    auto stsRegs = [&](int buf) {
        char* ta = tiles + (buf ? 2 * TILE16 : 0);
        char* tb = ta + TILE16;
#pragma unroll
        for (int s = 0; s < 4; s++) {
            int row = row0 + s * 32;
            *(uint4*)(ta + SWZ(row * 128 + col8 * 16)) = aH[s];
        }
#pragma unroll
        for (int t4 = 0; t4 < 4; t4++)
            *(uint4*)(tb + SWZ(j * 128 + 64 * h2 + t4 * 16)) = bH[t4];
    };

    loadRegs(0); stsRegs(0);
    __syncthreads();
    for (int ci = 0; ci < NC; ci++) {
        const int cur = ci & 1;
        if (ci + 1 < NC) loadRegs(ci + 1);
        mma_chunk16(aT[cur], bT[cur], aOff, bOff, aColSel, bColSel, xorv, acc);
        if (ci + 1 < NC) { stsRegs(cur ^ 1); __syncthreads(); }
    }

#pragma unroll
    for (int mt = 0; mt < 2; mt++) {
        int mloc = wm * 32 + mt * 16 + (lane >> 2);
#pragma unroll
        for (int half = 0; half < 2; half++) {
            int oc = rowBase + mloc + half * 8;
            float scale = bnw[oc] * rsqrtf(bnv[oc] + 1e-5f);
            float shift = bnb[oc] - bnm[oc] * scale;
            size_t ro = (size_t)oc * NTOT;
#pragma unroll
            for (int nt = 0; nt < 8; nt++) {
                int n = colBase + wn * 64 + nt * 8 + (lane & 3) * 2;
                float2 o;
                o.x = fmaxf(acc[mt][nt][half * 2 + 0] * scale + shift, 0.f);
                o.y = fmaxf(acc[mt][nt][half * 2 + 1] * scale + shift, 0.f);
                *(float2*)&Op[ro + n] = o;
            }
        }
    }
}

// ====== tc_nn: C[d,m] = sum_c W[d,c]*X[c,m] + bias[d]; optional gate; half output ======
__global__ __launch_bounds__(256) void tc_nn(
    const float* __restrict__ W, const float* __restrict__ X,
    const float* __restrict__ bias, const float* __restrict__ gateSrc,
    __half* __restrict__ Out, int K)
{
    extern __shared__ char smem[];
    uint32_t sb = smem_u32(smem);
    const int tid = threadIdx.x;
    const float* Xp = X + (size_t)blockIdx.z * K * NTOT;
    const float* Gp = gateSrc ? gateSrc + (size_t)blockIdx.z * CDIM * NTOT : (const float*)0;
    __half* Op = Out + (size_t)blockIdx.z * CDIM * NTOT;
    const int rowBase = blockIdx.y * TCM;
    const int colBase = blockIdx.x * TCN;

    uint32_t tilesAddr = (sb + 1024 + 1023) & ~1023u;
    char* tiles = smem + (tilesAddr - sb);
    const uint32_t aT[2] = { tilesAddr,          tilesAddr + 2 * TILE16 };
    const uint32_t bT[2] = { tilesAddr + TILE16, tilesAddr + 3 * TILE16 };

    MMA_PRECOMP16();

    const int kk0 = (tid >> 5) * 8;   // per-warp k-col group (8 k values)
    const int NC = K / TCK;           // 8
    uint4 aH[4], bH[4];

    auto loadRegs = [&](int ci) {
        const int k0 = ci * TCK;
#pragma unroll
        for (int s = 0; s < 4; s++) {
            int row = row0 + s * 32;
            const float* src = &W[(size_t)(rowBase + row) * K + k0 + col8 * 8];
            aH[s] = pack8h(*(const float4*)src, *(const float4*)(src + 4));
        }
#pragma unroll
        for (int mq = 0; mq < 4; mq++) {
            int jr = lane + 32 * mq;
            float f[8];
#pragma unroll
            for (int e = 0; e < 8; e++)
                f[e] = Xp[(size_t)(k0 + kk0 + e) * NTOT + colBase + jr];
            bH[mq] = pack8s(f);
        }
    };
    auto stsRegs = [&](int buf) {
        char* ta = tiles + (buf ? 2 * TILE16 : 0);
        char* tb = ta + TILE16;
#pragma unroll
        for (int s = 0; s < 4; s++) {
            int row = row0 + s * 32;
            *(uint4*)(ta + SWZ(row * 128 + col8 * 16)) = aH[s];
        }
#pragma unroll
        for (int mq = 0; mq < 4; mq++) {
            int jr = lane + 32 * mq;
            *(uint4*)(tb + SWZ(jr * 128 + kk0 * 2)) = bH[mq];
        }
    };

    loadRegs(0); stsRegs(0);
    __syncthreads();
    for (int ci = 0; ci < NC; ci++) {
        const int cur = ci & 1;
        if (ci + 1 < NC) loadRegs(ci + 1);
        mma_chunk16(aT[cur], bT[cur], aOff, bOff, aColSel, bColSel, xorv, acc);
        if (ci + 1 < NC) { stsRegs(cur ^ 1); __syncthreads(); }
    }

#pragma unroll
    for (int mt = 0; mt < 2; mt++) {
        int mloc = wm * 32 + mt * 16 + (lane >> 2);
#pragma unroll
        for (int half = 0; half < 2; half++) {
            int d = rowBase + mloc + half * 8;
            float bv = bias[d];
            size_t ro = (size_t)d * NTOT;
#pragma unroll
            for (int nt = 0; nt < 8; nt++) {
                int n = colBase + wn * 64 + nt * 8 + (lane & 3) * 2;
                float ox = acc[mt][nt][half * 2 + 0] + bv;
                float oy = acc[mt][nt][half * 2 + 1] + bv;
                if (Gp) {
                    float2 gv = *(const float2*)&Gp[ro + n];
                    ox = gv.x * (1.f / (1.f + __expf(-ox)));
                    oy = gv.y * (1.f / (1.f + __expf(-oy)));
                }
                *(__half2*)&Op[ro + n] = __floats2half2_rn(ox, oy);
            }
        }
    }
}

// ---------------- fp32 kernels: q/k projections, energy ----------------
__global__ __launch_bounds__(256) void gemm_nn_bias(
    const float* __restrict__ A, const float* __restrict__ B,
    const float* __restrict__ bias, float* __restrict__ Cout,
    int M, int K, size_t strideB, size_t strideC)
{
    __shared__ float As[BK][BM+PAD];
    __shared__ float Bs[BK][BN+PAD];
    const int tid = threadIdx.x;
    const int ty = tid >> 4, tx = tid & 15;
    const float* Bp = B + (size_t)blockIdx.z * strideB;
    float* Cp = Cout + (size_t)blockIdx.z * strideC;
    const int rowBase = blockIdx.y * BM;
    const int colBase = blockIdx.x * BN;
    float acc[8][4];
#pragma unroll
    for (int i = 0; i < 8; i++)
#pragma unroll
        for (int j = 0; j < 4; j++) acc[i][j] = 0.f;
    for (int k0 = 0; k0 < K; k0 += BK) {
#pragma unroll
        for (int s = 0; s < 8; s++) {
            int idx = tid + s * 256;
            int kk = idx & 15, ii = idx >> 4;
            int gr = rowBase + ii;
            As[kk][ii] = (gr < M) ? A[(size_t)gr * K + k0 + kk] : 0.f;
        }
#pragma unroll
        for (int s = 0; s < 4; s++) {
            int idx = tid + s * 256;
            int jj = idx & 63, kk = idx >> 6;
            Bs[kk][jj] = Bp[(size_t)(k0 + kk) * NTOT + colBase + jj];
        }
        __syncthreads();
#pragma unroll
        for (int kk = 0; kk < BK; kk++) {
            float a[8], bb[4];
            *(float4*)&a[0] = *(const float4*)&As[kk][ty * 8];
            *(float4*)&a[4] = *(const float4*)&As[kk][ty * 8 + 4];
            *(float4*)&bb[0] = *(const float4*)&Bs[kk][tx * 4];
#pragma unroll
            for (int i = 0; i < 8; i++)
#pragma unroll
                for (int j = 0; j < 4; j++) acc[i][j] = fmaf(a[i], bb[j], acc[i][j]);
        }
        __syncthreads();
    }
#pragma unroll
    for (int i = 0; i < 8; i++) {
        int gr = rowBase + ty * 8 + i;
        if (gr < M) {
            float bv = bias[gr];
            size_t base = (size_t)gr * NTOT + colBase + tx * 4;
#pragma unroll
            for (int j = 0; j < 4; j++) Cp[base + j] = acc[i][j] + bv;
        }
    }
}

__global__ __launch_bounds__(256) void gemm_tn(
    const float* __restrict__ A, const float* __restrict__ B, float* __restrict__ Cout,
    int M, int K, size_t strideA, size_t strideB, size_t strideC)
{
    __shared__ float As[BK][BM+PAD];
    __shared__ float Bs[BK][BN+PAD];
    const int tid = threadIdx.x;
    const int ty = tid >> 4, tx = tid & 15;
    const float* Ap = A + (size_t)blockIdx.z * strideA;
    const float* Bp = B + (size_t)blockIdx.z * strideB;
    float* Cp = Cout + (size_t)blockIdx.z * strideC;
    const int rowBase = blockIdx.y * BM;
    const int colBase = blockIdx.x * BN;
    float acc[8][4];
#pragma unroll
    for (int i = 0; i < 8; i++)
#pragma unroll
        for (int j = 0; j < 4; j++) acc[i][j] = 0.f;
    for (int k0 = 0; k0 < K; k0 += BK) {
#pragma unroll
        for (int s = 0; s < 8; s++) {
            int idx = tid + s * 256;
            int ii = idx & 127, kk = idx >> 7;
            As[kk][ii] = Ap[(size_t)(k0 + kk) * M + rowBase + ii];
        }
#pragma unroll
        for (int s = 0; s < 4; s++) {
            int idx = tid + s * 256;
            int jj = idx & 63, kk = idx >> 6;
            Bs[kk][jj] = Bp[(size_t)(k0 + kk) * NTOT + colBase + jj];
        }
        __syncthreads();
#pragma unroll
        for (int kk = 0; kk < BK; kk++) {
            float a[8], bb[4];
            *(float4*)&a[0] = *(const float4*)&As[kk][ty * 8];
            *(float4*)&a[4] = *(const float4*)&As[kk][ty * 8 + 4];
            *(float4*)&bb[0] = *(const float4*)&Bs[kk][tx * 4];
#pragma unroll
            for (int i = 0; i < 8; i++)
#pragma unroll
                for (int j = 0; j < 4; j++) acc[i][j] = fmaf(a[i], bb[j], acc[i][j]);
        }
        __syncthreads();
    }
#pragma unroll
    for (int i = 0; i < 8; i++) {
        int gr = rowBase + ty * 8 + i;
        size_t base = (size_t)gr * NTOT + colBase + tx * 4;
#pragma unroll
        for (int j = 0; j < 4; j++) Cp[base + j] = acc[i][j];
    }
}

// ---- softmax: per-row, 3 shifts (global / band12 / band6), 3 fp16 outputs ----
__global__ __launch_bounds__(256) void softmax_rows3(
    const float* __restrict__ P,
    __half* __restrict__ Ph0, __half* __restrict__ Ph1, __half* __restrict__ Ph2,
    float* __restrict__ inv0, float* __restrict__ inv1, float* __restrict__ inv2)
{
    __shared__ float rowv[NTOT];
    __shared__ float red[256];
    const int row = blockIdx.x, b = blockIdx.y, tid = threadIdx.x;
    const size_t roff = ((size_t)b * NTOT + row) * NTOT;
    const float* p = P + roff;

    for (int n = tid; n < NTOT; n += 256) rowv[n] = p[n];
    __syncthreads();

    const int rm = row / HW, cm = row - rm * HW;
    float m0 = -1e30f, m6 = -1e30f, m12 = -1e30f;
    for (int n = tid; n < NTOT; n += 256) {
        float v = rowv[n];
        m0 = fmaxf(m0, v);
        int rn = n / HW, cn = n - rn * HW;
        int dr = rm - rn; dr = dr < 0 ? -dr : dr;
        int dc = cm - cn; dc = dc < 0 ? -dc : dc;
        int d = dr > dc ? dr : dc;
        if (d <= 12) { m12 = fmaxf(m12, v); if (d <= 6) m6 = fmaxf(m6, v); }
    }
    red[tid] = m0; __syncthreads();
    for (int s = 128; s > 0; s >>= 1) { if (tid < s) red[tid] = fmaxf(red[tid], red[tid + s]); __syncthreads(); }
    m0 = red[0]; __syncthreads();
    red[tid] = m6; __syncthreads();
    for (int s = 128; s > 0; s >>= 1) { if (tid < s) red[tid] = fmaxf(red[tid], red[tid + s]); __syncthreads(); }
    m6 = red[0]; __syncthreads();
    red[tid] = m12; __syncthreads();
    for (int s = 128; s > 0; s >>= 1) { if (tid < s) red[tid] = fmaxf(red[tid], red[tid + s]); __syncthreads(); }
    m12 = red[0]; __syncthreads();

    float s0 = 0.f, s1 = 0.f, s2 = 0.f;
    for (int n = tid; n < NTOT; n += 256) {
        float v = rowv[n];
        __half h0 = __float2half_rn(__expf(v - m0));
        Ph0[roff + n] = h0;
        s0 += __half2float(h0);
        int rn = n / HW, cn = n - rn * HW;
        int dr = rm - rn; dr = dr < 0 ? -dr : dr;
        int dc = cm - cn; dc = dc < 0 ? -dc : dc;
        int d = dr > dc ? dr : dc;
        __half h1 = __ushort_as_half(0), h2 = __ushort_as_half(0);
        if (d <= 12) {
            h2 = __float2half_rn(__expf(v - m12));
            s2 += __half2float(h2);
            if (d <= 6) { h1 = __float2half_rn(__expf(v - m6)); s1 += __half2float(h1); }
        }
        Ph1[roff + n] = h1;
        Ph2[roff + n] = h2;
    }
    red[tid] = s0; __syncthreads();
    for (int s = 128; s > 0; s >>= 1) { if (tid < s) red[tid] += red[tid + s]; __syncthreads(); }
    if (tid == 0) inv0[(size_t)b * NTOT + row] = 1.f / red[0];
    __syncthreads();
    red[tid] = s1; __syncthreads();
    for (int s = 128; s > 0; s >>= 1) { if (tid < s) red[tid] += red[tid + s]; __syncthreads(); }
    if (tid == 0) inv1[(size_t)b * NTOT + row] = 1.f / red[0];
    __syncthreads();
    red[tid] = s2; __syncthreads();
    for (int s = 128; s > 0; s >>= 1) { if (tid < s) red[tid] += red[tid + s]; __syncthreads(); }
    if (tid == 0) inv2[(size_t)b * NTOT + row] = 1.f / red[0];
}

// ---------------- launch ----------------
extern "C" void kernel_launch(void* const* d_in, const int* in_sizes, int n_in,
                              void* d_out, int out_size)
{
    const float* x       = (const float*)d_in[0];
    const float* Wq      = (const float*)d_in[1];
    const float* bq      = (const float*)d_in[2];
    const float* Wk      = (const float*)d_in[3];
    const float* bk      = (const float*)d_in[4];
    const float* Wv      = (const float*)d_in[5];
    const float* bv      = (const float*)d_in[6];
    const float* conv1_w = (const float*)d_in[7];
    const float* bn1_w   = (const float*)d_in[8];
    const float* bn1_b   = (const float*)d_in[9];
    const float* bn1_m   = (const float*)d_in[10];
    const float* bn1_v   = (const float*)d_in[11];
    const float* conv2_w = (const float*)d_in[12];
    const float* bn2_w   = (const float*)d_in[13];
    const float* bn2_b   = (const float*)d_in[14];
    const float* bn2_m   = (const float*)d_in[15];
    const float* bn2_v   = (const float*)d_in[16];
    const float* sig1_w  = (const float*)d_in[17];
    const float* sig1_b  = (const float*)d_in[18];
    const float* sig2_w  = (const float*)d_in[19];
    const float* sig2_b  = (const float*)d_in[20];
    const float* gamma   = (const float*)d_in[21];
    const float* gamma1  = (const float*)d_in[22];
    const float* gamma2  = (const float*)d_in[23];

    float *q, *k, *p, *i0, *i1, *i2, *y, *t1, *t2;
    __half *ph0, *ph1, *ph2, *v, *s;
    cudaGetSymbolAddress((void**)&q,   g_q);
    cudaGetSymbolAddress((void**)&k,   g_k);
    cudaGetSymbolAddress((void**)&p,   g_p);
    cudaGetSymbolAddress((void**)&ph0, g_ph0);
    cudaGetSymbolAddress((void**)&ph1, g_ph1);
    cudaGetSymbolAddress((void**)&ph2, g_ph2);
    cudaGetSymbolAddress((void**)&v,   g_v);
    cudaGetSymbolAddress((void**)&s,   g_s);
    cudaGetSymbolAddress((void**)&i0,  g_inv0);
    cudaGetSymbolAddress((void**)&i1,  g_inv1);
    cudaGetSymbolAddress((void**)&i2,  g_inv2);
    cudaGetSymbolAddress((void**)&y,   g_y);
    cudaGetSymbolAddress((void**)&t1,  g_t1);
    cudaGetSymbolAddress((void**)&t2,  g_t2);

    cudaFuncSetAttribute(tc_attn<-1>, cudaFuncAttributeMaxDynamicSharedMemorySize, SMEM_TC_SZ);
    cudaFuncSetAttribute(tc_attn<6>,  cudaFuncAttributeMaxDynamicSharedMemorySize, SMEM_TC_SZ);
    cudaFuncSetAttribute(tc_attn<12>, cudaFuncAttributeMaxDynamicSharedMemorySize, SMEM_TC_SZ);
    cudaFuncSetAttribute(tc_conv,     cudaFuncAttributeMaxDynamicSharedMemorySize, SMEM_TC_SZ);
    cudaFuncSetAttribute(tc_nn,       cudaFuncAttributeMaxDynamicSharedMemorySize, SMEM_TC_SZ);

    const dim3 blk(256);
    const dim3 gSmall(NTOT / BN, 1, BDIM);
    const dim3 gEnergy(NTOT / BN, NTOT / BM, BDIM);
    const dim3 gTC(NTOT / TCN, CDIM / TCM, BDIM);   // (18, 4, 4)
    const size_t sX = (size_t)CDIM * NTOT;
    const size_t sQ = (size_t)DQD * NTOT;
    const size_t sP = (size_t)NTOT * NTOT;

    // q, k (fp32), v (fp16 mma, half out)
    gemm_nn_bias<<<gSmall, blk>>>(Wq, x, bq, q, DQD, CDIM, sX, sQ);
    gemm_nn_bias<<<gSmall, blk>>>(Wk, x, bk, k, DQD, CDIM, sX, sQ);
    tc_nn<<<gTC, blk, SMEM_TC_SZ>>>(Wv, x, bv, (const float*)0, v, CDIM);

    // energy + 3-shift softmax (3 fp16 P arrays, masks baked in)
    gemm_tn<<<gEnergy, blk>>>(q, k, p, NTOT, DQD, sQ, sQ, sP);
    softmax_rows3<<<dim3(NTOT, BDIM), blk>>>(p, ph0, ph1, ph2, i0, i1, i2);

    // stage 0
    tc_attn<-1><<<gTC, blk, SMEM_TC_SZ>>>(v, ph0, i0, gamma, x, y);
    tc_conv<<<gTC, blk, SMEM_TC_SZ>>>(conv1_w, y, bn1_w, bn1_b, bn1_m, bn1_v, t1);

    // stage 1
    tc_nn<<<gTC, blk, SMEM_TC_SZ>>>(sig1_w, t1, sig1_b, t1, s, CDIM);
    tc_attn<6><<<gTC, blk, SMEM_TC_SZ>>>(s, ph1, i1, gamma1, t1, y);
    tc_conv<<<gTC, blk, SMEM_TC_SZ>>>(conv2_w, y, bn2_w, bn2_b, bn2_m, bn2_v, t2);

    // stage 2
    tc_nn<<<gTC, blk, SMEM_TC_SZ>>>(sig2_w, t2, sig2_b, t2, s, CDIM);
    tc_attn<12><<<gTC, blk, SMEM_TC_SZ>>>(s, ph2, i2, gamma2, t2, (float*)d_out);
}

// round 6
// speedup vs baseline: 4.4146x; 1.4286x over previous
#include <cuda_runtime.h>
#include <cuda_fp16.h>
#include <stdint.h>

#define NTOT 2304
#define BDIM 4
#define CDIM 512
#define DQD  64
#define HW   48
#define KCONV (CDIM * 9)

// ---------------- fp32 tile config (small kernels) ----------------
#define BM 128
#define BN 64
#define BK 16
#define PAD 4

// ---------------- fp16 mma tile config ----------------
#define TCM 128
#define TCN 128
#define TCK 64                          // k halves per chunk (=128B row)
#define TILE16 (TCM * TCK * 2)          // 16384 bytes
#define SMEM_TC_SZ (2048 + 4 * TILE16)  // 67584

#define SWZ(off) ((off) ^ (((off) >> 3) & 0x70))

// ---------------- scratch ----------------
__device__ float  g_q [BDIM*DQD*NTOT];
__device__ float  g_k [BDIM*DQD*NTOT];
__device__ float  g_p [(size_t)BDIM*NTOT*NTOT];      // energy (fp32)
__device__ __half g_ph0[(size_t)BDIM*NTOT*NTOT];     // exp(e-rowmax)
__device__ __half g_ph1[(size_t)BDIM*NTOT*NTOT];     // exp(e-band6max)*mask6
__device__ __half g_ph2[(size_t)BDIM*NTOT*NTOT];     // exp(e-band12max)*mask12
__device__ __half g_v  [BDIM*CDIM*NTOT];
__device__ __half g_s  [BDIM*CDIM*NTOT];
__device__ float  g_inv0[BDIM*NTOT];
__device__ float  g_inv1[BDIM*NTOT];
__device__ float  g_inv2[BDIM*NTOT];
__device__ __half g_xt [BDIM*NTOT*CDIM];    // x transposed fp16 [n][c]
__device__ __half g_yt [BDIM*NTOT*CDIM];    // attn out transposed fp16 (conv input)
__device__ float  g_t1 [BDIM*CDIM*NTOT];
__device__ __half g_t1t[BDIM*NTOT*CDIM];
__device__ float  g_t2 [BDIM*CDIM*NTOT];
__device__ __half g_t2t[BDIM*NTOT*CDIM];
__device__ __half g_w1r[CDIM*KCONV];        // conv weights, (tap, ic) k-order, fp16
__device__ __half g_w2r[CDIM*KCONV];

// ---------------- helpers ----------------
__device__ __forceinline__ uint32_t smem_u32(const void* p) {
    return (uint32_t)__cvta_generic_to_shared(p);
}
__device__ __forceinline__ void ldsm4(uint32_t* r, uint32_t addr) {
    asm volatile("ldmatrix.sync.aligned.m8n8.x4.shared.b16 {%0,%1,%2,%3}, [%4];"
        : "=r"(r[0]), "=r"(r[1]), "=r"(r[2]), "=r"(r[3]) : "r"(addr));
}
__device__ __forceinline__ void mma16816(float* c, const uint32_t* a, const uint32_t* b) {
    asm volatile("mma.sync.aligned.m16n8k16.row.col.f32.f16.f16.f32 "
        "{%0,%1,%2,%3}, {%4,%5,%6,%7}, {%8,%9}, {%0,%1,%2,%3};"
        : "+f"(c[0]), "+f"(c[1]), "+f"(c[2]), "+f"(c[3])
        : "r"(a[0]), "r"(a[1]), "r"(a[2]), "r"(a[3]), "r"(b[0]), "r"(b[1]));
}
__device__ __forceinline__ uint4 pack8h(float4 a, float4 b) {
    uint4 o;
    ((__half2*)&o)[0] = __floats2half2_rn(a.x, a.y);
    ((__half2*)&o)[1] = __floats2half2_rn(a.z, a.w);
    ((__half2*)&o)[2] = __floats2half2_rn(b.x, b.y);
    ((__half2*)&o)[3] = __floats2half2_rn(b.z, b.w);
    return o;
}

// one 128x128x64 chunk of fp16 mma
__device__ __forceinline__ void mma_chunk16(
    uint32_t aT, uint32_t bT,
    const uint32_t aOff[2], const uint32_t bOff[4],
    uint32_t aColSel, uint32_t bColSel, uint32_t xorv,
    float (&acc)[2][8][4])
{
#pragma unroll
    for (int g = 0; g < 4; g++) {
        uint32_t ka = ((uint32_t)(g * 32) + aColSel) ^ xorv;
        uint32_t kb = ((uint32_t)(g * 32) + bColSel) ^ xorv;
        uint32_t af[2][4];
        ldsm4(af[0], aT + aOff[0] + ka);
        ldsm4(af[1], aT + aOff[1] + ka);
#pragma unroll
        for (int p = 0; p < 4; p++) {
            uint32_t bf[4];
            ldsm4(bf, bT + bOff[p] + kb);
            mma16816(acc[0][2 * p],     af[0], bf);
            mma16816(acc[0][2 * p + 1], af[0], bf + 2);
            mma16816(acc[1][2 * p],     af[1], bf);
            mma16816(acc[1][2 * p + 1], af[1], bf + 2);
        }
    }
}

// per-thread precompute: 4x2 warp grid, warp tile 32x64
#define MMA_PRECOMP16() \
    const int lane = tid & 31, wid = tid >> 5; \
    const int wm = wid >> 1, wn = wid & 1; \
    const int j8 = lane >> 3, rr = lane & 7; \
    const uint32_t xorv = rr * 16; \
    const uint32_t aColSel = (j8 >> 1) * 16; \
    const uint32_t bColSel = (j8 & 1) * 16; \
    uint32_t aOff[2], bOff[4]; \
    aOff[0] = (wm * 32 +      (j8 & 1) * 8 + rr) * 128; \
    aOff[1] = aOff[0] + 16 * 128; \
    bOff[0] = (wn * 64 +      (j8 >> 1) * 8 + rr) * 128; \
    bOff[1] = bOff[0] + 16 * 128; \
    bOff[2] = bOff[0] + 32 * 128; \
    bOff[3] = bOff[0] + 48 * 128; \
    const int col8 = tid & 7; \
    const int row0 = tid >> 3; \
    float acc[2][8][4]; \
_Pragma("unroll") \
    for (int i_ = 0; i_ < 2; i_++) \
_Pragma("unroll") \
        for (int j_ = 0; j_ < 8; j_++) \
_Pragma("unroll") \
            for (int e_ = 0; e_ < 4; e_++) acc[i_][j_][e_] = 0.f;

// ========== tc_attn: acc = g*inv[m]*sum_n A[c,n]*P[m,n] + Res[c,m] ==========
// OUT_T: write fp16 transposed [m][c] (conv input); else fp32 [c][m] (final out)
template<int RADIUS, bool OUT_T>
__global__ __launch_bounds__(256) void tc_attn(
    const __half* __restrict__ A, const __half* __restrict__ P,
    const float* __restrict__ invsum, const float* __restrict__ gammaPtr,
    const float* __restrict__ Res, float* __restrict__ OutF, __half* __restrict__ OutT)
{
    extern __shared__ char smem[];
    uint32_t sb = smem_u32(smem);
    float* smf = (float*)smem;
    const int tid = threadIdx.x;
    const int bz = blockIdx.z;
    const __half* Ap = A + (size_t)bz * CDIM * NTOT;
    const __half* Pp = P + (size_t)bz * NTOT * NTOT;
    const float* Rp = Res + (size_t)bz * CDIM * NTOT;
    const int rowBase = blockIdx.y * TCM;
    const int colBase = blockIdx.x * TCN;

    uint32_t tilesAddr = (sb + 1024 + 1023) & ~1023u;
    char* tiles = smem + (tilesAddr - sb);
    const uint32_t aT[2] = { tilesAddr,          tilesAddr + 2 * TILE16 };
    const uint32_t bT[2] = { tilesAddr + TILE16, tilesAddr + 3 * TILE16 };

    MMA_PRECOMP16();

    if (tid < TCN) smf[tid] = invsum[(size_t)bz * NTOT + colBase + tid];

    int kStart = 0, kEnd = NTOT;
    if (RADIUS >= 0) {
        int rmLo = colBase / HW, rmHi = (colBase + TCN - 1) / HW;
        int rlo = rmLo - RADIUS; if (rlo < 0) rlo = 0;
        int rhi = rmHi + RADIUS; if (rhi > HW - 1) rhi = HW - 1;
        kStart = (rlo * HW) & ~(TCK - 1);
        kEnd = ((rhi + 1) * HW + TCK - 1) & ~(TCK - 1);
        if (kEnd > NTOT) kEnd = NTOT;
    }
    const int NC = (kEnd - kStart) / TCK;

    uint4 aH[4], bH[4];
    auto loadRegs = [&](int ci) {
        const int k0 = kStart + ci * TCK;
#pragma unroll
        for (int s = 0; s < 4; s++) {
            int row = row0 + s * 32;
            aH[s] = *(const uint4*)&Ap[(size_t)(rowBase + row) * NTOT + k0 + col8 * 8];
            bH[s] = *(const uint4*)&Pp[(size_t)(colBase + row) * NTOT + k0 + col8 * 8];
        }
    };
    auto stsRegs = [&](int buf) {
        char* ta = tiles + (buf ? 2 * TILE16 : 0);
        char* tb = ta + TILE16;
#pragma unroll
        for (int s = 0; s < 4; s++) {
            int row = row0 + s * 32;
            *(uint4*)(ta + SWZ(row * 128 + col8 * 16)) = aH[s];
            *(uint4*)(tb + SWZ(row * 128 + col8 * 16)) = bH[s];
        }
    };

    loadRegs(0); stsRegs(0);
    __syncthreads();
    for (int ci = 0; ci < NC; ci++) {
        const int cur = ci & 1;
        if (ci + 1 < NC) loadRegs(ci + 1);
        mma_chunk16(aT[cur], bT[cur], aOff, bOff, aColSel, bColSel, xorv, acc);
        if (ci + 1 < NC) { stsRegs(cur ^ 1); __syncthreads(); }
    }

    const float g = *gammaPtr;
    float* OpF = OUT_T ? (float*)0 : OutF + (size_t)bz * CDIM * NTOT;
    __half* OpT = OUT_T ? OutT + (size_t)bz * NTOT * CDIM : (__half*)0;
#pragma unroll
    for (int mt = 0; mt < 2; mt++) {
        int mloc = wm * 32 + mt * 16 + (lane >> 2);
#pragma unroll
        for (int half = 0; half < 2; half++) {
            int c = rowBase + mloc + half * 8;
            size_t ro = (size_t)c * NTOT;
#pragma unroll
            for (int nt = 0; nt < 8; nt++) {
                int nl = wn * 64 + nt * 8 + (lane & 3) * 2;
                int n = colBase + nl;
                float2 res = *(const float2*)&Rp[ro + n];
                float ox = acc[mt][nt][half * 2 + 0] * (g * smf[nl])     + res.x;
                float oy = acc[mt][nt][half * 2 + 1] * (g * smf[nl + 1]) + res.y;
                if (OUT_T) {
                    OpT[(size_t)n * CDIM + c]       = __float2half_rn(ox);
                    OpT[(size_t)(n + 1) * CDIM + c] = __float2half_rn(oy);
                } else {
                    float2 o; o.x = ox; o.y = oy;
                    *(float2*)&OpF[ro + n] = o;
                }
            }
        }
    }
}

// ========== tc_conv: conv3x3 SAME + BN + ReLU over transposed fp16 input ==========
// Wr: fp16 [oc][(tap)*512+ic]; Xt: fp16 [n][c]; writes t fp32 [oc][n] + t_t fp16 [n][oc]
__global__ __launch_bounds__(256) void tc_conv(
    const __half* __restrict__ Wr, const __half* __restrict__ Xt,
    const float* __restrict__ bnw, const float* __restrict__ bnb,
    const float* __restrict__ bnm, const float* __restrict__ bnv,
    float* __restrict__ Out, __half* __restrict__ OutT)
{
    extern __shared__ char smem[];
    uint32_t sb = smem_u32(smem);
    const int tid = threadIdx.x;
    const __half* Xp = Xt + (size_t)blockIdx.z * NTOT * CDIM;
    float* Op = Out + (size_t)blockIdx.z * CDIM * NTOT;
    __half* OpT = OutT + (size_t)blockIdx.z * NTOT * CDIM;
    const int rowBase = blockIdx.y * TCM;
    const int colBase = blockIdx.x * TCN;

    uint32_t tilesAddr = (sb + 1024 + 1023) & ~1023u;
    char* tiles = smem + (tilesAddr - sb);
    const uint32_t aT[2] = { tilesAddr,          tilesAddr + 2 * TILE16 };
    const uint32_t bT[2] = { tilesAddr + TILE16, tilesAddr + 3 * TILE16 };

    MMA_PRECOMP16();

    // per-thread pixel coords for the 4 B rows
    int pys[4], pxs[4];
#pragma unroll
    for (int s = 0; s < 4; s++) {
        int pix = colBase + row0 + s * 32;
        pys[s] = pix / HW; pxs[s] = pix - pys[s] * HW;
    }

    const int NC = KCONV / TCK;   // 72
    uint4 aH[4], bH[4];

    auto loadRegs = [&](int ci) {
        const int k0 = ci * TCK;
        const int tap = ci >> 3;                // 8 chunks per tap (512/64)
        const int icb = (ci & 7) * TCK;
        const int ky = tap / 3, kx = tap - ky * 3;
#pragma unroll
        for (int s = 0; s < 4; s++) {
            int row = row0 + s * 32;
            aH[s] = *(const uint4*)&Wr[(size_t)(rowBase + row) * KCONV + k0 + col8 * 8];
        }
#pragma unroll
        for (int s = 0; s < 4; s++) {
            int iy = pys[s] + ky - 1, ix = pxs[s] + kx - 1;
            uint4 u = make_uint4(0, 0, 0, 0);
            if ((unsigned)iy < HW && (unsigned)ix < HW)
                u = *(const uint4*)&Xp[(size_t)(iy * HW + ix) * CDIM + icb + col8 * 8];
            bH[s] = u;
        }
    };
    auto stsRegs = [&](int buf) {
        char* ta = tiles + (buf ? 2 * TILE16 : 0);
        char* tb = ta + TILE16;
#pragma unroll
        for (int s = 0; s < 4; s++) {
            int row = row0 + s * 32;
            *(uint4*)(ta + SWZ(row * 128 + col8 * 16)) = aH[s];
            *(uint4*)(tb + SWZ(row * 128 + col8 * 16)) = bH[s];
        }
    };

    loadRegs(0); stsRegs(0);
    __syncthreads();
    for (int ci = 0; ci < NC; ci++) {
        const int cur = ci & 1;
        if (ci + 1 < NC) loadRegs(ci + 1);
        mma_chunk16(aT[cur], bT[cur], aOff, bOff, aColSel, bColSel, xorv, acc);
        if (ci + 1 < NC) { stsRegs(cur ^ 1); __syncthreads(); }
    }

#pragma unroll
    for (int mt = 0; mt < 2; mt++) {
        int mloc = wm * 32 + mt * 16 + (lane >> 2);
#pragma unroll
        for (int half = 0; half < 2; half++) {
            int oc = rowBase + mloc + half * 8;
            float scale = bnw[oc] * rsqrtf(bnv[oc] + 1e-5f);
            float shift = bnb[oc] - bnm[oc] * scale;
            size_t ro = (size_t)oc * NTOT;
#pragma unroll
            for (int nt = 0; nt < 8; nt++) {
                int n = colBase + wn * 64 + nt * 8 + (lane & 3) * 2;
                float ox = fmaxf(acc[mt][nt][half * 2 + 0] * scale + shift, 0.f);
                float oy = fmaxf(acc[mt][nt][half * 2 + 1] * scale + shift, 0.f);
                float2 o; o.x = ox; o.y = oy;
                *(float2*)&Op[ro + n] = o;
                OpT[(size_t)n * CDIM + oc]       = __float2half_rn(ox);
                OpT[(size_t)(n + 1) * CDIM + oc] = __float2half_rn(oy);
            }
        }
    }
}

// ====== tc_nn: C[d,m] = sum_c W[d,c]*Bt[m,c] + bias[d]; optional gate; half [d][m] out ======
__global__ __launch_bounds__(256) void tc_nn(
    const float* __restrict__ W, const __half* __restrict__ Bt,
    const float* __restrict__ bias, const float* __restrict__ gateSrc,
    __half* __restrict__ Out)
{
    extern __shared__ char smem[];
    uint32_t sb = smem_u32(smem);
    const int tid = threadIdx.x;
    const __half* Bp = Bt + (size_t)blockIdx.z * NTOT * CDIM;
    const float* Gp = gateSrc ? gateSrc + (size_t)blockIdx.z * CDIM * NTOT : (const float*)0;
    __half* Op = Out + (size_t)blockIdx.z * CDIM * NTOT;
    const int rowBase = blockIdx.y * TCM;
    const int colBase = blockIdx.x * TCN;

    uint32_t tilesAddr = (sb + 1024 + 1023) & ~1023u;
    char* tiles = smem + (tilesAddr - sb);
    const uint32_t aT[2] = { tilesAddr,          tilesAddr + 2 * TILE16 };
    const uint32_t bT[2] = { tilesAddr + TILE16, tilesAddr + 3 * TILE16 };

    MMA_PRECOMP16();

    const int NC = CDIM / TCK;   // 8
    uint4 aH[4], bH[4];

    auto loadRegs = [&](int ci) {
        const int k0 = ci * TCK;
#pragma unroll
        for (int s = 0; s < 4; s++) {
            int row = row0 + s * 32;
            const float* src = &W[(size_t)(rowBase + row) * CDIM + k0 + col8 * 8];
            aH[s] = pack8h(*(const float4*)src, *(const float4*)(src + 4));
            bH[s] = *(const uint4*)&Bp[(size_t)(colBase + row) * CDIM + k0 + col8 * 8];
        }
    };
    auto stsRegs = [&](int buf) {
        char* ta = tiles + (buf ? 2 * TILE16 : 0);
        char* tb = ta + TILE16;
#pragma unroll
        for (int s = 0; s < 4; s++) {
            int row = row0 + s * 32;
            *(uint4*)(ta + SWZ(row * 128 + col8 * 16)) = aH[s];
            *(uint4*)(tb + SWZ(row * 128 + col8 * 16)) = bH[s];
        }
    };

    loadRegs(0); stsRegs(0);
    __syncthreads();
    for (int ci = 0; ci < NC; ci++) {
        const int cur = ci & 1;
        if (ci + 1 < NC) loadRegs(ci + 1);
        mma_chunk16(aT[cur], bT[cur], aOff, bOff, aColSel, bColSel, xorv, acc);
        if (ci + 1 < NC) { stsRegs(cur ^ 1); __syncthreads(); }
    }

#pragma unroll
    for (int mt = 0; mt < 2; mt++) {
        int mloc = wm * 32 + mt * 16 + (lane >> 2);
#pragma unroll
        for (int half = 0; half < 2; half++) {
            int d = rowBase + mloc + half * 8;
            float bv = bias[d];
            size_t ro = (size_t)d * NTOT;
#pragma unroll
            for (int nt = 0; nt < 8; nt++) {
                int n = colBase + wn * 64 + nt * 8 + (lane & 3) * 2;
                float ox = acc[mt][nt][half * 2 + 0] + bv;
                float oy = acc[mt][nt][half * 2 + 1] + bv;
                if (Gp) {
                    float2 gv = *(const float2*)&Gp[ro + n];
                    ox = gv.x * (1.f / (1.f + __expf(-ox)));
                    oy = gv.y * (1.f / (1.f + __expf(-oy)));
                }
                *(__half2*)&Op[ro + n] = __floats2half2_rn(ox, oy);
            }
        }
    }
}

// ---------------- transpose: fp32 [C][N] -> fp16 [N][C] ----------------
__global__ __launch_bounds__(256) void transpose_c2n(
    const float* __restrict__ X, __half* __restrict__ Xt)
{
    __shared__ float tile[32][33];
    const int b = blockIdx.z;
    const int n0 = blockIdx.x * 32, c0 = blockIdx.y * 32;
    const int tx = threadIdx.x & 31, ty = threadIdx.x >> 5;   // 32x8
    const float* Xp = X + (size_t)b * CDIM * NTOT;
    __half* Tp = Xt + (size_t)b * NTOT * CDIM;
#pragma unroll
    for (int k = 0; k < 4; k++)
        tile[ty + 8 * k][tx] = Xp[(size_t)(c0 + ty + 8 * k) * NTOT + n0 + tx];
    __syncthreads();
#pragma unroll
    for (int k = 0; k < 4; k++)
        Tp[(size_t)(n0 + ty + 8 * k) * CDIM + c0 + tx] = __float2half_rn(tile[tx][ty + 8 * k]);
}

// ---------------- conv weight reorder: OIHW fp32 -> [oc][(tap)*512+ic] fp16 ----------------
__global__ __launch_bounds__(256) void reorder_w(
    const float* __restrict__ W, __half* __restrict__ Wr)
{
    int idx = blockIdx.x * 256 + threadIdx.x;
    if (idx < CDIM * KCONV) {
        int oc = idx / KCONV, kk = idx - oc * KCONV;
        int tap = kk >> 9, ic = kk & 511;
        Wr[idx] = __float2half_rn(W[(size_t)oc * KCONV + ic * 9 + tap]);
    }
}

// ---------------- fp32 kernels: q/k projections, energy ----------------
__global__ __launch_bounds__(256) void gemm_nn_bias(
    const float* __restrict__ A, const float* __restrict__ B,
    const float* __restrict__ bias, float* __restrict__ Cout,
    int M, int K, size_t strideB, size_t strideC)
{
    __shared__ float As[BK][BM+PAD];
    __shared__ float Bs[BK][BN+PAD];
    const int tid = threadIdx.x;
    const int ty = tid >> 4, tx = tid & 15;
    const float* Bp = B + (size_t)blockIdx.z * strideB;
    float* Cp = Cout + (size_t)blockIdx.z * strideC;
    const int rowBase = blockIdx.y * BM;
    const int colBase = blockIdx.x * BN;
    float acc[8][4];
#pragma unroll
    for (int i = 0; i < 8; i++)
#pragma unroll
        for (int j = 0; j < 4; j++) acc[i][j] = 0.f;
    for (int k0 = 0; k0 < K; k0 += BK) {
#pragma unroll
        for (int s = 0; s < 8; s++) {
            int idx = tid + s * 256;
            int kk = idx & 15, ii = idx >> 4;
            int gr = rowBase + ii;
            As[kk][ii] = (gr < M) ? A[(size_t)gr * K + k0 + kk] : 0.f;
        }
#pragma unroll
        for (int s = 0; s < 4; s++) {
            int idx = tid + s * 256;
            int jj = idx & 63, kk = idx >> 6;
            Bs[kk][jj] = Bp[(size_t)(k0 + kk) * NTOT + colBase + jj];
        }
        __syncthreads();
#pragma unroll
        for (int kk = 0; kk < BK; kk++) {
            float a[8], bb[4];
            *(float4*)&a[0] = *(const float4*)&As[kk][ty * 8];
            *(float4*)&a[4] = *(const float4*)&As[kk][ty * 8 + 4];
            *(float4*)&bb[0] = *(const float4*)&Bs[kk][tx * 4];
#pragma unroll
            for (int i = 0; i < 8; i++)
#pragma unroll
                for (int j = 0; j < 4; j++) acc[i][j] = fmaf(a[i], bb[j], acc[i][j]);
        }
        __syncthreads();
    }
#pragma unroll
    for (int i = 0; i < 8; i++) {
        int gr = rowBase + ty * 8 + i;
        if (gr < M) {
            float bv = bias[gr];
            size_t base = (size_t)gr * NTOT + colBase + tx * 4;
#pragma unroll
            for (int j = 0; j < 4; j++) Cp[base + j] = acc[i][j] + bv;
        }
    }
}

__global__ __launch_bounds__(256) void gemm_tn(
    const float* __restrict__ A, const float* __restrict__ B, float* __restrict__ Cout,
    int M, int K, size_t strideA, size_t strideB, size_t strideC)
{
    __shared__ float As[BK][BM+PAD];
    __shared__ float Bs[BK][BN+PAD];
    const int tid = threadIdx.x;
    const int ty = tid >> 4, tx = tid & 15;
    const float* Ap = A + (size_t)blockIdx.z * strideA;
    const float* Bp = B + (size_t)blockIdx.z * strideB;
    float* Cp = Cout + (size_t)blockIdx.z * strideC;
    const int rowBase = blockIdx.y * BM;
    const int colBase = blockIdx.x * BN;
    float acc[8][4];
#pragma unroll
    for (int i = 0; i < 8; i++)
#pragma unroll
        for (int j = 0; j < 4; j++) acc[i][j] = 0.f;
    for (int k0 = 0; k0 < K; k0 += BK) {
#pragma unroll
        for (int s = 0; s < 8; s++) {
            int idx = tid + s * 256;
            int ii = idx & 127, kk = idx >> 7;
            As[kk][ii] = Ap[(size_t)(k0 + kk) * M + rowBase + ii];
        }
#pragma unroll
        for (int s = 0; s < 4; s++) {
            int idx = tid + s * 256;
            int jj = idx & 63, kk = idx >> 6;
            Bs[kk][jj] = Bp[(size_t)(k0 + kk) * NTOT + colBase + jj];
        }
        __syncthreads();
#pragma unroll
        for (int kk = 0; kk < BK; kk++) {
            float a[8], bb[4];
            *(float4*)&a[0] = *(const float4*)&As[kk][ty * 8];
            *(float4*)&a[4] = *(const float4*)&As[kk][ty * 8 + 4];
            *(float4*)&bb[0] = *(const float4*)&Bs[kk][tx * 4];
#pragma unroll
            for (int i = 0; i < 8; i++)
#pragma unroll
                for (int j = 0; j < 4; j++) acc[i][j] = fmaf(a[i], bb[j], acc[i][j]);
        }
        __syncthreads();
    }
#pragma unroll
    for (int i = 0; i < 8; i++) {
        int gr = rowBase + ty * 8 + i;
        size_t base = (size_t)gr * NTOT + colBase + tx * 4;
#pragma unroll
        for (int j = 0; j < 4; j++) Cp[base + j] = acc[i][j];
    }
}

// ---- softmax: per-row, 3 shifts (global / band12 / band6), 3 fp16 outputs ----
__global__ __launch_bounds__(256) void softmax_rows3(
    const float* __restrict__ P,
    __half* __restrict__ Ph0, __half* __restrict__ Ph1, __half* __restrict__ Ph2,
    float* __restrict__ inv0, float* __restrict__ inv1, float* __restrict__ inv2)
{
    __shared__ float rowv[NTOT];
    __shared__ float red[256];
    const int row = blockIdx.x, b = blockIdx.y, tid = threadIdx.x;
    const size_t roff = ((size_t)b * NTOT + row) * NTOT;
    const float* p = P + roff;

    for (int n = tid; n < NTOT; n += 256) rowv[n] = p[n];
    __syncthreads();

    const int rm = row / HW, cm = row - rm * HW;
    float m0 = -1e30f, m6 = -1e30f, m12 = -1e30f;
    for (int n = tid; n < NTOT; n += 256) {
        float v = rowv[n];
        m0 = fmaxf(m0, v);
        int rn = n / HW, cn = n - rn * HW;
        int dr = rm - rn; dr = dr < 0 ? -dr : dr;
        int dc = cm - cn; dc = dc < 0 ? -dc : dc;
        int d = dr > dc ? dr : dc;
        if (d <= 12) { m12 = fmaxf(m12, v); if (d <= 6) m6 = fmaxf(m6, v); }
    }
    red[tid] = m0; __syncthreads();
    for (int s = 128; s > 0; s >>= 1) { if (tid < s) red[tid] = fmaxf(red[tid], red[tid + s]); __syncthreads(); }
    m0 = red[0]; __syncthreads();
    red[tid] = m6; __syncthreads();
    for (int s = 128; s > 0; s >>= 1) { if (tid < s) red[tid] = fmaxf(red[tid], red[tid + s]); __syncthreads(); }
    m6 = red[0]; __syncthreads();
    red[tid] = m12; __syncthreads();
    for (int s = 128; s > 0; s >>= 1) { if (tid < s) red[tid] = fmaxf(red[tid], red[tid + s]); __syncthreads(); }
    m12 = red[0]; __syncthreads();

    float s0 = 0.f, s1 = 0.f, s2 = 0.f;
    for (int n = tid; n < NTOT; n += 256) {
        float v = rowv[n];
        __half h0 = __float2half_rn(__expf(v - m0));
        Ph0[roff + n] = h0;
        s0 += __half2float(h0);
        int rn = n / HW, cn = n - rn * HW;
        int dr = rm - rn; dr = dr < 0 ? -dr : dr;
        int dc = cm - cn; dc = dc < 0 ? -dc : dc;
        int d = dr > dc ? dr : dc;
        __half h1 = __ushort_as_half(0), h2 = __ushort_as_half(0);
        if (d <= 12) {
            h2 = __float2half_rn(__expf(v - m12));
            s2 += __half2float(h2);
            if (d <= 6) { h1 = __float2half_rn(__expf(v - m6)); s1 += __half2float(h1); }
        }
        Ph1[roff + n] = h1;
        Ph2[roff + n] = h2;
    }
    red[tid] = s0; __syncthreads();
    for (int s = 128; s > 0; s >>= 1) { if (tid < s) red[tid] += red[tid + s]; __syncthreads(); }
    if (tid == 0) inv0[(size_t)b * NTOT + row] = 1.f / red[0];
    __syncthreads();
    red[tid] = s1; __syncthreads();
    for (int s = 128; s > 0; s >>= 1) { if (tid < s) red[tid] += red[tid + s]; __syncthreads(); }
    if (tid == 0) inv1[(size_t)b * NTOT + row] = 1.f / red[0];
    __syncthreads();
    red[tid] = s2; __syncthreads();
    for (int s = 128; s > 0; s >>= 1) { if (tid < s) red[tid] += red[tid + s]; __syncthreads(); }
    if (tid == 0) inv2[(size_t)b * NTOT + row] = 1.f / red[0];
}

// ---------------- launch ----------------
extern "C" void kernel_launch(void* const* d_in, const int* in_sizes, int n_in,
                              void* d_out, int out_size)
{
    const float* x       = (const float*)d_in[0];
    const float* Wq      = (const float*)d_in[1];
    const float* bq      = (const float*)d_in[2];
    const float* Wk      = (const float*)d_in[3];
    const float* bk      = (const float*)d_in[4];
    const float* Wv      = (const float*)d_in[5];
    const float* bv      = (const float*)d_in[6];
    const float* conv1_w = (const float*)d_in[7];
    const float* bn1_w   = (const float*)d_in[8];
    const float* bn1_b   = (const float*)d_in[9];
    const float* bn1_m   = (const float*)d_in[10];
    const float* bn1_v   = (const float*)d_in[11];
    const float* conv2_w = (const float*)d_in[12];
    const float* bn2_w   = (const float*)d_in[13];
    const float* bn2_b   = (const float*)d_in[14];
    const float* bn2_m   = (const float*)d_in[15];
    const float* bn2_v   = (const float*)d_in[16];
    const float* sig1_w  = (const float*)d_in[17];
    const float* sig1_b  = (const float*)d_in[18];
    const float* sig2_w  = (const float*)d_in[19];
    const float* sig2_b  = (const float*)d_in[20];
    const float* gamma   = (const float*)d_in[21];
    const float* gamma1  = (const float*)d_in[22];
    const float* gamma2  = (const float*)d_in[23];

    float *q, *k, *p, *i0, *i1, *i2, *t1, *t2;
    __half *ph0, *ph1, *ph2, *v, *s, *xt, *yt, *t1t, *t2t, *w1r, *w2r;
    cudaGetSymbolAddress((void**)&q,   g_q);
    cudaGetSymbolAddress((void**)&k,   g_k);
    cudaGetSymbolAddress((void**)&p,   g_p);
    cudaGetSymbolAddress((void**)&ph0, g_ph0);
    cudaGetSymbolAddress((void**)&ph1, g_ph1);
    cudaGetSymbolAddress((void**)&ph2, g_ph2);
    cudaGetSymbolAddress((void**)&v,   g_v);
    cudaGetSymbolAddress((void**)&s,   g_s);
    cudaGetSymbolAddress((void**)&i0,  g_inv0);
    cudaGetSymbolAddress((void**)&i1,  g_inv1);
    cudaGetSymbolAddress((void**)&i2,  g_inv2);
    cudaGetSymbolAddress((void**)&xt,  g_xt);
    cudaGetSymbolAddress((void**)&yt,  g_yt);
    cudaGetSymbolAddress((void**)&t1,  g_t1);
    cudaGetSymbolAddress((void**)&t1t, g_t1t);
    cudaGetSymbolAddress((void**)&t2,  g_t2);
    cudaGetSymbolAddress((void**)&t2t, g_t2t);
    cudaGetSymbolAddress((void**)&w1r, g_w1r);
    cudaGetSymbolAddress((void**)&w2r, g_w2r);

    cudaFuncSetAttribute((const void*)tc_attn<-1, true>,  cudaFuncAttributeMaxDynamicSharedMemorySize, SMEM_TC_SZ);
    cudaFuncSetAttribute((const void*)tc_attn<6, true>,   cudaFuncAttributeMaxDynamicSharedMemorySize, SMEM_TC_SZ);
    cudaFuncSetAttribute((const void*)tc_attn<12, false>, cudaFuncAttributeMaxDynamicSharedMemorySize, SMEM_TC_SZ);
    cudaFuncSetAttribute((const void*)tc_conv,            cudaFuncAttributeMaxDynamicSharedMemorySize, SMEM_TC_SZ);
    cudaFuncSetAttribute((const void*)tc_nn,              cudaFuncAttributeMaxDynamicSharedMemorySize, SMEM_TC_SZ);

    const dim3 blk(256);
    const dim3 gSmall(NTOT / BN, 1, BDIM);
    const dim3 gEnergy(NTOT / BN, NTOT / BM, BDIM);
    const dim3 gTC(NTOT / TCN, CDIM / TCM, BDIM);   // (18, 4, 4)
    const dim3 gTr(NTOT / 32, CDIM / 32, BDIM);
    const size_t sX = (size_t)CDIM * NTOT;
    const size_t sQ = (size_t)DQD * NTOT;
    const size_t sP = (size_t)NTOT * NTOT;
    const int wElems = CDIM * KCONV;

    // prep: transposed fp16 x, reordered fp16 conv weights
    transpose_c2n<<<gTr, blk>>>(x, xt);
    reorder_w<<<(wElems + 255) / 256, blk>>>(conv1_w, w1r);
    reorder_w<<<(wElems + 255) / 256, blk>>>(conv2_w, w2r);

    // q, k (fp32), v (fp16 mma over xt)
    gemm_nn_bias<<<gSmall, blk>>>(Wq, x, bq, q, DQD, CDIM, sX, sQ);
    gemm_nn_bias<<<gSmall, blk>>>(Wk, x, bk, k, DQD, CDIM, sX, sQ);
    tc_nn<<<gTC, blk, SMEM_TC_SZ>>>(Wv, xt, bv, (const float*)0, v);

    // energy + 3-shift softmax
    gemm_tn<<<gEnergy, blk>>>(q, k, p, NTOT, DQD, sQ, sQ, sP);
    softmax_rows3<<<dim3(NTOT, BDIM), blk>>>(p, ph0, ph1, ph2, i0, i1, i2);

    // stage 0
    tc_attn<-1, true><<<gTC, blk, SMEM_TC_SZ>>>(v, ph0, i0, gamma, x, (float*)0, yt);
    tc_conv<<<gTC, blk, SMEM_TC_SZ>>>(w1r, yt, bn1_w, bn1_b, bn1_m, bn1_v, t1, t1t);

    // stage 1
    tc_nn<<<gTC, blk, SMEM_TC_SZ>>>(sig1_w, t1t, sig1_b, t1, s);
    tc_attn<6, true><<<gTC, blk, SMEM_TC_SZ>>>(s, ph1, i1, gamma1, t1, (float*)0, yt);
    tc_conv<<<gTC, blk, SMEM_TC_SZ>>>(w2r, yt, bn2_w, bn2_b, bn2_m, bn2_v, t2, t2t);

    // stage 2
    tc_nn<<<gTC, blk, SMEM_TC_SZ>>>(sig2_w, t2t, sig2_b, t2, s);
    tc_attn<12, false><<<gTC, blk, SMEM_TC_SZ>>>(s, ph2, i2, gamma2, t2, (float*)d_out, (__half*)0);
}

// round 7
// speedup vs baseline: 5.9905x; 1.3570x over previous
#include <cuda_runtime.h>
#include <cuda_fp16.h>
#include <stdint.h>

#define NTOT 2304
#define BDIM 4
#define CDIM 512
#define DQD  64
#define HW   48
#define KCONV (CDIM * 9)

// ---------------- fp32 tile config (qk projection) ----------------
#define BM 128
#define BN 64
#define BK 16
#define PAD 4

// ---------------- fp16 mma tile config ----------------
#define TCM 128
#define TCN 128
#define TCK 64                          // k halves per chunk (=128B row)
#define TILE16 (TCM * TCK * 2)          // 16384 bytes
#define NSTAGE 3
#define SMEM_TC_SZ (2048 + 2 * NSTAGE * TILE16)  // 100352

#define SWZ(off) ((off) ^ (((off) >> 3) & 0x70))

// ---------------- scratch ----------------
__device__ __half g_qh [BDIM*NTOT*128];              // q hi/lo [n][128]
__device__ __half g_kh [BDIM*NTOT*128];              // k hi/lo [n][128]
__device__ float  g_p [(size_t)BDIM*NTOT*NTOT];      // energy (fp32)
__device__ __half g_ph0[(size_t)BDIM*NTOT*NTOT];
__device__ __half g_ph1[(size_t)BDIM*NTOT*NTOT];
__device__ __half g_ph2[(size_t)BDIM*NTOT*NTOT];
__device__ __half g_v  [BDIM*CDIM*NTOT];
__device__ __half g_s  [BDIM*CDIM*NTOT];
__device__ float  g_inv0[BDIM*NTOT];
__device__ float  g_inv1[BDIM*NTOT];
__device__ float  g_inv2[BDIM*NTOT];
__device__ __half g_xt [BDIM*NTOT*CDIM];
__device__ __half g_yt [BDIM*NTOT*CDIM];
__device__ float  g_t1 [BDIM*CDIM*NTOT];
__device__ __half g_t1t[BDIM*NTOT*CDIM];
__device__ float  g_t2 [BDIM*CDIM*NTOT];
__device__ __half g_t2t[BDIM*NTOT*CDIM];
__device__ __half g_w1r[CDIM*KCONV];
__device__ __half g_w2r[CDIM*KCONV];
__device__ __half g_wv16[CDIM*CDIM];
__device__ __half g_ws1[CDIM*CDIM];
__device__ __half g_ws2[CDIM*CDIM];

// ---------------- helpers ----------------
__device__ __forceinline__ uint32_t smem_u32(const void* p) {
    return (uint32_t)__cvta_generic_to_shared(p);
}
__device__ __forceinline__ void ldsm4(uint32_t* r, uint32_t addr) {
    asm volatile("ldmatrix.sync.aligned.m8n8.x4.shared.b16 {%0,%1,%2,%3}, [%4];"
        : "=r"(r[0]), "=r"(r[1]), "=r"(r[2]), "=r"(r[3]) : "r"(addr));
}
__device__ __forceinline__ void mma16816(float* c, const uint32_t* a, const uint32_t* b) {
    asm volatile("mma.sync.aligned.m16n8k16.row.col.f32.f16.f16.f32 "
        "{%0,%1,%2,%3}, {%4,%5,%6,%7}, {%8,%9}, {%0,%1,%2,%3};"
        : "+f"(c[0]), "+f"(c[1]), "+f"(c[2]), "+f"(c[3])
        : "r"(a[0]), "r"(a[1]), "r"(a[2]), "r"(a[3]), "r"(b[0]), "r"(b[1]));
}
#define CP_A16(dst, src) \
    asm volatile("cp.async.cg.shared.global [%0], [%1], 16;" :: "r"(dst), "l"(src))
#define CP_A16Z(dst, src, sz) \
    asm volatile("cp.async.cg.shared.global [%0], [%1], 16, %2;" :: "r"(dst), "l"(src), "r"(sz))
#define CP_COMMIT() asm volatile("cp.async.commit_group;")
#define CP_WAIT1()  asm volatile("cp.async.wait_group 1;")

// one 128x128x64 chunk of fp16 mma
__device__ __forceinline__ void mma_chunk16(
    uint32_t aT, uint32_t bT,
    const uint32_t aOff[2], const uint32_t bOff[4],
    uint32_t aColSel, uint32_t bColSel, uint32_t xorv,
    float (&acc)[2][8][4])
{
#pragma unroll
    for (int g = 0; g < 4; g++) {
        uint32_t ka = ((uint32_t)(g * 32) + aColSel) ^ xorv;
        uint32_t kb = ((uint32_t)(g * 32) + bColSel) ^ xorv;
        uint32_t af[2][4];
        ldsm4(af[0], aT + aOff[0] + ka);
        ldsm4(af[1], aT + aOff[1] + ka);
#pragma unroll
        for (int p = 0; p < 4; p++) {
            uint32_t bf[4];
            ldsm4(bf, bT + bOff[p] + kb);
            mma16816(acc[0][2 * p],     af[0], bf);
            mma16816(acc[0][2 * p + 1], af[0], bf + 2);
            mma16816(acc[1][2 * p],     af[1], bf);
            mma16816(acc[1][2 * p + 1], af[1], bf + 2);
        }
    }
}

// per-thread precompute: 4x2 warp grid, warp tile 32x64
#define MMA_PRECOMP16() \
    const int lane = tid & 31, wid = tid >> 5; \
    const int wm = wid >> 1, wn = wid & 1; \
    const int j8 = lane >> 3, rr = lane & 7; \
    const uint32_t xorv = rr * 16; \
    const uint32_t aColSel = (j8 >> 1) * 16; \
    const uint32_t bColSel = (j8 & 1) * 16; \
    uint32_t aOff[2], bOff[4]; \
    aOff[0] = (wm * 32 +      (j8 & 1) * 8 + rr) * 128; \
    aOff[1] = aOff[0] + 16 * 128; \
    bOff[0] = (wn * 64 +      (j8 >> 1) * 8 + rr) * 128; \
    bOff[1] = bOff[0] + 16 * 128; \
    bOff[2] = bOff[0] + 32 * 128; \
    bOff[3] = bOff[0] + 48 * 128; \
    const int col8 = tid & 7; \
    const int row0 = tid >> 3; \
    float acc[2][8][4]; \
_Pragma("unroll") \
    for (int i_ = 0; i_ < 2; i_++) \
_Pragma("unroll") \
        for (int j_ = 0; j_ < 8; j_++) \
_Pragma("unroll") \
            for (int e_ = 0; e_ < 4; e_++) acc[i_][j_][e_] = 0.f;

// tiles base + stage addresses
#define TILES_SETUP() \
    uint32_t tilesAddr = (sb + 1024 + 1023) & ~1023u; \
    uint32_t stA[NSTAGE], stB[NSTAGE]; \
_Pragma("unroll") \
    for (int s_ = 0; s_ < NSTAGE; s_++) { \
        stA[s_] = tilesAddr + s_ * 2 * TILE16; \
        stB[s_] = stA[s_] + TILE16; \
    }

// ========== tc_attn ==========
template<int RADIUS, bool OUT_T>
__global__ __launch_bounds__(256) void tc_attn(
    const __half* __restrict__ A, const __half* __restrict__ P,
    const float* __restrict__ invsum, const float* __restrict__ gammaPtr,
    const float* __restrict__ Res, float* __restrict__ OutF, __half* __restrict__ OutT)
{
    extern __shared__ char smem[];
    uint32_t sb = smem_u32(smem);
    float* smf = (float*)smem;
    const int tid = threadIdx.x;
    const int bz = blockIdx.z;
    const __half* Ap = A + (size_t)bz * CDIM * NTOT;
    const __half* Pp = P + (size_t)bz * NTOT * NTOT;
    const float* Rp = Res + (size_t)bz * CDIM * NTOT;
    const int rowBase = blockIdx.y * TCM;
    const int colBase = blockIdx.x * TCN;

    TILES_SETUP();
    MMA_PRECOMP16();

    if (tid < TCN) smf[tid] = invsum[(size_t)bz * NTOT + colBase + tid];

    int kStart = 0, kEnd = NTOT;
    if (RADIUS >= 0) {
        int rmLo = colBase / HW, rmHi = (colBase + TCN - 1) / HW;
        int rlo = rmLo - RADIUS; if (rlo < 0) rlo = 0;
        int rhi = rmHi + RADIUS; if (rhi > HW - 1) rhi = HW - 1;
        kStart = (rlo * HW) & ~(TCK - 1);
        kEnd = ((rhi + 1) * HW + TCK - 1) & ~(TCK - 1);
        if (kEnd > NTOT) kEnd = NTOT;
    }
    const int NC = (kEnd - kStart) / TCK;

    auto issueLoads = [&](int ci, int st) {
        const int k0 = kStart + ci * TCK;
#pragma unroll
        for (int s = 0; s < 4; s++) {
            int row = row0 + s * 32;
            uint32_t sw = SWZ(row * 128 + col8 * 16);
            CP_A16(stA[st] + sw, &Ap[(size_t)(rowBase + row) * NTOT + k0 + col8 * 8]);
            CP_A16(stB[st] + sw, &Pp[(size_t)(colBase + row) * NTOT + k0 + col8 * 8]);
        }
    };

#pragma unroll
    for (int s = 0; s < NSTAGE - 1; s++) {
        if (s < NC) issueLoads(s, s);
        CP_COMMIT();
    }
    for (int ci = 0; ci < NC; ci++) {
        CP_WAIT1();
        __syncthreads();
        int nci = ci + NSTAGE - 1;
        if (nci < NC) issueLoads(nci, nci % NSTAGE);
        CP_COMMIT();
        int st = ci % NSTAGE;
        mma_chunk16(stA[st], stB[st], aOff, bOff, aColSel, bColSel, xorv, acc);
    }

    const float g = *gammaPtr;
    float* OpF = OUT_T ? (float*)0 : OutF + (size_t)bz * CDIM * NTOT;
    __half* OpT = OUT_T ? OutT + (size_t)bz * NTOT * CDIM : (__half*)0;
#pragma unroll
    for (int mt = 0; mt < 2; mt++) {
        int mloc = wm * 32 + mt * 16 + (lane >> 2);
#pragma unroll
        for (int half = 0; half < 2; half++) {
            int c = rowBase + mloc + half * 8;
            size_t ro = (size_t)c * NTOT;
#pragma unroll
            for (int nt = 0; nt < 8; nt++) {
                int nl = wn * 64 + nt * 8 + (lane & 3) * 2;
                int n = colBase + nl;
                float2 res = *(const float2*)&Rp[ro + n];
                float ox = acc[mt][nt][half * 2 + 0] * (g * smf[nl])     + res.x;
                float oy = acc[mt][nt][half * 2 + 1] * (g * smf[nl + 1]) + res.y;
                if (OUT_T) {
                    OpT[(size_t)n * CDIM + c]       = __float2half_rn(ox);
                    OpT[(size_t)(n + 1) * CDIM + c] = __float2half_rn(oy);
                } else {
                    float2 o; o.x = ox; o.y = oy;
                    *(float2*)&OpF[ro + n] = o;
                }
            }
        }
    }
}

// ========== tc_conv ==========
__global__ __launch_bounds__(256) void tc_conv(
    const __half* __restrict__ Wr, const __half* __restrict__ Xt,
    const float* __restrict__ bnw, const float* __restrict__ bnb,
    const float* __restrict__ bnm, const float* __restrict__ bnv,
    float* __restrict__ Out, __half* __restrict__ OutT)
{
    extern __shared__ char smem[];
    uint32_t sb = smem_u32(smem);
    const int tid = threadIdx.x;
    const __half* Xp = Xt + (size_t)blockIdx.z * NTOT * CDIM;
    float* Op = Out + (size_t)blockIdx.z * CDIM * NTOT;
    __half* OpT = OutT + (size_t)blockIdx.z * NTOT * CDIM;
    const int rowBase = blockIdx.y * TCM;
    const int colBase = blockIdx.x * TCN;

    TILES_SETUP();
    MMA_PRECOMP16();

    int pys[4], pxs[4];
#pragma unroll
    for (int s = 0; s < 4; s++) {
        int pix = colBase + row0 + s * 32;
        pys[s] = pix / HW; pxs[s] = pix - pys[s] * HW;
    }

    const int NC = KCONV / TCK;   // 72

    auto issueLoads = [&](int ci, int st) {
        const int k0 = ci * TCK;
        const int tap = ci >> 3;
        const int icb = (ci & 7) * TCK;
        const int ky = tap / 3, kx = tap - ky * 3;
#pragma unroll
        for (int s = 0; s < 4; s++) {
            int row = row0 + s * 32;
            uint32_t sw = SWZ(row * 128 + col8 * 16);
            CP_A16(stA[st] + sw, &Wr[(size_t)(rowBase + row) * KCONV + k0 + col8 * 8]);
            int iy = pys[s] + ky - 1, ix = pxs[s] + kx - 1;
            bool ok = (unsigned)iy < HW && (unsigned)ix < HW;
            const __half* src = ok ? &Xp[(size_t)(iy * HW + ix) * CDIM + icb + col8 * 8] : Xp;
            CP_A16Z(stB[st] + sw, src, ok ? 16u : 0u);
        }
    };

#pragma unroll
    for (int s = 0; s < NSTAGE - 1; s++) {
        if (s < NC) issueLoads(s, s);
        CP_COMMIT();
    }
    for (int ci = 0; ci < NC; ci++) {
        CP_WAIT1();
        __syncthreads();
        int nci = ci + NSTAGE - 1;
        if (nci < NC) issueLoads(nci, nci % NSTAGE);
        CP_COMMIT();
        int st = ci % NSTAGE;
        mma_chunk16(stA[st], stB[st], aOff, bOff, aColSel, bColSel, xorv, acc);
    }

#pragma unroll
    for (int mt = 0; mt < 2; mt++) {
        int mloc = wm * 32 + mt * 16 + (lane >> 2);
#pragma unroll
        for (int half = 0; half < 2; half++) {
            int oc = rowBase + mloc + half * 8;
            float scale = bnw[oc] * rsqrtf(bnv[oc] + 1e-5f);
            float shift = bnb[oc] - bnm[oc] * scale;
            size_t ro = (size_t)oc * NTOT;
#pragma unroll
            for (int nt = 0; nt < 8; nt++) {
                int n = colBase + wn * 64 + nt * 8 + (lane & 3) * 2;
                float ox = fmaxf(acc[mt][nt][half * 2 + 0] * scale + shift, 0.f);
                float oy = fmaxf(acc[mt][nt][half * 2 + 1] * scale + shift, 0.f);
                float2 o; o.x = ox; o.y = oy;
                *(float2*)&Op[ro + n] = o;
                OpT[(size_t)n * CDIM + oc]       = __float2half_rn(ox);
                OpT[(size_t)(n + 1) * CDIM + oc] = __float2half_rn(oy);
            }
        }
    }
}

// ====== tc_nn: fp16 weights [d][c], fp16 Bt [m][c]; optional gate; half [d][m] out ======
__global__ __launch_bounds__(256) void tc_nn(
    const __half* __restrict__ W16, const __half* __restrict__ Bt,
    const float* __restrict__ bias, const float* __restrict__ gateSrc,
    __half* __restrict__ Out)
{
    extern __shared__ char smem[];
    uint32_t sb = smem_u32(smem);
    const int tid = threadIdx.x;
    const __half* Bp = Bt + (size_t)blockIdx.z * NTOT * CDIM;
    const float* Gp = gateSrc ? gateSrc + (size_t)blockIdx.z * CDIM * NTOT : (const float*)0;
    __half* Op = Out + (size_t)blockIdx.z * CDIM * NTOT;
    const int rowBase = blockIdx.y * TCM;
    const int colBase = blockIdx.x * TCN;

    TILES_SETUP();
    MMA_PRECOMP16();

    const int NC = CDIM / TCK;   // 8

    auto issueLoads = [&](int ci, int st) {
        const int k0 = ci * TCK;
#pragma unroll
        for (int s = 0; s < 4; s++) {
            int row = row0 + s * 32;
            uint32_t sw = SWZ(row * 128 + col8 * 16);
            CP_A16(stA[st] + sw, &W16[(size_t)(rowBase + row) * CDIM + k0 + col8 * 8]);
            CP_A16(stB[st] + sw, &Bp[(size_t)(colBase + row) * CDIM + k0 + col8 * 8]);
        }
    };

#pragma unroll
    for (int s = 0; s < NSTAGE - 1; s++) {
        if (s < NC) issueLoads(s, s);
        CP_COMMIT();
    }
    for (int ci = 0; ci < NC; ci++) {
        CP_WAIT1();
        __syncthreads();
        int nci = ci + NSTAGE - 1;
        if (nci < NC) issueLoads(nci, nci % NSTAGE);
        CP_COMMIT();
        int st = ci % NSTAGE;
        mma_chunk16(stA[st], stB[st], aOff, bOff, aColSel, bColSel, xorv, acc);
    }

#pragma unroll
    for (int mt = 0; mt < 2; mt++) {
        int mloc = wm * 32 + mt * 16 + (lane >> 2);
#pragma unroll
        for (int half = 0; half < 2; half++) {
            int d = rowBase + mloc + half * 8;
            float bv = bias[d];
            size_t ro = (size_t)d * NTOT;
#pragma unroll
            for (int nt = 0; nt < 8; nt++) {
                int n = colBase + wn * 64 + nt * 8 + (lane & 3) * 2;
                float ox = acc[mt][nt][half * 2 + 0] + bv;
                float oy = acc[mt][nt][half * 2 + 1] + bv;
                if (Gp) {
                    float2 gv = *(const float2*)&Gp[ro + n];
                    ox = gv.x * (1.f / (1.f + __expf(-ox)));
                    oy = gv.y * (1.f / (1.f + __expf(-oy)));
                }
                *(__half2*)&Op[ro + n] = __floats2half2_rn(ox, oy);
            }
        }
    }
}

// ====== tc_energy: E[m][n] = sum_k qh[m][k]*kh[n][k], K=128 (hi/lo split), fp32 out ======
__global__ __launch_bounds__(256) void tc_energy(
    const __half* __restrict__ Qh, const __half* __restrict__ Kh,
    float* __restrict__ E)
{
    extern __shared__ char smem[];
    uint32_t sb = smem_u32(smem);
    const int tid = threadIdx.x;
    const __half* Ap = Qh + (size_t)blockIdx.z * NTOT * 128;
    const __half* Bp = Kh + (size_t)blockIdx.z * NTOT * 128;
    float* Ep = E + (size_t)blockIdx.z * NTOT * NTOT;
    const int rowBase = blockIdx.y * TCM;
    const int colBase = blockIdx.x * TCN;

    TILES_SETUP();
    MMA_PRECOMP16();

    const int NC = 2;

    auto issueLoads = [&](int ci, int st) {
        const int k0 = ci * TCK;
#pragma unroll
        for (int s = 0; s < 4; s++) {
            int row = row0 + s * 32;
            uint32_t sw = SWZ(row * 128 + col8 * 16);
            CP_A16(stA[st] + sw, &Ap[(size_t)(rowBase + row) * 128 + k0 + col8 * 8]);
            CP_A16(stB[st] + sw, &Bp[(size_t)(colBase + row) * 128 + k0 + col8 * 8]);
        }
    };

#pragma unroll
    for (int s = 0; s < NSTAGE - 1; s++) {
        if (s < NC) issueLoads(s, s);
        CP_COMMIT();
    }
    for (int ci = 0; ci < NC; ci++) {
        CP_WAIT1();
        __syncthreads();
        int nci = ci + NSTAGE - 1;
        if (nci < NC) issueLoads(nci, nci % NSTAGE);
        CP_COMMIT();
        int st = ci % NSTAGE;
        mma_chunk16(stA[st], stB[st], aOff, bOff, aColSel, bColSel, xorv, acc);
    }

#pragma unroll
    for (int mt = 0; mt < 2; mt++) {
        int mloc = wm * 32 + mt * 16 + (lane >> 2);
#pragma unroll
        for (int half = 0; half < 2; half++) {
            int m = rowBase + mloc + half * 8;
            size_t ro = (size_t)m * NTOT;
#pragma unroll
            for (int nt = 0; nt < 8; nt++) {
                int n = colBase + wn * 64 + nt * 8 + (lane & 3) * 2;
                float2 o;
                o.x = acc[mt][nt][half * 2 + 0];
                o.y = acc[mt][nt][half * 2 + 1];
                *(float2*)&Ep[ro + n] = o;
            }
        }
    }
}

// ------- fused q/k projection (fp32 math) -> hi/lo fp16 [n][128] -------
__global__ __launch_bounds__(256) void gemm_qk(
    const float* __restrict__ Wq, const float* __restrict__ bq,
    const float* __restrict__ Wk, const float* __restrict__ bk,
    const float* __restrict__ X,
    __half* __restrict__ Qh, __half* __restrict__ Kh)
{
    __shared__ float As[BK][BM+PAD];
    __shared__ float Bs[BK][BN+PAD];
    const int tid = threadIdx.x;
    const int ty = tid >> 4, tx = tid & 15;
    const float* Bp = X + (size_t)blockIdx.z * CDIM * NTOT;
    __half* qh = Qh + (size_t)blockIdx.z * NTOT * 128;
    __half* kh = Kh + (size_t)blockIdx.z * NTOT * 128;
    const int colBase = blockIdx.x * BN;
    float acc[8][4];
#pragma unroll
    for (int i = 0; i < 8; i++)
#pragma unroll
        for (int j = 0; j < 4; j++) acc[i][j] = 0.f;
    for (int k0 = 0; k0 < CDIM; k0 += BK) {
#pragma unroll
        for (int s = 0; s < 8; s++) {
            int idx = tid + s * 256;
            int kk = idx & 15, ii = idx >> 4;
            As[kk][ii] = (ii < 64) ? Wq[(size_t)ii * CDIM + k0 + kk]
                                   : Wk[(size_t)(ii - 64) * CDIM + k0 + kk];
        }
#pragma unroll
        for (int s = 0; s < 4; s++) {
            int idx = tid + s * 256;
            int jj = idx & 63, kk = idx >> 6;
            Bs[kk][jj] = Bp[(size_t)(k0 + kk) * NTOT + colBase + jj];
        }
        __syncthreads();
#pragma unroll
        for (int kk = 0; kk < BK; kk++) {
            float a[8], bb[4];
            *(float4*)&a[0] = *(const float4*)&As[kk][ty * 8];
            *(float4*)&a[4] = *(const float4*)&As[kk][ty * 8 + 4];
            *(float4*)&bb[0] = *(const float4*)&Bs[kk][tx * 4];
#pragma unroll
            for (int i = 0; i < 8; i++)
#pragma unroll
                for (int j = 0; j < 4; j++) acc[i][j] = fmaf(a[i], bb[j], acc[i][j]);
        }
        __syncthreads();
    }
#pragma unroll
    for (int i = 0; i < 8; i++) {
        int gr = ty * 8 + i;
        bool isQ = gr < 64;
        __half* dst = isQ ? qh : kh;
        int ch = isQ ? gr : gr - 64;
        float bv = isQ ? bq[gr] : bk[gr - 64];
#pragma unroll
        for (int j = 0; j < 4; j++) {
            int n = colBase + tx * 4 + j;
            float val = acc[i][j] + bv;
            __half hi = __float2half_rn(val);
            __half lo = __float2half_rn(val - __half2float(hi));
            dst[(size_t)n * 128 + ch]      = hi;
            dst[(size_t)n * 128 + 64 + ch] = lo;
        }
    }
}

// ---------------- transpose: fp32 [C][N] -> fp16 [N][C] ----------------
__global__ __launch_bounds__(256) void transpose_c2n(
    const float* __restrict__ X, __half* __restrict__ Xt)
{
    __shared__ float tile[32][33];
    const int b = blockIdx.z;
    const int n0 = blockIdx.x * 32, c0 = blockIdx.y * 32;
    const int tx = threadIdx.x & 31, ty = threadIdx.x >> 5;
    const float* Xp = X + (size_t)b * CDIM * NTOT;
    __half* Tp = Xt + (size_t)b * NTOT * CDIM;
#pragma unroll
    for (int k = 0; k < 4; k++)
        tile[ty + 8 * k][tx] = Xp[(size_t)(c0 + ty + 8 * k) * NTOT + n0 + tx];
    __syncthreads();
#pragma unroll
    for (int k = 0; k < 4; k++)
        Tp[(size_t)(n0 + ty + 8 * k) * CDIM + c0 + tx] = __float2half_rn(tile[tx][ty + 8 * k]);
}

// ---------------- conv weight reorder + fp16 cvt ----------------
__global__ __launch_bounds__(256) void reorder_w(
    const float* __restrict__ W, __half* __restrict__ Wr)
{
    int idx = blockIdx.x * 256 + threadIdx.x;
    if (idx < CDIM * KCONV) {
        int oc = idx / KCONV, kk = idx - oc * KCONV;
        int tap = kk >> 9, ic = kk & 511;
        Wr[idx] = __float2half_rn(W[(size_t)oc * KCONV + ic * 9 + tap]);
    }
}
__global__ __launch_bounds__(256) void cvt_w16(
    const float* __restrict__ W, __half* __restrict__ O, int n)
{
    int idx = blockIdx.x * 256 + threadIdx.x;
    if (idx < n) O[idx] = __float2half_rn(W[idx]);
}

// ---- softmax: per-row, 3 shifts, vectorized ----
__global__ __launch_bounds__(256) void softmax_rows3(
    const float* __restrict__ P,
    __half* __restrict__ Ph0, __half* __restrict__ Ph1, __half* __restrict__ Ph2,
    float* __restrict__ inv0, float* __restrict__ inv1, float* __restrict__ inv2)
{
    __shared__ float rowv[NTOT];
    __shared__ float red[256];
    const int row = blockIdx.x, b = blockIdx.y, tid = threadIdx.x;
    const size_t roff = ((size_t)b * NTOT + row) * NTOT;
    const float* p = P + roff;

    for (int i = tid; i < NTOT / 4; i += 256)
        ((float4*)rowv)[i] = ((const float4*)p)[i];
    __syncthreads();

    const int rm = row / HW, cm = row - rm * HW;
    float m0 = -1e30f, m6 = -1e30f, m12 = -1e30f;
    for (int i = tid; i < NTOT / 4; i += 256) {
        float4 v4 = ((const float4*)rowv)[i];
        const float* v = (const float*)&v4;
        int n0 = i * 4;
#pragma unroll
        for (int e = 0; e < 4; e++) {
            int n = n0 + e;
            float v1 = v[e];
            m0 = fmaxf(m0, v1);
            int rn = n / HW, cn = n - rn * HW;
            int dr = rm - rn; dr = dr < 0 ? -dr : dr;
            int dc = cm - cn; dc = dc < 0 ? -dc : dc;
            int d = dr > dc ? dr : dc;
            if (d <= 12) { m12 = fmaxf(m12, v1); if (d <= 6) m6 = fmaxf(m6, v1); }
        }
    }
    red[tid] = m0; __syncthreads();
    for (int s = 128; s > 0; s >>= 1) { if (tid < s) red[tid] = fmaxf(red[tid], red[tid + s]); __syncthreads(); }
    m0 = red[0]; __syncthreads();
    red[tid] = m6; __syncthreads();
    for (int s = 128; s > 0; s >>= 1) { if (tid < s) red[tid] = fmaxf(red[tid], red[tid + s]); __syncthreads(); }
    m6 = red[0]; __syncthreads();
    red[tid] = m12; __syncthreads();
    for (int s = 128; s > 0; s >>= 1) { if (tid < s) red[tid] = fmaxf(red[tid], red[tid + s]); __syncthreads(); }
    m12 = red[0]; __syncthreads();

    float s0 = 0.f, s1 = 0.f, s2 = 0.f;
    for (int i = tid; i < NTOT / 4; i += 256) {
        float4 v4 = ((const float4*)rowv)[i];
        const float* v = (const float*)&v4;
        int n0 = i * 4;
        __half h0a[4], h1a[4], h2a[4];
#pragma unroll
        for (int e = 0; e < 4; e++) {
            int n = n0 + e;
            float v1 = v[e];
            float e0 = __expf(v1 - m0);
            __half h0 = __float2half_rn(e0);
            h0a[e] = h0;
            s0 += __half2float(h0);
            int rn = n / HW, cn = n - rn * HW;
            int dr = rm - rn; dr = dr < 0 ? -dr : dr;
            int dc = cm - cn; dc = dc < 0 ? -dc : dc;
            int d = dr > dc ? dr : dc;
            __half h1 = __ushort_as_half(0), h2 = __ushort_as_half(0);
            if (d <= 12) {
                h2 = __float2half_rn(__expf(v1 - m12));
                s2 += __half2float(h2);
                if (d <= 6) { h1 = __float2half_rn(__expf(v1 - m6)); s1 += __half2float(h1); }
            }
            h1a[e] = h1; h2a[e] = h2;
        }
        *(uint2*)&Ph0[roff + n0] = *(uint2*)h0a;
        *(uint2*)&Ph1[roff + n0] = *(uint2*)h1a;
        *(uint2*)&Ph2[roff + n0] = *(uint2*)h2a;
    }
    red[tid] = s0; __syncthreads();
    for (int s = 128; s > 0; s >>= 1) { if (tid < s) red[tid] += red[tid + s]; __syncthreads(); }
    if (tid == 0) inv0[(size_t)b * NTOT + row] = 1.f / red[0];
    __syncthreads();
    red[tid] = s1; __syncthreads();
    for (int s = 128; s > 0; s >>= 1) { if (tid < s) red[tid] += red[tid + s]; __syncthreads(); }
    if (tid == 0) inv1[(size_t)b * NTOT + row] = 1.f / red[0];
    __syncthreads();
    red[tid] = s2; __syncthreads();
    for (int s = 128; s > 0; s >>= 1) { if (tid < s) red[tid] += red[tid + s]; __syncthreads(); }
    if (tid == 0) inv2[(size_t)b * NTOT + row] = 1.f / red[0];
}

// ---------------- launch ----------------
extern "C" void kernel_launch(void* const* d_in, const int* in_sizes, int n_in,
                              void* d_out, int out_size)
{
    const float* x       = (const float*)d_in[0];
    const float* Wq      = (const float*)d_in[1];
    const float* bq      = (const float*)d_in[2];
    const float* Wk      = (const float*)d_in[3];
    const float* bk      = (const float*)d_in[4];
    const float* Wv      = (const float*)d_in[5];
    const float* bv      = (const float*)d_in[6];
    const float* conv1_w = (const float*)d_in[7];
    const float* bn1_w   = (const float*)d_in[8];
    const float* bn1_b   = (const float*)d_in[9];
    const float* bn1_m   = (const float*)d_in[10];
    const float* bn1_v   = (const float*)d_in[11];
    const float* conv2_w = (const float*)d_in[12];
    const float* bn2_w   = (const float*)d_in[13];
    const float* bn2_b   = (const float*)d_in[14];
    const float* bn2_m   = (const float*)d_in[15];
    const float* bn2_v   = (const float*)d_in[16];
    const float* sig1_w  = (const float*)d_in[17];
    const float* sig1_b  = (const float*)d_in[18];
    const float* sig2_w  = (const float*)d_in[19];
    const float* sig2_b  = (const float*)d_in[20];
    const float* gamma   = (const float*)d_in[21];
    const float* gamma1  = (const float*)d_in[22];
    const float* gamma2  = (const float*)d_in[23];

    float *p, *i0, *i1, *i2, *t1, *t2;
    __half *qh, *kh, *ph0, *ph1, *ph2, *v, *s, *xt, *yt, *t1t, *t2t;
    __half *w1r, *w2r, *wv16, *ws1, *ws2;
    cudaGetSymbolAddress((void**)&qh,  g_qh);
    cudaGetSymbolAddress((void**)&kh,  g_kh);
    cudaGetSymbolAddress((void**)&p,   g_p);
    cudaGetSymbolAddress((void**)&ph0, g_ph0);
    cudaGetSymbolAddress((void**)&ph1, g_ph1);
    cudaGetSymbolAddress((void**)&ph2, g_ph2);
    cudaGetSymbolAddress((void**)&v,   g_v);
    cudaGetSymbolAddress((void**)&s,   g_s);
    cudaGetSymbolAddress((void**)&i0,  g_inv0);
    cudaGetSymbolAddress((void**)&i1,  g_inv1);
    cudaGetSymbolAddress((void**)&i2,  g_inv2);
    cudaGetSymbolAddress((void**)&xt,  g_xt);
    cudaGetSymbolAddress((void**)&yt,  g_yt);
    cudaGetSymbolAddress((void**)&t1,  g_t1);
    cudaGetSymbolAddress((void**)&t1t, g_t1t);
    cudaGetSymbolAddress((void**)&t2,  g_t2);
    cudaGetSymbolAddress((void**)&t2t, g_t2t);
    cudaGetSymbolAddress((void**)&w1r, g_w1r);
    cudaGetSymbolAddress((void**)&w2r, g_w2r);
    cudaGetSymbolAddress((void**)&wv16, g_wv16);
    cudaGetSymbolAddress((void**)&ws1, g_ws1);
    cudaGetSymbolAddress((void**)&ws2, g_ws2);

    cudaFuncSetAttribute((const void*)tc_attn<-1, true>,  cudaFuncAttributeMaxDynamicSharedMemorySize, SMEM_TC_SZ);
    cudaFuncSetAttribute((const void*)tc_attn<6, true>,   cudaFuncAttributeMaxDynamicSharedMemorySize, SMEM_TC_SZ);
    cudaFuncSetAttribute((const void*)tc_attn<12, false>, cudaFuncAttributeMaxDynamicSharedMemorySize, SMEM_TC_SZ);
    cudaFuncSetAttribute((const void*)tc_conv,            cudaFuncAttributeMaxDynamicSharedMemorySize, SMEM_TC_SZ);
    cudaFuncSetAttribute((const void*)tc_nn,              cudaFuncAttributeMaxDynamicSharedMemorySize, SMEM_TC_SZ);
    cudaFuncSetAttribute((const void*)tc_energy,          cudaFuncAttributeMaxDynamicSharedMemorySize, SMEM_TC_SZ);

    const dim3 blk(256);
    const dim3 gQK(NTOT / BN, 1, BDIM);
    const dim3 gTC(NTOT / TCN, CDIM / TCM, BDIM);    // (18, 4, 4)
    const dim3 gEn(NTOT / TCN, NTOT / TCM, BDIM);    // (18, 18, 4)
    const dim3 gTr(NTOT / 32, CDIM / 32, BDIM);
    const int wElems = CDIM * KCONV;
    const int sqElems = CDIM * CDIM;

    // prep
    transpose_c2n<<<gTr, blk>>>(x, xt);
    reorder_w<<<(wElems + 255) / 256, blk>>>(conv1_w, w1r);
    reorder_w<<<(wElems + 255) / 256, blk>>>(conv2_w, w2r);
    cvt_w16<<<(sqElems + 255) / 256, blk>>>(Wv, wv16, sqElems);
    cvt_w16<<<(sqElems + 255) / 256, blk>>>(sig1_w, ws1, sqElems);
    cvt_w16<<<(sqElems + 255) / 256, blk>>>(sig2_w, ws2, sqElems);

    // q/k fused (fp32 math -> hi/lo fp16), v (tensor)
    gemm_qk<<<gQK, blk>>>(Wq, bq, Wk, bk, x, qh, kh);
    tc_nn<<<gTC, blk, SMEM_TC_SZ>>>(wv16, xt, bv, (const float*)0, v);

    // energy (tensor, hi/lo exact) + 3-shift softmax
    tc_energy<<<gEn, blk, SMEM_TC_SZ>>>(qh, kh, p);
    softmax_rows3<<<dim3(NTOT, BDIM), blk>>>(p, ph0, ph1, ph2, i0, i1, i2);

    // stage 0
    tc_attn<-1, true><<<gTC, blk, SMEM_TC_SZ>>>(v, ph0, i0, gamma, x, (float*)0, yt);
    tc_conv<<<gTC, blk, SMEM_TC_SZ>>>(w1r, yt, bn1_w, bn1_b, bn1_m, bn1_v, t1, t1t);

    // stage 1
    tc_nn<<<gTC, blk, SMEM_TC_SZ>>>(ws1, t1t, sig1_b, t1, s);
    tc_attn<6, true><<<gTC, blk, SMEM_TC_SZ>>>(s, ph1, i1, gamma1, t1, (float*)0, yt);
    tc_conv<<<gTC, blk, SMEM_TC_SZ>>>(w2r, yt, bn2_w, bn2_b, bn2_m, bn2_v, t2, t2t);

    // stage 2
    tc_nn<<<gTC, blk, SMEM_TC_SZ>>>(ws2, t2t, sig2_b, t2, s);
    tc_attn<12, false><<<gTC, blk, SMEM_TC_SZ>>>(s, ph2, i2, gamma2, t2, (float*)d_out, (__half*)0);
}

// round 9
// speedup vs baseline: 6.3719x; 1.0637x over previous
#include <cuda_runtime.h>
#include <cuda_fp16.h>
#include <stdint.h>

#define NTOT 2304
#define BDIM 4
#define CDIM 512
#define DQD  64
#define HW   48
#define KCONV (CDIM * 9)
#define KQK  1536

// ---------------- fp16 mma tile config ----------------
#define TCM 128
#define TCN 128
#define TCK 64                          // k halves per chunk (=128B row)
#define TILE16 (TCM * TCK * 2)          // 16384 bytes
#define NSTAGE 3
#define SMEM_TC_SZ (2048 + 2 * NSTAGE * TILE16)  // 100352

#define SWZ(off) ((off) ^ (((off) >> 3) & 0x70))

// ---------------- scratch ----------------
__device__ __half g_qh [BDIM*NTOT*128];              // q hi/lo [n][128]
__device__ __half g_kh [BDIM*NTOT*128];
__device__ float  g_p [(size_t)BDIM*NTOT*NTOT];      // energy (fp32)
__device__ __half g_ph0[(size_t)BDIM*NTOT*NTOT];
__device__ __half g_ph1[(size_t)BDIM*NTOT*NTOT];
__device__ __half g_ph2[(size_t)BDIM*NTOT*NTOT];
__device__ __half g_v  [BDIM*CDIM*NTOT];
__device__ __half g_s  [BDIM*CDIM*NTOT];
__device__ float  g_inv0[BDIM*NTOT];
__device__ float  g_inv1[BDIM*NTOT];
__device__ float  g_inv2[BDIM*NTOT];
__device__ __half g_xt [BDIM*NTOT*CDIM];
__device__ __half g_xqk[(size_t)BDIM*NTOT*KQK];      // [xhi | xlo | xhi]
__device__ __half g_yt [BDIM*NTOT*CDIM];
__device__ float  g_t1 [BDIM*CDIM*NTOT];
__device__ __half g_t1t[BDIM*NTOT*CDIM];
__device__ float  g_t2 [BDIM*CDIM*NTOT];
__device__ __half g_t2t[BDIM*NTOT*CDIM];
__device__ __half g_w1r[CDIM*KCONV];
__device__ __half g_w2r[CDIM*KCONV];
__device__ __half g_wv16[CDIM*CDIM];
__device__ __half g_ws1[CDIM*CDIM];
__device__ __half g_ws2[CDIM*CDIM];
__device__ __half g_wqk[128*KQK];                    // [Whi | Whi | Wlo]

// ---------------- helpers ----------------
__device__ __forceinline__ uint32_t smem_u32(const void* p) {
    return (uint32_t)__cvta_generic_to_shared(p);
}
__device__ __forceinline__ void ldsm4(uint32_t* r, uint32_t addr) {
    asm volatile("ldmatrix.sync.aligned.m8n8.x4.shared.b16 {%0,%1,%2,%3}, [%4];"
        : "=r"(r[0]), "=r"(r[1]), "=r"(r[2]), "=r"(r[3]) : "r"(addr));
}
__device__ __forceinline__ void mma16816(float* c, const uint32_t* a, const uint32_t* b) {
    asm volatile("mma.sync.aligned.m16n8k16.row.col.f32.f16.f16.f32 "
        "{%0,%1,%2,%3}, {%4,%5,%6,%7}, {%8,%9}, {%0,%1,%2,%3};"
        : "+f"(c[0]), "+f"(c[1]), "+f"(c[2]), "+f"(c[3])
        : "r"(a[0]), "r"(a[1]), "r"(a[2]), "r"(a[3]), "r"(b[0]), "r"(b[1]));
}
#define CP_A16(dst, src) \
    asm volatile("cp.async.cg.shared.global [%0], [%1], 16;" :: "r"(dst), "l"(src))
#define CP_A16Z(dst, src, sz) \
    asm volatile("cp.async.cg.shared.global [%0], [%1], 16, %2;" :: "r"(dst), "l"(src), "r"(sz))
#define CP_COMMIT() asm volatile("cp.async.commit_group;")
#define CP_WAIT1()  asm volatile("cp.async.wait_group 1;")
#define CP_WAIT0()  asm volatile("cp.async.wait_group 0;")

__device__ __forceinline__ void mma_chunk16(
    uint32_t aT, uint32_t bT,
    const uint32_t aOff[2], const uint32_t bOff[4],
    uint32_t aColSel, uint32_t bColSel, uint32_t xorv,
    float (&acc)[2][8][4])
{
#pragma unroll
    for (int g = 0; g < 4; g++) {
        uint32_t ka = ((uint32_t)(g * 32) + aColSel) ^ xorv;
        uint32_t kb = ((uint32_t)(g * 32) + bColSel) ^ xorv;
        uint32_t af[2][4];
        ldsm4(af[0], aT + aOff[0] + ka);
        ldsm4(af[1], aT + aOff[1] + ka);
#pragma unroll
        for (int p = 0; p < 4; p++) {
            uint32_t bf[4];
            ldsm4(bf, bT + bOff[p] + kb);
            mma16816(acc[0][2 * p],     af[0], bf);
            mma16816(acc[0][2 * p + 1], af[0], bf + 2);
            mma16816(acc[1][2 * p],     af[1], bf);
            mma16816(acc[1][2 * p + 1], af[1], bf + 2);
        }
    }
}

#define MMA_PRECOMP16() \
    const int lane = tid & 31, wid = tid >> 5; \
    const int wm = wid >> 1, wn = wid & 1; \
    const int j8 = lane >> 3, rr = lane & 7; \
    const uint32_t xorv = rr * 16; \
    const uint32_t aColSel = (j8 >> 1) * 16; \
    const uint32_t bColSel = (j8 & 1) * 16; \
    uint32_t aOff[2], bOff[4]; \
    aOff[0] = (wm * 32 +      (j8 & 1) * 8 + rr) * 128; \
    aOff[1] = aOff[0] + 16 * 128; \
    bOff[0] = (wn * 64 +      (j8 >> 1) * 8 + rr) * 128; \
    bOff[1] = bOff[0] + 16 * 128; \
    bOff[2] = bOff[0] + 32 * 128; \
    bOff[3] = bOff[0] + 48 * 128; \
    const int col8 = tid & 7; \
    const int row0 = tid >> 3; \
    float acc[2][8][4]; \
_Pragma("unroll") \
    for (int i_ = 0; i_ < 2; i_++) \
_Pragma("unroll") \
        for (int j_ = 0; j_ < 8; j_++) \
_Pragma("unroll") \
            for (int e_ = 0; e_ < 4; e_++) acc[i_][j_][e_] = 0.f;

#define TILES_SETUP() \
    uint32_t tilesAddr = (sb + 1024 + 1023) & ~1023u; \
    uint32_t stA[NSTAGE], stB[NSTAGE]; \
_Pragma("unroll") \
    for (int s_ = 0; s_ < NSTAGE; s_++) { \
        stA[s_] = tilesAddr + s_ * 2 * TILE16; \
        stB[s_] = stA[s_] + TILE16; \
    }

// staged coalesced transposed store: acc-held tile -> OutT[n][c] fp16
// sm16: padded [128][136] halves at tiles region
#define STAGE_ROWSTRIDE 136

// ========== tc_attn ==========
template<int RADIUS, bool OUT_T>
__global__ __launch_bounds__(256) void tc_attn(
    const __half* __restrict__ A, const __half* __restrict__ P,
    const float* __restrict__ invsum, const float* __restrict__ gammaPtr,
    const float* __restrict__ Res, float* __restrict__ OutF, __half* __restrict__ OutT)
{
    extern __shared__ char smem[];
    uint32_t sb = smem_u32(smem);
    float* smf = (float*)smem;
    const int tid = threadIdx.x;
    const int bz = blockIdx.z;
    const __half* Ap = A + (size_t)bz * CDIM * NTOT;
    const __half* Pp = P + (size_t)bz * NTOT * NTOT;
    const float* Rp = Res + (size_t)bz * CDIM * NTOT;
    const int rowBase = blockIdx.y * TCM;
    const int colBase = blockIdx.x * TCN;

    TILES_SETUP();
    MMA_PRECOMP16();

    if (tid < TCN) smf[tid] = invsum[(size_t)bz * NTOT + colBase + tid];

    int kStart = 0, kEnd = NTOT;
    if (RADIUS >= 0) {
        int rmLo = colBase / HW, rmHi = (colBase + TCN - 1) / HW;
        int rlo = rmLo - RADIUS; if (rlo < 0) rlo = 0;
        int rhi = rmHi + RADIUS; if (rhi > HW - 1) rhi = HW - 1;
        kStart = (rlo * HW) & ~(TCK - 1);
        kEnd = ((rhi + 1) * HW + TCK - 1) & ~(TCK - 1);
        if (kEnd > NTOT) kEnd = NTOT;
    }
    const int NC = (kEnd - kStart) / TCK;

    auto issueLoads = [&](int ci, int st) {
        const int k0 = kStart + ci * TCK;
#pragma unroll
        for (int s = 0; s < 4; s++) {
            int row = row0 + s * 32;
            uint32_t sw = SWZ(row * 128 + col8 * 16);
            CP_A16(stA[st] + sw, &Ap[(size_t)(rowBase + row) * NTOT + k0 + col8 * 8]);
            CP_A16(stB[st] + sw, &Pp[(size_t)(colBase + row) * NTOT + k0 + col8 * 8]);
        }
    };

#pragma unroll
    for (int s = 0; s < NSTAGE - 1; s++) {
        if (s < NC) issueLoads(s, s);
        CP_COMMIT();
    }
    for (int ci = 0; ci < NC; ci++) {
        CP_WAIT1();
        __syncthreads();
        int nci = ci + NSTAGE - 1;
        if (nci < NC) issueLoads(nci, nci % NSTAGE);
        CP_COMMIT();
        int st = ci % NSTAGE;
        mma_chunk16(stA[st], stB[st], aOff, bOff, aColSel, bColSel, xorv, acc);
    }

    const float g = *gammaPtr;
    if (OUT_T) {
        CP_WAIT0();
        __syncthreads();
        __half* sm16 = (__half*)(smem + (tilesAddr - sb));
        __half* OpT = OutT + (size_t)bz * NTOT * CDIM;
#pragma unroll
        for (int mt = 0; mt < 2; mt++) {
            int mloc = wm * 32 + mt * 16 + (lane >> 2);
#pragma unroll
            for (int half = 0; half < 2; half++) {
                int cc = mloc + half * 8;
                int c = rowBase + cc;
                size_t ro = (size_t)c * NTOT;
#pragma unroll
                for (int nt = 0; nt < 8; nt++) {
                    int nl = wn * 64 + nt * 8 + (lane & 3) * 2;
                    int n = colBase + nl;
                    float2 res = *(const float2*)&Rp[ro + n];
                    float ox = acc[mt][nt][half * 2 + 0] * (g * smf[nl])     + res.x;
                    float oy = acc[mt][nt][half * 2 + 1] * (g * smf[nl + 1]) + res.y;
                    sm16[nl * STAGE_ROWSTRIDE + cc]       = __float2half_rn(ox);
                    sm16[(nl + 1) * STAGE_ROWSTRIDE + cc] = __float2half_rn(oy);
                }
            }
        }
        __syncthreads();
#pragma unroll
        for (int r = 0; r < 8; r++) {
            int row = r * 16 + (tid >> 4);
            int c8 = (tid & 15) * 8;
            uint4 u = *(const uint4*)&sm16[row * STAGE_ROWSTRIDE + c8];
            *(uint4*)&OpT[(size_t)(colBase + row) * CDIM + rowBase + c8] = u;
        }
    } else {
        float* OpF = OutF + (size_t)bz * CDIM * NTOT;
#pragma unroll
        for (int mt = 0; mt < 2; mt++) {
            int mloc = wm * 32 + mt * 16 + (lane >> 2);
#pragma unroll
            for (int half = 0; half < 2; half++) {
                int c = rowBase + mloc + half * 8;
                size_t ro = (size_t)c * NTOT;
#pragma unroll
                for (int nt = 0; nt < 8; nt++) {
                    int nl = wn * 64 + nt * 8 + (lane & 3) * 2;
                    int n = colBase + nl;
                    float2 res = *(const float2*)&Rp[ro + n];
                    float2 o;
                    o.x = acc[mt][nt][half * 2 + 0] * (g * smf[nl])     + res.x;
                    o.y = acc[mt][nt][half * 2 + 1] * (g * smf[nl + 1]) + res.y;
                    *(float2*)&OpF[ro + n] = o;
                }
            }
        }
    }
}

// ========== tc_conv ==========
__global__ __launch_bounds__(256) void tc_conv(
    const __half* __restrict__ Wr, const __half* __restrict__ Xt,
    const float* __restrict__ bnw, const float* __restrict__ bnb,
    const float* __restrict__ bnm, const float* __restrict__ bnv,
    float* __restrict__ Out, __half* __restrict__ OutT)
{
    extern __shared__ char smem[];
    uint32_t sb = smem_u32(smem);
    const int tid = threadIdx.x;
    const __half* Xp = Xt + (size_t)blockIdx.z * NTOT * CDIM;
    float* Op = Out + (size_t)blockIdx.z * CDIM * NTOT;
    __half* OpT = OutT + (size_t)blockIdx.z * NTOT * CDIM;
    const int rowBase = blockIdx.y * TCM;
    const int colBase = blockIdx.x * TCN;

    TILES_SETUP();
    MMA_PRECOMP16();

    int pys[4], pxs[4];
#pragma unroll
    for (int s = 0; s < 4; s++) {
        int pix = colBase + row0 + s * 32;
        pys[s] = pix / HW; pxs[s] = pix - pys[s] * HW;
    }

    const int NC = KCONV / TCK;   // 72

    auto issueLoads = [&](int ci, int st) {
        const int k0 = ci * TCK;
        const int tap = ci >> 3;
        const int icb = (ci & 7) * TCK;
        const int ky = tap / 3, kx = tap - ky * 3;
#pragma unroll
        for (int s = 0; s < 4; s++) {
            int row = row0 + s * 32;
            uint32_t sw = SWZ(row * 128 + col8 * 16);
            CP_A16(stA[st] + sw, &Wr[(size_t)(rowBase + row) * KCONV + k0 + col8 * 8]);
            int iy = pys[s] + ky - 1, ix = pxs[s] + kx - 1;
            bool ok = (unsigned)iy < HW && (unsigned)ix < HW;
            const __half* src = ok ? &Xp[(size_t)(iy * HW + ix) * CDIM + icb + col8 * 8] : Xp;
            CP_A16Z(stB[st] + sw, src, ok ? 16u : 0u);
        }
    };

#pragma unroll
    for (int s = 0; s < NSTAGE - 1; s++) {
        if (s < NC) issueLoads(s, s);
        CP_COMMIT();
    }
    for (int ci = 0; ci < NC; ci++) {
        CP_WAIT1();
        __syncthreads();
        int nci = ci + NSTAGE - 1;
        if (nci < NC) issueLoads(nci, nci % NSTAGE);
        CP_COMMIT();
        int st = ci % NSTAGE;
        mma_chunk16(stA[st], stB[st], aOff, bOff, aColSel, bColSel, xorv, acc);
    }

    CP_WAIT0();
    __syncthreads();
    __half* sm16 = (__half*)(smem + (tilesAddr - sb));
#pragma unroll
    for (int mt = 0; mt < 2; mt++) {
        int mloc = wm * 32 + mt * 16 + (lane >> 2);
#pragma unroll
        for (int half = 0; half < 2; half++) {
            int cc = mloc + half * 8;
            int oc = rowBase + cc;
            float scale = bnw[oc] * rsqrtf(bnv[oc] + 1e-5f);
            float shift = bnb[oc] - bnm[oc] * scale;
            size_t ro = (size_t)oc * NTOT;
#pragma unroll
            for (int nt = 0; nt < 8; nt++) {
                int nl = wn * 64 + nt * 8 + (lane & 3) * 2;
                int n = colBase + nl;
                float ox = fmaxf(acc[mt][nt][half * 2 + 0] * scale + shift, 0.f);
                float oy = fmaxf(acc[mt][nt][half * 2 + 1] * scale + shift, 0.f);
                float2 o; o.x = ox; o.y = oy;
                *(float2*)&Op[ro + n] = o;
                sm16[nl * STAGE_ROWSTRIDE + cc]       = __float2half_rn(ox);
                sm16[(nl + 1) * STAGE_ROWSTRIDE + cc] = __float2half_rn(oy);
            }
        }
    }
    __syncthreads();
#pragma unroll
    for (int r = 0; r < 8; r++) {
        int row = r * 16 + (tid >> 4);
        int c8 = (tid & 15) * 8;
        uint4 u = *(const uint4*)&sm16[row * STAGE_ROWSTRIDE + c8];
        *(uint4*)&OpT[(size_t)(colBase + row) * CDIM + rowBase + c8] = u;
    }
}

// ====== tc_nn ======
__global__ __launch_bounds__(256) void tc_nn(
    const __half* __restrict__ W16, const __half* __restrict__ Bt,
    const float* __restrict__ bias, const float* __restrict__ gateSrc,
    __half* __restrict__ Out)
{
    extern __shared__ char smem[];
    uint32_t sb = smem_u32(smem);
    const int tid = threadIdx.x;
    const __half* Bp = Bt + (size_t)blockIdx.z * NTOT * CDIM;
    const float* Gp = gateSrc ? gateSrc + (size_t)blockIdx.z * CDIM * NTOT : (const float*)0;
    __half* Op = Out + (size_t)blockIdx.z * CDIM * NTOT;
    const int rowBase = blockIdx.y * TCM;
    const int colBase = blockIdx.x * TCN;

    TILES_SETUP();
    MMA_PRECOMP16();

    const int NC = CDIM / TCK;   // 8

    auto issueLoads = [&](int ci, int st) {
        const int k0 = ci * TCK;
#pragma unroll
        for (int s = 0; s < 4; s++) {
            int row = row0 + s * 32;
            uint32_t sw = SWZ(row * 128 + col8 * 16);
            CP_A16(stA[st] + sw, &W16[(size_t)(rowBase + row) * CDIM + k0 + col8 * 8]);
            CP_A16(stB[st] + sw, &Bp[(size_t)(colBase + row) * CDIM + k0 + col8 * 8]);
        }
    };

#pragma unroll
    for (int s = 0; s < NSTAGE - 1; s++) {
        if (s < NC) issueLoads(s, s);
        CP_COMMIT();
    }
    for (int ci = 0; ci < NC; ci++) {
        CP_WAIT1();
        __syncthreads();
        int nci = ci + NSTAGE - 1;
        if (nci < NC) issueLoads(nci, nci % NSTAGE);
        CP_COMMIT();
        int st = ci % NSTAGE;
        mma_chunk16(stA[st], stB[st], aOff, bOff, aColSel, bColSel, xorv, acc);
    }

#pragma unroll
    for (int mt = 0; mt < 2; mt++) {
        int mloc = wm * 32 + mt * 16 + (lane >> 2);
#pragma unroll
        for (int half = 0; half < 2; half++) {
            int d = rowBase + mloc + half * 8;
            float bv = bias[d];
            size_t ro = (size_t)d * NTOT;
#pragma unroll
            for (int nt = 0; nt < 8; nt++) {
                int n = colBase + wn * 64 + nt * 8 + (lane & 3) * 2;
                float ox = acc[mt][nt][half * 2 + 0] + bv;
                float oy = acc[mt][nt][half * 2 + 1] + bv;
                if (Gp) {
                    float2 gv = *(const float2*)&Gp[ro + n];
                    ox = gv.x * (1.f / (1.f + __expf(-ox)));
                    oy = gv.y * (1.f / (1.f + __expf(-oy)));
                }
                *(__half2*)&Op[ro + n] = __floats2half2_rn(ox, oy);
            }
        }
    }
}

// ====== tc_qk: [q;k][n] = Wqk(hi/lo concat) x xqk(hi/lo concat), hi/lo fp16 out ======
__global__ __launch_bounds__(256) void tc_qk(
    const __half* __restrict__ Wqk, const __half* __restrict__ Xqk,
    const float* __restrict__ bq, const float* __restrict__ bk,
    __half* __restrict__ Qh, __half* __restrict__ Kh)
{
    extern __shared__ char smem[];
    uint32_t sb = smem_u32(smem);
    const int tid = threadIdx.x;
    const int bz = blockIdx.z;
    const __half* Bp = Xqk + (size_t)bz * NTOT * KQK;
    __half* qh = Qh + (size_t)bz * NTOT * 128;
    __half* kh = Kh + (size_t)bz * NTOT * 128;
    const int colBase = blockIdx.x * TCN;

    TILES_SETUP();
    MMA_PRECOMP16();

    const int NC = KQK / TCK;   // 24

    auto issueLoads = [&](int ci, int st) {
        const int k0 = ci * TCK;
#pragma unroll
        for (int s = 0; s < 4; s++) {
            int row = row0 + s * 32;
            uint32_t sw = SWZ(row * 128 + col8 * 16);
            CP_A16(stA[st] + sw, &Wqk[(size_t)row * KQK + k0 + col8 * 8]);
            CP_A16(stB[st] + sw, &Bp[(size_t)(colBase + row) * KQK + k0 + col8 * 8]);
        }
    };

#pragma unroll
    for (int s = 0; s < NSTAGE - 1; s++) {
        if (s < NC) issueLoads(s, s);
        CP_COMMIT();
    }
    for (int ci = 0; ci < NC; ci++) {
        CP_WAIT1();
        __syncthreads();
        int nci = ci + NSTAGE - 1;
        if (nci < NC) issueLoads(nci, nci % NSTAGE);
        CP_COMMIT();
        int st = ci % NSTAGE;
        mma_chunk16(stA[st], stB[st], aOff, bOff, aColSel, bColSel, xorv, acc);
    }

#pragma unroll
    for (int mt = 0; mt < 2; mt++) {
        int mloc = wm * 32 + mt * 16 + (lane >> 2);
#pragma unroll
        for (int half = 0; half < 2; half++) {
            int d = mloc + half * 8;
            bool isQ = d < 64;
            float bv = isQ ? bq[d] : bk[d - 64];
            __half* dst = isQ ? qh : kh;
            int ch = d & 63;
#pragma unroll
            for (int nt = 0; nt < 8; nt++) {
                int n = colBase + wn * 64 + nt * 8 + (lane & 3) * 2;
#pragma unroll
                for (int e = 0; e < 2; e++) {
                    float val = acc[mt][nt][half * 2 + e] + bv;
                    __half hi = __float2half_rn(val);
                    __half lo = __float2half_rn(val - __half2float(hi));
                    dst[(size_t)(n + e) * 128 + ch]      = hi;
                    dst[(size_t)(n + e) * 128 + 64 + ch] = lo;
                }
            }
        }
    }
}

// ====== tc_energy ======
__global__ __launch_bounds__(256) void tc_energy(
    const __half* __restrict__ Qh, const __half* __restrict__ Kh,
    float* __restrict__ E)
{
    extern __shared__ char smem[];
    uint32_t sb = smem_u32(smem);
    const int tid = threadIdx.x;
    const __half* Ap = Qh + (size_t)blockIdx.z * NTOT * 128;
    const __half* Bp = Kh + (size_t)blockIdx.z * NTOT * 128;
    float* Ep = E + (size_t)blockIdx.z * NTOT * NTOT;
    const int rowBase = blockIdx.y * TCM;
    const int colBase = blockIdx.x * TCN;

    TILES_SETUP();
    MMA_PRECOMP16();

    const int NC = 2;

    auto issueLoads = [&](int ci, int st) {
        const int k0 = ci * TCK;
#pragma unroll
        for (int s = 0; s < 4; s++) {
            int row = row0 + s * 32;
            uint32_t sw = SWZ(row * 128 + col8 * 16);
            CP_A16(stA[st] + sw, &Ap[(size_t)(rowBase + row) * 128 + k0 + col8 * 8]);
            CP_A16(stB[st] + sw, &Bp[(size_t)(colBase + row) * 128 + k0 + col8 * 8]);
        }
    };

#pragma unroll
    for (int s = 0; s < NSTAGE - 1; s++) {
        if (s < NC) issueLoads(s, s);
        CP_COMMIT();
    }
    for (int ci = 0; ci < NC; ci++) {
        CP_WAIT1();
        __syncthreads();
        int nci = ci + NSTAGE - 1;
        if (nci < NC) issueLoads(nci, nci % NSTAGE);
        CP_COMMIT();
        int st = ci % NSTAGE;
        mma_chunk16(stA[st], stB[st], aOff, bOff, aColSel, bColSel, xorv, acc);
    }

#pragma unroll
    for (int mt = 0; mt < 2; mt++) {
        int mloc = wm * 32 + mt * 16 + (lane >> 2);
#pragma unroll
        for (int half = 0; half < 2; half++) {
            int m = rowBase + mloc + half * 8;
            size_t ro = (size_t)m * NTOT;
#pragma unroll
            for (int nt = 0; nt < 8; nt++) {
                int n = colBase + wn * 64 + nt * 8 + (lane & 3) * 2;
                float2 o;
                o.x = acc[mt][nt][half * 2 + 0];
                o.y = acc[mt][nt][half * 2 + 1];
                *(float2*)&Ep[ro + n] = o;
            }
        }
    }
}

// ---------------- transpose: fp32 [C][N] -> xt fp16 [N][C] + xqk [N][1536] ----------------
__global__ __launch_bounds__(256) void transpose_c2n(
    const float* __restrict__ X, __half* __restrict__ Xt, __half* __restrict__ Xqk)
{
    __shared__ float tile[32][33];
    const int b = blockIdx.z;
    const int n0 = blockIdx.x * 32, c0 = blockIdx.y * 32;
    const int tx = threadIdx.x & 31, ty = threadIdx.x >> 5;
    const float* Xp = X + (size_t)b * CDIM * NTOT;
    __half* Tp = Xt + (size_t)b * NTOT * CDIM;
    __half* Qp = Xqk + (size_t)b * NTOT * KQK;
#pragma unroll
    for (int k = 0; k < 4; k++)
        tile[ty + 8 * k][tx] = Xp[(size_t)(c0 + ty + 8 * k) * NTOT + n0 + tx];
    __syncthreads();
#pragma unroll
    for (int k = 0; k < 4; k++) {
        float val = tile[tx][ty + 8 * k];
        __half hi = __float2half_rn(val);
        __half lo = __float2half_rn(val - __half2float(hi));
        int n = n0 + ty + 8 * k, c = c0 + tx;
        Tp[(size_t)n * CDIM + c] = hi;
        size_t qb = (size_t)n * KQK + c;
        Qp[qb] = hi;
        Qp[qb + 512] = lo;
        Qp[qb + 1024] = hi;
    }
}

// ---------------- prep: all weight conversions in one launch ----------------
__global__ __launch_bounds__(256) void prep_all(
    const float* __restrict__ conv1_w, const float* __restrict__ conv2_w,
    const float* __restrict__ Wv, const float* __restrict__ sig1_w,
    const float* __restrict__ sig2_w,
    const float* __restrict__ Wq, const float* __restrict__ Wk,
    __half* __restrict__ w1r, __half* __restrict__ w2r,
    __half* __restrict__ wv16, __half* __restrict__ ws1, __half* __restrict__ ws2,
    __half* __restrict__ wqk)
{
    const int seg = blockIdx.y;
    const int idx = blockIdx.x * 256 + threadIdx.x;
    if (seg < 2) {
        if (idx < CDIM * KCONV) {
            const float* W = seg == 0 ? conv1_w : conv2_w;
            __half* Wr = seg == 0 ? w1r : w2r;
            int oc = idx / KCONV, kk = idx - oc * KCONV;
            int tap = kk >> 9, ic = kk & 511;
            Wr[idx] = __float2half_rn(W[(size_t)oc * KCONV + ic * 9 + tap]);
        }
    } else if (seg < 5) {
        if (idx < CDIM * CDIM) {
            const float* W = seg == 2 ? Wv : (seg == 3 ? sig1_w : sig2_w);
            __half* O = seg == 2 ? wv16 : (seg == 3 ? ws1 : ws2);
            O[idx] = __float2half_rn(W[idx]);
        }
    } else {
        if (idx < 128 * 512) {
            int d = idx >> 9, c = idx & 511;
            float w = d < 64 ? Wq[(size_t)d * CDIM + c] : Wk[(size_t)(d - 64) * CDIM + c];
            __half hi = __float2half_rn(w);
            __half lo = __float2half_rn(w - __half2float(hi));
            size_t base = (size_t)d * KQK + c;
            wqk[base] = hi;
            wqk[base + 512] = hi;
            wqk[base + 1024] = lo;
        }
    }
}

// ---- softmax: 3 shifts, band-limited ph1/ph2 writes ----
__global__ __launch_bounds__(256) void softmax_rows3(
    const float* __restrict__ P,
    __half* __restrict__ Ph0, __half* __restrict__ Ph1, __half* __restrict__ Ph2,
    float* __restrict__ inv0, float* __restrict__ inv1, float* __restrict__ inv2)
{
    __shared__ float rowv[NTOT];
    __shared__ float red[256];
    const int row = blockIdx.x, b = blockIdx.y, tid = threadIdx.x;
    const size_t roff = ((size_t)b * NTOT + row) * NTOT;
    const float* p = P + roff;

    for (int i = tid; i < NTOT / 4; i += 256)
        ((float4*)rowv)[i] = ((const float4*)p)[i];
    __syncthreads();

    const int rm = row / HW, cm = row - rm * HW;
    // conservative 64-aligned write windows covering everything any consumer tile reads
    int w1lo = (rm - 6 - 4) * HW;  w1lo = w1lo < 0 ? 0 : (w1lo & ~63);
    int w1hi = ((rm + 6 + 5) * HW + 63) & ~63; if (w1hi > NTOT) w1hi = NTOT;
    int w2lo = (rm - 12 - 4) * HW; w2lo = w2lo < 0 ? 0 : (w2lo & ~63);
    int w2hi = ((rm + 12 + 5) * HW + 63) & ~63; if (w2hi > NTOT) w2hi = NTOT;

    float m0 = -1e30f, m6 = -1e30f, m12 = -1e30f;
    for (int i = tid; i < NTOT / 4; i += 256) {
        float4 v4 = ((const float4*)rowv)[i];
        const float* v = (const float*)&v4;
        int n0 = i * 4;
#pragma unroll
        for (int e = 0; e < 4; e++) {
            int n = n0 + e;
            float v1 = v[e];
            m0 = fmaxf(m0, v1);
            int rn = n / HW, cn = n - rn * HW;
            int dr = rm - rn; dr = dr < 0 ? -dr : dr;
            int dc = cm - cn; dc = dc < 0 ? -dc : dc;
            int d = dr > dc ? dr : dc;
            if (d <= 12) { m12 = fmaxf(m12, v1); if (d <= 6) m6 = fmaxf(m6, v1); }
        }
    }
    red[tid] = m0; __syncthreads();
    for (int s = 128; s > 0; s >>= 1) { if (tid < s) red[tid] = fmaxf(red[tid], red[tid + s]); __syncthreads(); }
    m0 = red[0]; __syncthreads();
    red[tid] = m6; __syncthreads();
    for (int s = 128; s > 0; s >>= 1) { if (tid < s) red[tid] = fmaxf(red[tid], red[tid + s]); __syncthreads(); }
    m6 = red[0]; __syncthreads();
    red[tid] = m12; __syncthreads();
    for (int s = 128; s > 0; s >>= 1) { if (tid < s) red[tid] = fmaxf(red[tid], red[tid + s]); __syncthreads(); }
    m12 = red[0]; __syncthreads();

    float s0 = 0.f, s1 = 0.f, s2 = 0.f;
    for (int i = tid; i < NTOT / 4; i += 256) {
        float4 v4 = ((const float4*)rowv)[i];
        const float* v = (const float*)&v4;
        int n0 = i * 4;
        __half h0a[4], h1a[4], h2a[4];
#pragma unroll
        for (int e = 0; e < 4; e++) {
            int n = n0 + e;
            float v1 = v[e];
            __half h0 = __float2half_rn(__expf(v1 - m0));
            h0a[e] = h0;
            s0 += __half2float(h0);
            int rn = n / HW, cn = n - rn * HW;
            int dr = rm - rn; dr = dr < 0 ? -dr : dr;
            int dc = cm - cn; dc = dc < 0 ? -dc : dc;
            int d = dr > dc ? dr : dc;
            __half h1 = __ushort_as_half(0), h2 = __ushort_as_half(0);
            if (d <= 12) {
                h2 = __float2half_rn(__expf(v1 - m12));
                s2 += __half2float(h2);
                if (d <= 6) { h1 = __float2half_rn(__expf(v1 - m6)); s1 += __half2float(h1); }
            }
            h1a[e] = h1; h2a[e] = h2;
        }
        *(uint2*)&Ph0[roff + n0] = *(uint2*)h0a;
        if (n0 >= w1lo && n0 < w1hi) *(uint2*)&Ph1[roff + n0] = *(uint2*)h1a;
        if (n0 >= w2lo && n0 < w2hi) *(uint2*)&Ph2[roff + n0] = *(uint2*)h2a;
    }
    red[tid] = s0; __syncthreads();
    for (int s = 128; s > 0; s >>= 1) { if (tid < s) red[tid] += red[tid + s]; __syncthreads(); }
    if (tid == 0) inv0[(size_t)b * NTOT + row] = 1.f / red[0];
    __syncthreads();
    red[tid] = s1; __syncthreads();
    for (int s = 128; s > 0; s >>= 1) { if (tid < s) red[tid] += red[tid + s]; __syncthreads(); }
    if (tid == 0) inv1[(size_t)b * NTOT + row] = 1.f / red[0];
    __syncthreads();
    red[tid] = s2; __syncthreads();
    for (int s = 128; s > 0; s >>= 1) { if (tid < s) red[tid] += red[tid + s]; __syncthreads(); }
    if (tid == 0) inv2[(size_t)b * NTOT + row] = 1.f / red[0];
}

// ---------------- launch ----------------
extern "C" void kernel_launch(void* const* d_in, const int* in_sizes, int n_in,
                              void* d_out, int out_size)
{
    const float* x       = (const float*)d_in[0];
    const float* Wq      = (const float*)d_in[1];
    const float* bq      = (const float*)d_in[2];
    const float* Wk      = (const float*)d_in[3];
    const float* bk      = (const float*)d_in[4];
    const float* Wv      = (const float*)d_in[5];
    const float* bv      = (const float*)d_in[6];
    const float* conv1_w = (const float*)d_in[7];
    const float* bn1_w   = (const float*)d_in[8];
    const float* bn1_b   = (const float*)d_in[9];
    const float* bn1_m   = (const float*)d_in[10];
    const float* bn1_v   = (const float*)d_in[11];
    const float* conv2_w = (const float*)d_in[12];
    const float* bn2_w   = (const float*)d_in[13];
    const float* bn2_b   = (const float*)d_in[14];
    const float* bn2_m   = (const float*)d_in[15];
    const float* bn2_v   = (const float*)d_in[16];
    const float* sig1_w  = (const float*)d_in[17];
    const float* sig1_b  = (const float*)d_in[18];
    const float* sig2_w  = (const float*)d_in[19];
    const float* sig2_b  = (const float*)d_in[20];
    const float* gamma   = (const float*)d_in[21];
    const float* gamma1  = (const float*)d_in[22];
    const float* gamma2  = (const float*)d_in[23];

    float *p, *i0, *i1, *i2, *t1, *t2;
    __half *qh, *kh, *ph0, *ph1, *ph2, *v, *s, *xt, *xqk, *yt, *t1t, *t2t;
    __half *w1r, *w2r, *wv16, *ws1, *ws2, *wqk;
    cudaGetSymbolAddress((void**)&qh,  g_qh);
    cudaGetSymbolAddress((void**)&kh,  g_kh);
    cudaGetSymbolAddress((void**)&p,   g_p);
    cudaGetSymbolAddress((void**)&ph0, g_ph0);
    cudaGetSymbolAddress((void**)&ph1, g_ph1);
    cudaGetSymbolAddress((void**)&ph2, g_ph2);
    cudaGetSymbolAddress((void**)&v,   g_v);
    cudaGetSymbolAddress((void**)&s,   g_s);
    cudaGetSymbolAddress((void**)&i0,  g_inv0);
    cudaGetSymbolAddress((void**)&i1,  g_inv1);
    cudaGetSymbolAddress((void**)&i2,  g_inv2);
    cudaGetSymbolAddress((void**)&xt,  g_xt);
    cudaGetSymbolAddress((void**)&xqk, g_xqk);
    cudaGetSymbolAddress((void**)&yt,  g_yt);
    cudaGetSymbolAddress((void**)&t1,  g_t1);
    cudaGetSymbolAddress((void**)&t1t, g_t1t);
    cudaGetSymbolAddress((void**)&t2,  g_t2);
    cudaGetSymbolAddress((void**)&t2t, g_t2t);
    cudaGetSymbolAddress((void**)&w1r, g_w1r);
    cudaGetSymbolAddress((void**)&w2r, g_w2r);
    cudaGetSymbolAddress((void**)&wv16, g_wv16);
    cudaGetSymbolAddress((void**)&ws1, g_ws1);
    cudaGetSymbolAddress((void**)&ws2, g_ws2);
    cudaGetSymbolAddress((void**)&wqk, g_wqk);

    cudaFuncSetAttribute((const void*)tc_attn<-1, true>,  cudaFuncAttributeMaxDynamicSharedMemorySize, SMEM_TC_SZ);
    cudaFuncSetAttribute((const void*)tc_attn<6, true>,   cudaFuncAttributeMaxDynamicSharedMemorySize, SMEM_TC_SZ);
    cudaFuncSetAttribute((const void*)tc_attn<12, false>, cudaFuncAttributeMaxDynamicSharedMemorySize, SMEM_TC_SZ);
    cudaFuncSetAttribute((const void*)tc_conv,            cudaFuncAttributeMaxDynamicSharedMemorySize, SMEM_TC_SZ);
    cudaFuncSetAttribute((const void*)tc_nn,              cudaFuncAttributeMaxDynamicSharedMemorySize, SMEM_TC_SZ);
    cudaFuncSetAttribute((const void*)tc_qk,              cudaFuncAttributeMaxDynamicSharedMemorySize, SMEM_TC_SZ);
    cudaFuncSetAttribute((const void*)tc_energy,          cudaFuncAttributeMaxDynamicSharedMemorySize, SMEM_TC_SZ);

    const dim3 blk(256);
    const dim3 gTC(NTOT / TCN, CDIM / TCM, BDIM);    // (18, 4, 4)
    const dim3 gQK(NTOT / TCN, 1, BDIM);             // (18, 1, 4)
    const dim3 gEn(NTOT / TCN, NTOT / TCM, BDIM);    // (18, 18, 4)
    const dim3 gTr(NTOT / 32, CDIM / 32, BDIM);
    const dim3 gPrep((CDIM * KCONV + 255) / 256, 6);

    // prep
    transpose_c2n<<<gTr, blk>>>(x, xt, xqk);
    prep_all<<<gPrep, blk>>>(conv1_w, conv2_w, Wv, sig1_w, sig2_w, Wq, Wk,
                             w1r, w2r, wv16, ws1, ws2, wqk);

    // q/k (tensor, double hi/lo), v
    tc_qk<<<gQK, blk, SMEM_TC_SZ>>>(wqk, xqk, bq, bk, qh, kh);
    tc_nn<<<gTC, blk, SMEM_TC_SZ>>>(wv16, xt, bv, (const float*)0, v);

    // energy + 3-shift softmax
    tc_energy<<<gEn, blk, SMEM_TC_SZ>>>(qh, kh, p);
    softmax_rows3<<<dim3(NTOT, BDIM), blk>>>(p, ph0, ph1, ph2, i0, i1, i2);

    // stage 0
    tc_attn<-1, true><<<gTC, blk, SMEM_TC_SZ>>>(v, ph0, i0, gamma, x, (float*)0, yt);
    tc_conv<<<gTC, blk, SMEM_TC_SZ>>>(w1r, yt, bn1_w, bn1_b, bn1_m, bn1_v, t1, t1t);

    // stage 1
    tc_nn<<<gTC, blk, SMEM_TC_SZ>>>(ws1, t1t, sig1_b, t1, s);
    tc_attn<6, true><<<gTC, blk, SMEM_TC_SZ>>>(s, ph1, i1, gamma1, t1, (float*)0, yt);
    tc_conv<<<gTC, blk, SMEM_TC_SZ>>>(w2r, yt, bn2_w, bn2_b, bn2_m, bn2_v, t2, t2t);

    // stage 2
    tc_nn<<<gTC, blk, SMEM_TC_SZ>>>(ws2, t2t, sig2_b, t2, s);
    tc_attn<12, false><<<gTC, blk, SMEM_TC_SZ>>>(s, ph2, i2, gamma2, t2, (float*)d_out, (__half*)0);
}

// round 10
// speedup vs baseline: 6.6409x; 1.0422x over previous
#include <cuda_runtime.h>
#include <cuda_fp16.h>
#include <stdint.h>

#define NTOT 2304
#define BDIM 4
#define CDIM 512
#define DQD  64
#define HW   48
#define KCONV (CDIM * 9)
#define KQK  1536

// ---------------- fp16 mma tile config ----------------
#define TCM 128
#define TCN 128
#define TCK 64                          // k halves per chunk (=128B row)
#define TILE16 (TCM * TCK * 2)          // 16384 bytes
#define NSTAGE 2
#define SMEM_TC_SZ (2048 + 2 * NSTAGE * TILE16)  // 67584 -> 2 CTAs/SM

#define SWZ(off) ((off) ^ (((off) >> 3) & 0x70))

// ---------------- scratch ----------------
__device__ __half g_qh [BDIM*NTOT*128];
__device__ __half g_kh [BDIM*NTOT*128];
__device__ float  g_p [(size_t)BDIM*NTOT*NTOT];
__device__ __half g_ph0[(size_t)BDIM*NTOT*NTOT];
__device__ __half g_ph1[(size_t)BDIM*NTOT*NTOT];
__device__ __half g_ph2[(size_t)BDIM*NTOT*NTOT];
__device__ __half g_v  [BDIM*CDIM*NTOT];
__device__ __half g_s  [BDIM*CDIM*NTOT];
__device__ float  g_inv0[BDIM*NTOT];
__device__ float  g_inv1[BDIM*NTOT];
__device__ float  g_inv2[BDIM*NTOT];
__device__ __half g_xt [BDIM*NTOT*CDIM];
__device__ __half g_xqk[(size_t)BDIM*NTOT*KQK];
__device__ __half g_yt [BDIM*NTOT*CDIM];
__device__ float  g_t1 [BDIM*CDIM*NTOT];
__device__ __half g_t1t[BDIM*NTOT*CDIM];
__device__ float  g_t2 [BDIM*CDIM*NTOT];
__device__ __half g_t2t[BDIM*NTOT*CDIM];
__device__ __half g_w1r[CDIM*KCONV];
__device__ __half g_w2r[CDIM*KCONV];
__device__ __half g_wv16[CDIM*CDIM];
__device__ __half g_ws1[CDIM*CDIM];
__device__ __half g_ws2[CDIM*CDIM];
__device__ __half g_wqk[128*KQK];

// ---------------- helpers ----------------
__device__ __forceinline__ uint32_t smem_u32(const void* p) {
    return (uint32_t)__cvta_generic_to_shared(p);
}
__device__ __forceinline__ void ldsm4(uint32_t* r, uint32_t addr) {
    asm volatile("ldmatrix.sync.aligned.m8n8.x4.shared.b16 {%0,%1,%2,%3}, [%4];"
        : "=r"(r[0]), "=r"(r[1]), "=r"(r[2]), "=r"(r[3]) : "r"(addr));
}
__device__ __forceinline__ void mma16816(float* c, const uint32_t* a, const uint32_t* b) {
    asm volatile("mma.sync.aligned.m16n8k16.row.col.f32.f16.f16.f32 "
        "{%0,%1,%2,%3}, {%4,%5,%6,%7}, {%8,%9}, {%0,%1,%2,%3};"
        : "+f"(c[0]), "+f"(c[1]), "+f"(c[2]), "+f"(c[3])
        : "r"(a[0]), "r"(a[1]), "r"(a[2]), "r"(a[3]), "r"(b[0]), "r"(b[1]));
}
#define CP_A16(dst, src) \
    asm volatile("cp.async.cg.shared.global [%0], [%1], 16;" :: "r"(dst), "l"(src))
#define CP_A16Z(dst, src, sz) \
    asm volatile("cp.async.cg.shared.global [%0], [%1], 16, %2;" :: "r"(dst), "l"(src), "r"(sz))
#define CP_COMMIT() asm volatile("cp.async.commit_group;")
#define CP_WAIT0()  asm volatile("cp.async.wait_group 0;")

__device__ __forceinline__ void mma_chunk16(
    uint32_t aT, uint32_t bT,
    const uint32_t aOff[2], const uint32_t bOff[4],
    uint32_t aColSel, uint32_t bColSel, uint32_t xorv,
    float (&acc)[2][8][4])
{
#pragma unroll
    for (int g = 0; g < 4; g++) {
        uint32_t ka = ((uint32_t)(g * 32) + aColSel) ^ xorv;
        uint32_t kb = ((uint32_t)(g * 32) + bColSel) ^ xorv;
        uint32_t af[2][4];
        ldsm4(af[0], aT + aOff[0] + ka);
        ldsm4(af[1], aT + aOff[1] + ka);
#pragma unroll
        for (int p = 0; p < 4; p++) {
            uint32_t bf[4];
            ldsm4(bf, bT + bOff[p] + kb);
            mma16816(acc[0][2 * p],     af[0], bf);
            mma16816(acc[0][2 * p + 1], af[0], bf + 2);
            mma16816(acc[1][2 * p],     af[1], bf);
            mma16816(acc[1][2 * p + 1], af[1], bf + 2);
        }
    }
}

#define MMA_PRECOMP16() \
    const int lane = tid & 31, wid = tid >> 5; \
    const int wm = wid >> 1, wn = wid & 1; \
    const int j8 = lane >> 3, rr = lane & 7; \
    const uint32_t xorv = rr * 16; \
    const uint32_t aColSel = (j8 >> 1) * 16; \
    const uint32_t bColSel = (j8 & 1) * 16; \
    uint32_t aOff[2], bOff[4]; \
    aOff[0] = (wm * 32 +      (j8 & 1) * 8 + rr) * 128; \
    aOff[1] = aOff[0] + 16 * 128; \
    bOff[0] = (wn * 64 +      (j8 >> 1) * 8 + rr) * 128; \
    bOff[1] = bOff[0] + 16 * 128; \
    bOff[2] = bOff[0] + 32 * 128; \
    bOff[3] = bOff[0] + 48 * 128; \
    const int col8 = tid & 7; \
    const int row0 = tid >> 3; \
    float acc[2][8][4]; \
_Pragma("unroll") \
    for (int i_ = 0; i_ < 2; i_++) \
_Pragma("unroll") \
        for (int j_ = 0; j_ < 8; j_++) \
_Pragma("unroll") \
            for (int e_ = 0; e_ < 4; e_++) acc[i_][j_][e_] = 0.f;

#define TILES_SETUP() \
    uint32_t tilesAddr = (sb + 1024 + 1023) & ~1023u; \
    uint32_t stA[NSTAGE], stB[NSTAGE]; \
_Pragma("unroll") \
    for (int s_ = 0; s_ < NSTAGE; s_++) { \
        stA[s_] = tilesAddr + s_ * 2 * TILE16; \
        stB[s_] = stA[s_] + TILE16; \
    }

// double-buffer mainloop: wait(ci) -> sync -> issue(ci+1) -> compute(ci)
#define TC_MAINLOOP(NC) \
    issueLoads(0, 0); CP_COMMIT(); \
    for (int ci = 0; ci < (NC); ci++) { \
        CP_WAIT0(); \
        __syncthreads(); \
        if (ci + 1 < (NC)) { issueLoads(ci + 1, (ci + 1) & 1); CP_COMMIT(); } \
        mma_chunk16(stA[ci & 1], stB[ci & 1], aOff, bOff, aColSel, bColSel, xorv, acc); \
    }

#define STAGE_ROWSTRIDE 136

// ========== tc_attn ==========
template<int RADIUS, bool OUT_T>
__global__ __launch_bounds__(256, 2) void tc_attn(
    const __half* __restrict__ A, const __half* __restrict__ P,
    const float* __restrict__ invsum, const float* __restrict__ gammaPtr,
    const float* __restrict__ Res, float* __restrict__ OutF, __half* __restrict__ OutT)
{
    extern __shared__ char smem[];
    uint32_t sb = smem_u32(smem);
    float* smf = (float*)smem;
    const int tid = threadIdx.x;
    const int bz = blockIdx.z;
    const __half* Ap = A + (size_t)bz * CDIM * NTOT;
    const __half* Pp = P + (size_t)bz * NTOT * NTOT;
    const float* Rp = Res + (size_t)bz * CDIM * NTOT;
    const int rowBase = blockIdx.y * TCM;
    const int colBase = blockIdx.x * TCN;

    TILES_SETUP();
    MMA_PRECOMP16();

    if (tid < TCN) smf[tid] = invsum[(size_t)bz * NTOT + colBase + tid];

    int kStart = 0, kEnd = NTOT;
    if (RADIUS >= 0) {
        int rmLo = colBase / HW, rmHi = (colBase + TCN - 1) / HW;
        int rlo = rmLo - RADIUS; if (rlo < 0) rlo = 0;
        int rhi = rmHi + RADIUS; if (rhi > HW - 1) rhi = HW - 1;
        kStart = (rlo * HW) & ~(TCK - 1);
        kEnd = ((rhi + 1) * HW + TCK - 1) & ~(TCK - 1);
        if (kEnd > NTOT) kEnd = NTOT;
    }
    const int NC = (kEnd - kStart) / TCK;

    auto issueLoads = [&](int ci, int st) {
        const int k0 = kStart + ci * TCK;
#pragma unroll
        for (int s = 0; s < 4; s++) {
            int row = row0 + s * 32;
            uint32_t sw = SWZ(row * 128 + col8 * 16);
            CP_A16(stA[st] + sw, &Ap[(size_t)(rowBase + row) * NTOT + k0 + col8 * 8]);
            CP_A16(stB[st] + sw, &Pp[(size_t)(colBase + row) * NTOT + k0 + col8 * 8]);
        }
    };

    TC_MAINLOOP(NC);

    const float g = *gammaPtr;
    if (OUT_T) {
        __syncthreads();
        __half* sm16 = (__half*)(smem + (tilesAddr - sb));
        __half* OpT = OutT + (size_t)bz * NTOT * CDIM;
#pragma unroll
        for (int mt = 0; mt < 2; mt++) {
            int mloc = wm * 32 + mt * 16 + (lane >> 2);
#pragma unroll
            for (int half = 0; half < 2; half++) {
                int cc = mloc + half * 8;
                int c = rowBase + cc;
                size_t ro = (size_t)c * NTOT;
#pragma unroll
                for (int nt = 0; nt < 8; nt++) {
                    int nl = wn * 64 + nt * 8 + (lane & 3) * 2;
                    int n = colBase + nl;
                    float2 res = *(const float2*)&Rp[ro + n];
                    float ox = acc[mt][nt][half * 2 + 0] * (g * smf[nl])     + res.x;
                    float oy = acc[mt][nt][half * 2 + 1] * (g * smf[nl + 1]) + res.y;
                    sm16[nl * STAGE_ROWSTRIDE + cc]       = __float2half_rn(ox);
                    sm16[(nl + 1) * STAGE_ROWSTRIDE + cc] = __float2half_rn(oy);
                }
            }
        }
        __syncthreads();
#pragma unroll
        for (int r = 0; r < 8; r++) {
            int row = r * 16 + (tid >> 4);
            int c8 = (tid & 15) * 8;
            uint4 u = *(const uint4*)&sm16[row * STAGE_ROWSTRIDE + c8];
            *(uint4*)&OpT[(size_t)(colBase + row) * CDIM + rowBase + c8] = u;
        }
    } else {
        float* OpF = OutF + (size_t)bz * CDIM * NTOT;
#pragma unroll
        for (int mt = 0; mt < 2; mt++) {
            int mloc = wm * 32 + mt * 16 + (lane >> 2);
#pragma unroll
            for (int half = 0; half < 2; half++) {
                int c = rowBase + mloc + half * 8;
                size_t ro = (size_t)c * NTOT;
#pragma unroll
                for (int nt = 0; nt < 8; nt++) {
                    int nl = wn * 64 + nt * 8 + (lane & 3) * 2;
                    int n = colBase + nl;
                    float2 res = *(const float2*)&Rp[ro + n];
                    float2 o;
                    o.x = acc[mt][nt][half * 2 + 0] * (g * smf[nl])     + res.x;
                    o.y = acc[mt][nt][half * 2 + 1] * (g * smf[nl + 1]) + res.y;
                    *(float2*)&OpF[ro + n] = o;
                }
            }
        }
    }
}

// ========== tc_conv ==========
__global__ __launch_bounds__(256, 2) void tc_conv(
    const __half* __restrict__ Wr, const __half* __restrict__ Xt,
    const float* __restrict__ bnw, const float* __restrict__ bnb,
    const float* __restrict__ bnm, const float* __restrict__ bnv,
    float* __restrict__ Out, __half* __restrict__ OutT)
{
    extern __shared__ char smem[];
    uint32_t sb = smem_u32(smem);
    const int tid = threadIdx.x;
    const __half* Xp = Xt + (size_t)blockIdx.z * NTOT * CDIM;
    float* Op = Out + (size_t)blockIdx.z * CDIM * NTOT;
    __half* OpT = OutT + (size_t)blockIdx.z * NTOT * CDIM;
    const int rowBase = blockIdx.y * TCM;
    const int colBase = blockIdx.x * TCN;

    TILES_SETUP();
    MMA_PRECOMP16();

    int pys[4], pxs[4];
#pragma unroll
    for (int s = 0; s < 4; s++) {
        int pix = colBase + row0 + s * 32;
        pys[s] = pix / HW; pxs[s] = pix - pys[s] * HW;
    }

    const int NC = KCONV / TCK;   // 72

    auto issueLoads = [&](int ci, int st) {
        const int k0 = ci * TCK;
        const int tap = ci >> 3;
        const int icb = (ci & 7) * TCK;
        const int ky = tap / 3, kx = tap - ky * 3;
#pragma unroll
        for (int s = 0; s < 4; s++) {
            int row = row0 + s * 32;
            uint32_t sw = SWZ(row * 128 + col8 * 16);
            CP_A16(stA[st] + sw, &Wr[(size_t)(rowBase + row) * KCONV + k0 + col8 * 8]);
            int iy = pys[s] + ky - 1, ix = pxs[s] + kx - 1;
            bool ok = (unsigned)iy < HW && (unsigned)ix < HW;
            const __half* src = ok ? &Xp[(size_t)(iy * HW + ix) * CDIM + icb + col8 * 8] : Xp;
            CP_A16Z(stB[st] + sw, src, ok ? 16u : 0u);
        }
    };

    TC_MAINLOOP(NC);

    __syncthreads();
    __half* sm16 = (__half*)(smem + (tilesAddr - sb));
#pragma unroll
    for (int mt = 0; mt < 2; mt++) {
        int mloc = wm * 32 + mt * 16 + (lane >> 2);
#pragma unroll
        for (int half = 0; half < 2; half++) {
            int cc = mloc + half * 8;
            int oc = rowBase + cc;
            float scale = bnw[oc] * rsqrtf(bnv[oc] + 1e-5f);
            float shift = bnb[oc] - bnm[oc] * scale;
            size_t ro = (size_t)oc * NTOT;
#pragma unroll
            for (int nt = 0; nt < 8; nt++) {
                int nl = wn * 64 + nt * 8 + (lane & 3) * 2;
                int n = colBase + nl;
                float ox = fmaxf(acc[mt][nt][half * 2 + 0] * scale + shift, 0.f);
                float oy = fmaxf(acc[mt][nt][half * 2 + 1] * scale + shift, 0.f);
                float2 o; o.x = ox; o.y = oy;
                *(float2*)&Op[ro + n] = o;
                sm16[nl * STAGE_ROWSTRIDE + cc]       = __float2half_rn(ox);
                sm16[(nl + 1) * STAGE_ROWSTRIDE + cc] = __float2half_rn(oy);
            }
        }
    }
    __syncthreads();
#pragma unroll
    for (int r = 0; r < 8; r++) {
        int row = r * 16 + (tid >> 4);
        int c8 = (tid & 15) * 8;
        uint4 u = *(const uint4*)&sm16[row * STAGE_ROWSTRIDE + c8];
        *(uint4*)&OpT[(size_t)(colBase + row) * CDIM + rowBase + c8] = u;
    }
}

// ====== tc_nn ======
__global__ __launch_bounds__(256, 2) void tc_nn(
    const __half* __restrict__ W16, const __half* __restrict__ Bt,
    const float* __restrict__ bias, const float* __restrict__ gateSrc,
    __half* __restrict__ Out)
{
    extern __shared__ char smem[];
    uint32_t sb = smem_u32(smem);
    const int tid = threadIdx.x;
    const __half* Bp = Bt + (size_t)blockIdx.z * NTOT * CDIM;
    const float* Gp = gateSrc ? gateSrc + (size_t)blockIdx.z * CDIM * NTOT : (const float*)0;
    __half* Op = Out + (size_t)blockIdx.z * CDIM * NTOT;
    const int rowBase = blockIdx.y * TCM;
    const int colBase = blockIdx.x * TCN;

    TILES_SETUP();
    MMA_PRECOMP16();

    const int NC = CDIM / TCK;   // 8

    auto issueLoads = [&](int ci, int st) {
        const int k0 = ci * TCK;
#pragma unroll
        for (int s = 0; s < 4; s++) {
            int row = row0 + s * 32;
            uint32_t sw = SWZ(row * 128 + col8 * 16);
            CP_A16(stA[st] + sw, &W16[(size_t)(rowBase + row) * CDIM + k0 + col8 * 8]);
            CP_A16(stB[st] + sw, &Bp[(size_t)(colBase + row) * CDIM + k0 + col8 * 8]);
        }
    };

    TC_MAINLOOP(NC);

#pragma unroll
    for (int mt = 0; mt < 2; mt++) {
        int mloc = wm * 32 + mt * 16 + (lane >> 2);
#pragma unroll
        for (int half = 0; half < 2; half++) {
            int d = rowBase + mloc + half * 8;
            float bv = bias[d];
            size_t ro = (size_t)d * NTOT;
#pragma unroll
            for (int nt = 0; nt < 8; nt++) {
                int n = colBase + wn * 64 + nt * 8 + (lane & 3) * 2;
                float ox = acc[mt][nt][half * 2 + 0] + bv;
                float oy = acc[mt][nt][half * 2 + 1] + bv;
                if (Gp) {
                    float2 gv = *(const float2*)&Gp[ro + n];
                    ox = gv.x * (1.f / (1.f + __expf(-ox)));
                    oy = gv.y * (1.f / (1.f + __expf(-oy)));
                }
                *(__half2*)&Op[ro + n] = __floats2half2_rn(ox, oy);
            }
        }
    }
}

// ====== tc_qk ======
__global__ __launch_bounds__(256, 2) void tc_qk(
    const __half* __restrict__ Wqk, const __half* __restrict__ Xqk,
    const float* __restrict__ bq, const float* __restrict__ bk,
    __half* __restrict__ Qh, __half* __restrict__ Kh)
{
    extern __shared__ char smem[];
    uint32_t sb = smem_u32(smem);
    const int tid = threadIdx.x;
    const int bz = blockIdx.z;
    const __half* Bp = Xqk + (size_t)bz * NTOT * KQK;
    __half* qh = Qh + (size_t)bz * NTOT * 128;
    __half* kh = Kh + (size_t)bz * NTOT * 128;
    const int colBase = blockIdx.x * TCN;

    TILES_SETUP();
    MMA_PRECOMP16();

    const int NC = KQK / TCK;   // 24

    auto issueLoads = [&](int ci, int st) {
        const int k0 = ci * TCK;
#pragma unroll
        for (int s = 0; s < 4; s++) {
            int row = row0 + s * 32;
            uint32_t sw = SWZ(row * 128 + col8 * 16);
            CP_A16(stA[st] + sw, &Wqk[(size_t)row * KQK + k0 + col8 * 8]);
            CP_A16(stB[st] + sw, &Bp[(size_t)(colBase + row) * KQK + k0 + col8 * 8]);
        }
    };

    TC_MAINLOOP(NC);

#pragma unroll
    for (int mt = 0; mt < 2; mt++) {
        int mloc = wm * 32 + mt * 16 + (lane >> 2);
#pragma unroll
        for (int half = 0; half < 2; half++) {
            int d = mloc + half * 8;
            bool isQ = d < 64;
            float bv = isQ ? bq[d] : bk[d - 64];
            __half* dst = isQ ? qh : kh;
            int ch = d & 63;
#pragma unroll
            for (int nt = 0; nt < 8; nt++) {
                int n = colBase + wn * 64 + nt * 8 + (lane & 3) * 2;
#pragma unroll
                for (int e = 0; e < 2; e++) {
                    float val = acc[mt][nt][half * 2 + e] + bv;
                    __half hi = __float2half_rn(val);
                    __half lo = __float2half_rn(val - __half2float(hi));
                    dst[(size_t)(n + e) * 128 + ch]      = hi;
                    dst[(size_t)(n + e) * 128 + 64 + ch] = lo;
                }
            }
        }
    }
}

// ====== tc_energy ======
__global__ __launch_bounds__(256, 2) void tc_energy(
    const __half* __restrict__ Qh, const __half* __restrict__ Kh,
    float* __restrict__ E)
{
    extern __shared__ char smem[];
    uint32_t sb = smem_u32(smem);
    const int tid = threadIdx.x;
    const __half* Ap = Qh + (size_t)blockIdx.z * NTOT * 128;
    const __half* Bp = Kh + (size_t)blockIdx.z * NTOT * 128;
    float* Ep = E + (size_t)blockIdx.z * NTOT * NTOT;
    const int rowBase = blockIdx.y * TCM;
    const int colBase = blockIdx.x * TCN;

    TILES_SETUP();
    MMA_PRECOMP16();

    const int NC = 2;

    auto issueLoads = [&](int ci, int st) {
        const int k0 = ci * TCK;
#pragma unroll
        for (int s = 0; s < 4; s++) {
            int row = row0 + s * 32;
            uint32_t sw = SWZ(row * 128 + col8 * 16);
            CP_A16(stA[st] + sw, &Ap[(size_t)(rowBase + row) * 128 + k0 + col8 * 8]);
            CP_A16(stB[st] + sw, &Bp[(size_t)(colBase + row) * 128 + k0 + col8 * 8]);
        }
    };

    TC_MAINLOOP(NC);

#pragma unroll
    for (int mt = 0; mt < 2; mt++) {
        int mloc = wm * 32 + mt * 16 + (lane >> 2);
#pragma unroll
        for (int half = 0; half < 2; half++) {
            int m = rowBase + mloc + half * 8;
            size_t ro = (size_t)m * NTOT;
#pragma unroll
            for (int nt = 0; nt < 8; nt++) {
                int n = colBase + wn * 64 + nt * 8 + (lane & 3) * 2;
                float2 o;
                o.x = acc[mt][nt][half * 2 + 0];
                o.y = acc[mt][nt][half * 2 + 1];
                *(float2*)&Ep[ro + n] = o;
            }
        }
    }
}

// ---------------- transpose: fp32 [C][N] -> xt fp16 [N][C] + xqk [N][1536] ----------------
__global__ __launch_bounds__(256) void transpose_c2n(
    const float* __restrict__ X, __half* __restrict__ Xt, __half* __restrict__ Xqk)
{
    __shared__ float tile[32][33];
    const int b = blockIdx.z;
    const int n0 = blockIdx.x * 32, c0 = blockIdx.y * 32;
    const int tx = threadIdx.x & 31, ty = threadIdx.x >> 5;
    const float* Xp = X + (size_t)b * CDIM * NTOT;
    __half* Tp = Xt + (size_t)b * NTOT * CDIM;
    __half* Qp = Xqk + (size_t)b * NTOT * KQK;
#pragma unroll
    for (int k = 0; k < 4; k++)
        tile[ty + 8 * k][tx] = Xp[(size_t)(c0 + ty + 8 * k) * NTOT + n0 + tx];
    __syncthreads();
#pragma unroll
    for (int k = 0; k < 4; k++) {
        float val = tile[tx][ty + 8 * k];
        __half hi = __float2half_rn(val);
        __half lo = __float2half_rn(val - __half2float(hi));
        int n = n0 + ty + 8 * k, c = c0 + tx;
        Tp[(size_t)n * CDIM + c] = hi;
        size_t qb = (size_t)n * KQK + c;
        Qp[qb] = hi;
        Qp[qb + 512] = lo;
        Qp[qb + 1024] = hi;
    }
}

// ---------------- prep: all weight conversions in one launch ----------------
__global__ __launch_bounds__(256) void prep_all(
    const float* __restrict__ conv1_w, const float* __restrict__ conv2_w,
    const float* __restrict__ Wv, const float* __restrict__ sig1_w,
    const float* __restrict__ sig2_w,
    const float* __restrict__ Wq, const float* __restrict__ Wk,
    __half* __restrict__ w1r, __half* __restrict__ w2r,
    __half* __restrict__ wv16, __half* __restrict__ ws1, __half* __restrict__ ws2,
    __half* __restrict__ wqk)
{
    const int seg = blockIdx.y;
    const int idx = blockIdx.x * 256 + threadIdx.x;
    if (seg < 2) {
        if (idx < CDIM * KCONV) {
            const float* W = seg == 0 ? conv1_w : conv2_w;
            __half* Wr = seg == 0 ? w1r : w2r;
            int oc = idx / KCONV, kk = idx - oc * KCONV;
            int tap = kk >> 9, ic = kk & 511;
            Wr[idx] = __float2half_rn(W[(size_t)oc * KCONV + ic * 9 + tap]);
        }
    } else if (seg < 5) {
        if (idx < CDIM * CDIM) {
            const float* W = seg == 2 ? Wv : (seg == 3 ? sig1_w : sig2_w);
            __half* O = seg == 2 ? wv16 : (seg == 3 ? ws1 : ws2);
            O[idx] = __float2half_rn(W[idx]);
        }
    } else {
        if (idx < 128 * 512) {
            int d = idx >> 9, c = idx & 511;
            float w = d < 64 ? Wq[(size_t)d * CDIM + c] : Wk[(size_t)(d - 64) * CDIM + c];
            __half hi = __float2half_rn(w);
            __half lo = __float2half_rn(w - __half2float(hi));
            size_t base = (size_t)d * KQK + c;
            wqk[base] = hi;
            wqk[base + 512] = hi;
            wqk[base + 1024] = lo;
        }
    }
}

// ---- softmax: 3 shifts, band-limited ph1/ph2 writes ----
__global__ __launch_bounds__(256) void softmax_rows3(
    const float* __restrict__ P,
    __half* __restrict__ Ph0, __half* __restrict__ Ph1, __half* __restrict__ Ph2,
    float* __restrict__ inv0, float* __restrict__ inv1, float* __restrict__ inv2)
{
    __shared__ float rowv[NTOT];
    __shared__ float red[256];
    const int row = blockIdx.x, b = blockIdx.y, tid = threadIdx.x;
    const size_t roff = ((size_t)b * NTOT + row) * NTOT;
    const float* p = P + roff;

    for (int i = tid; i < NTOT / 4; i += 256)
        ((float4*)rowv)[i] = ((const float4*)p)[i];
    __syncthreads();

    const int rm = row / HW, cm = row - rm * HW;
    int w1lo = (rm - 6 - 4) * HW;  w1lo = w1lo < 0 ? 0 : (w1lo & ~63);
    int w1hi = ((rm + 6 + 5) * HW + 63) & ~63; if (w1hi > NTOT) w1hi = NTOT;
    int w2lo = (rm - 12 - 4) * HW; w2lo = w2lo < 0 ? 0 : (w2lo & ~63);
    int w2hi = ((rm + 12 + 5) * HW + 63) & ~63; if (w2hi > NTOT) w2hi = NTOT;

    float m0 = -1e30f, m6 = -1e30f, m12 = -1e30f;
    for (int i = tid; i < NTOT / 4; i += 256) {
        float4 v4 = ((const float4*)rowv)[i];
        const float* v = (const float*)&v4;
        int n0 = i * 4;
#pragma unroll
        for (int e = 0; e < 4; e++) {
            int n = n0 + e;
            float v1 = v[e];
            m0 = fmaxf(m0, v1);
            int rn = n / HW, cn = n - rn * HW;
            int dr = rm - rn; dr = dr < 0 ? -dr : dr;
            int dc = cm - cn; dc = dc < 0 ? -dc : dc;
            int d = dr > dc ? dr : dc;
            if (d <= 12) { m12 = fmaxf(m12, v1); if (d <= 6) m6 = fmaxf(m6, v1); }
        }
    }
    red[tid] = m0; __syncthreads();
    for (int s = 128; s > 0; s >>= 1) { if (tid < s) red[tid] = fmaxf(red[tid], red[tid + s]); __syncthreads(); }
    m0 = red[0]; __syncthreads();
    red[tid] = m6; __syncthreads();
    for (int s = 128; s > 0; s >>= 1) { if (tid < s) red[tid] = fmaxf(red[tid], red[tid + s]); __syncthreads(); }
    m6 = red[0]; __syncthreads();
    red[tid] = m12; __syncthreads();
    for (int s = 128; s > 0; s >>= 1) { if (tid < s) red[tid] = fmaxf(red[tid], red[tid + s]); __syncthreads(); }
    m12 = red[0]; __syncthreads();

    float s0 = 0.f, s1 = 0.f, s2 = 0.f;
    for (int i = tid; i < NTOT / 4; i += 256) {
        float4 v4 = ((const float4*)rowv)[i];
        const float* v = (const float*)&v4;
        int n0 = i * 4;
        __half h0a[4], h1a[4], h2a[4];
#pragma unroll
        for (int e = 0; e < 4; e++) {
            int n = n0 + e;
            float v1 = v[e];
            __half h0 = __float2half_rn(__expf(v1 - m0));
            h0a[e] = h0;
            s0 += __half2float(h0);
            int rn = n / HW, cn = n - rn * HW;
            int dr = rm - rn; dr = dr < 0 ? -dr : dr;
            int dc = cm - cn; dc = dc < 0 ? -dc : dc;
            int d = dr > dc ? dr : dc;
            __half h1 = __ushort_as_half(0), h2 = __ushort_as_half(0);
            if (d <= 12) {
                h2 = __float2half_rn(__expf(v1 - m12));
                s2 += __half2float(h2);
                if (d <= 6) { h1 = __float2half_rn(__expf(v1 - m6)); s1 += __half2float(h1); }
            }
            h1a[e] = h1; h2a[e] = h2;
        }
        *(uint2*)&Ph0[roff + n0] = *(uint2*)h0a;
        if (n0 >= w1lo && n0 < w1hi) *(uint2*)&Ph1[roff + n0] = *(uint2*)h1a;
        if (n0 >= w2lo && n0 < w2hi) *(uint2*)&Ph2[roff + n0] = *(uint2*)h2a;
    }
    red[tid] = s0; __syncthreads();
    for (int s = 128; s > 0; s >>= 1) { if (tid < s) red[tid] += red[tid + s]; __syncthreads(); }
    if (tid == 0) inv0[(size_t)b * NTOT + row] = 1.f / red[0];
    __syncthreads();
    red[tid] = s1; __syncthreads();
    for (int s = 128; s > 0; s >>= 1) { if (tid < s) red[tid] += red[tid + s]; __syncthreads(); }
    if (tid == 0) inv1[(size_t)b * NTOT + row] = 1.f / red[0];
    __syncthreads();
    red[tid] = s2; __syncthreads();
    for (int s = 128; s > 0; s >>= 1) { if (tid < s) red[tid] += red[tid + s]; __syncthreads(); }
    if (tid == 0) inv2[(size_t)b * NTOT + row] = 1.f / red[0];
}

// ---------------- launch ----------------
extern "C" void kernel_launch(void* const* d_in, const int* in_sizes, int n_in,
                              void* d_out, int out_size)
{
    const float* x       = (const float*)d_in[0];
    const float* Wq      = (const float*)d_in[1];
    const float* bq      = (const float*)d_in[2];
    const float* Wk      = (const float*)d_in[3];
    const float* bk      = (const float*)d_in[4];
    const float* Wv      = (const float*)d_in[5];
    const float* bv      = (const float*)d_in[6];
    const float* conv1_w = (const float*)d_in[7];
    const float* bn1_w   = (const float*)d_in[8];
    const float* bn1_b   = (const float*)d_in[9];
    const float* bn1_m   = (const float*)d_in[10];
    const float* bn1_v   = (const float*)d_in[11];
    const float* conv2_w = (const float*)d_in[12];
    const float* bn2_w   = (const float*)d_in[13];
    const float* bn2_b   = (const float*)d_in[14];
    const float* bn2_m   = (const float*)d_in[15];
    const float* bn2_v   = (const float*)d_in[16];
    const float* sig1_w  = (const float*)d_in[17];
    const float* sig1_b  = (const float*)d_in[18];
    const float* sig2_w  = (const float*)d_in[19];
    const float* sig2_b  = (const float*)d_in[20];
    const float* gamma   = (const float*)d_in[21];
    const float* gamma1  = (const float*)d_in[22];
    const float* gamma2  = (const float*)d_in[23];

    float *p, *i0, *i1, *i2, *t1, *t2;
    __half *qh, *kh, *ph0, *ph1, *ph2, *v, *s, *xt, *xqk, *yt, *t1t, *t2t;
    __half *w1r, *w2r, *wv16, *ws1, *ws2, *wqk;
    cudaGetSymbolAddress((void**)&qh,  g_qh);
    cudaGetSymbolAddress((void**)&kh,  g_kh);
    cudaGetSymbolAddress((void**)&p,   g_p);
    cudaGetSymbolAddress((void**)&ph0, g_ph0);
    cudaGetSymbolAddress((void**)&ph1, g_ph1);
    cudaGetSymbolAddress((void**)&ph2, g_ph2);
    cudaGetSymbolAddress((void**)&v,   g_v);
    cudaGetSymbolAddress((void**)&s,   g_s);
    cudaGetSymbolAddress((void**)&i0,  g_inv0);
    cudaGetSymbolAddress((void**)&i1,  g_inv1);
    cudaGetSymbolAddress((void**)&i2,  g_inv2);
    cudaGetSymbolAddress((void**)&xt,  g_xt);
    cudaGetSymbolAddress((void**)&xqk, g_xqk);
    cudaGetSymbolAddress((void**)&yt,  g_yt);
    cudaGetSymbolAddress((void**)&t1,  g_t1);
    cudaGetSymbolAddress((void**)&t1t, g_t1t);
    cudaGetSymbolAddress((void**)&t2,  g_t2);
    cudaGetSymbolAddress((void**)&t2t, g_t2t);
    cudaGetSymbolAddress((void**)&w1r, g_w1r);
    cudaGetSymbolAddress((void**)&w2r, g_w2r);
    cudaGetSymbolAddress((void**)&wv16, g_wv16);
    cudaGetSymbolAddress((void**)&ws1, g_ws1);
    cudaGetSymbolAddress((void**)&ws2, g_ws2);
    cudaGetSymbolAddress((void**)&wqk, g_wqk);

    cudaFuncSetAttribute((const void*)tc_attn<-1, true>,  cudaFuncAttributeMaxDynamicSharedMemorySize, SMEM_TC_SZ);
    cudaFuncSetAttribute((const void*)tc_attn<6, true>,   cudaFuncAttributeMaxDynamicSharedMemorySize, SMEM_TC_SZ);
    cudaFuncSetAttribute((const void*)tc_attn<12, false>, cudaFuncAttributeMaxDynamicSharedMemorySize, SMEM_TC_SZ);
    cudaFuncSetAttribute((const void*)tc_conv,            cudaFuncAttributeMaxDynamicSharedMemorySize, SMEM_TC_SZ);
    cudaFuncSetAttribute((const void*)tc_nn,              cudaFuncAttributeMaxDynamicSharedMemorySize, SMEM_TC_SZ);
    cudaFuncSetAttribute((const void*)tc_qk,              cudaFuncAttributeMaxDynamicSharedMemorySize, SMEM_TC_SZ);
    cudaFuncSetAttribute((const void*)tc_energy,          cudaFuncAttributeMaxDynamicSharedMemorySize, SMEM_TC_SZ);

    const dim3 blk(256);
    const dim3 gTC(NTOT / TCN, CDIM / TCM, BDIM);    // (18, 4, 4)
    const dim3 gQK(NTOT / TCN, 1, BDIM);
    const dim3 gEn(NTOT / TCN, NTOT / TCM, BDIM);    // (18, 18, 4)
    const dim3 gTr(NTOT / 32, CDIM / 32, BDIM);
    const dim3 gPrep((CDIM * KCONV + 255) / 256, 6);

    // prep
    transpose_c2n<<<gTr, blk>>>(x, xt, xqk);
    prep_all<<<gPrep, blk>>>(conv1_w, conv2_w, Wv, sig1_w, sig2_w, Wq, Wk,
                             w1r, w2r, wv16, ws1, ws2, wqk);

    // q/k (tensor, double hi/lo), v
    tc_qk<<<gQK, blk, SMEM_TC_SZ>>>(wqk, xqk, bq, bk, qh, kh);
    tc_nn<<<gTC, blk, SMEM_TC_SZ>>>(wv16, xt, bv, (const float*)0, v);

    // energy + 3-shift softmax
    tc_energy<<<gEn, blk, SMEM_TC_SZ>>>(qh, kh, p);
    softmax_rows3<<<dim3(NTOT, BDIM), blk>>>(p, ph0, ph1, ph2, i0, i1, i2);

    // stage 0
    tc_attn<-1, true><<<gTC, blk, SMEM_TC_SZ>>>(v, ph0, i0, gamma, x, (float*)0, yt);
    tc_conv<<<gTC, blk, SMEM_TC_SZ>>>(w1r, yt, bn1_w, bn1_b, bn1_m, bn1_v, t1, t1t);

    // stage 1
    tc_nn<<<gTC, blk, SMEM_TC_SZ>>>(ws1, t1t, sig1_b, t1, s);
    tc_attn<6, true><<<gTC, blk, SMEM_TC_SZ>>>(s, ph1, i1, gamma1, t1, (float*)0, yt);
    tc_conv<<<gTC, blk, SMEM_TC_SZ>>>(w2r, yt, bn2_w, bn2_b, bn2_m, bn2_v, t2, t2t);

    // stage 2
    tc_nn<<<gTC, blk, SMEM_TC_SZ>>>(ws2, t2t, sig2_b, t2, s);
    tc_attn<12, false><<<gTC, blk, SMEM_TC_SZ>>>(s, ph2, i2, gamma2, t2, (float*)d_out, (__half*)0);
}

// round 11
// speedup vs baseline: 6.6885x; 1.0072x over previous
#include <cuda_runtime.h>
#include <cuda_fp16.h>
#include <stdint.h>

#define NTOT 2304
#define BDIM 4
#define CDIM 512
#define DQD  64
#define HW   48
#define KCONV (CDIM * 9)
#define KQK  1536

// ---------------- fp16 mma tile config ----------------
#define TCM 128
#define TCN 128
#define TCK 64                          // k halves per chunk (=128B row)
#define TILE16 (TCM * TCK * 2)          // 16384 bytes
#define NSTAGE 3
#define SMEM_TC_SZ (2048 + 2 * NSTAGE * TILE16)  // 100352; x2 CTAs = 196KB/SM

#define SWZ(off) ((off) ^ (((off) >> 3) & 0x70))

// ---------------- scratch ----------------
__device__ __half g_qh [BDIM*NTOT*128];
__device__ __half g_kh [BDIM*NTOT*128];
__device__ float  g_p [(size_t)BDIM*NTOT*NTOT];
__device__ __half g_ph0[(size_t)BDIM*NTOT*NTOT];
__device__ __half g_ph1[(size_t)BDIM*NTOT*NTOT];
__device__ __half g_ph2[(size_t)BDIM*NTOT*NTOT];
__device__ __half g_v  [BDIM*CDIM*NTOT];
__device__ __half g_s  [BDIM*CDIM*NTOT];
__device__ float  g_inv0[BDIM*NTOT];
__device__ float  g_inv1[BDIM*NTOT];
__device__ float  g_inv2[BDIM*NTOT];
__device__ __half g_xt [BDIM*NTOT*CDIM];
__device__ __half g_xqk[(size_t)BDIM*NTOT*KQK];
__device__ __half g_yt [BDIM*NTOT*CDIM];
__device__ float  g_t1 [BDIM*CDIM*NTOT];
__device__ __half g_t1t[BDIM*NTOT*CDIM];
__device__ float  g_t2 [BDIM*CDIM*NTOT];
__device__ __half g_t2t[BDIM*NTOT*CDIM];
__device__ __half g_w1r[CDIM*KCONV];
__device__ __half g_w2r[CDIM*KCONV];
__device__ __half g_wv16[CDIM*CDIM];
__device__ __half g_ws1[CDIM*CDIM];
__device__ __half g_ws2[CDIM*CDIM];
__device__ __half g_wqk[128*KQK];

// ---------------- helpers ----------------
__device__ __forceinline__ uint32_t smem_u32(const void* p) {
    return (uint32_t)__cvta_generic_to_shared(p);
}
__device__ __forceinline__ void ldsm4(uint32_t* r, uint32_t addr) {
    asm volatile("ldmatrix.sync.aligned.m8n8.x4.shared.b16 {%0,%1,%2,%3}, [%4];"
        : "=r"(r[0]), "=r"(r[1]), "=r"(r[2]), "=r"(r[3]) : "r"(addr));
}
__device__ __forceinline__ void mma16816(float* c, const uint32_t* a, const uint32_t* b) {
    asm volatile("mma.sync.aligned.m16n8k16.row.col.f32.f16.f16.f32 "
        "{%0,%1,%2,%3}, {%4,%5,%6,%7}, {%8,%9}, {%0,%1,%2,%3};"
        : "+f"(c[0]), "+f"(c[1]), "+f"(c[2]), "+f"(c[3])
        : "r"(a[0]), "r"(a[1]), "r"(a[2]), "r"(a[3]), "r"(b[0]), "r"(b[1]));
}
#define CP_A16(dst, src) \
    asm volatile("cp.async.cg.shared.global [%0], [%1], 16;" :: "r"(dst), "l"(src))
#define CP_A16Z(dst, src, sz) \
    asm volatile("cp.async.cg.shared.global [%0], [%1], 16, %2;" :: "r"(dst), "l"(src), "r"(sz))
#define CP_COMMIT() asm volatile("cp.async.commit_group;")
#define CP_WAIT1()  asm volatile("cp.async.wait_group 1;")
#define CP_WAIT0()  asm volatile("cp.async.wait_group 0;")

__device__ __forceinline__ void mma_chunk16(
    uint32_t aT, uint32_t bT,
    const uint32_t aOff[2], const uint32_t bOff[4],
    uint32_t aColSel, uint32_t bColSel, uint32_t xorv,
    float (&acc)[2][8][4])
{
#pragma unroll
    for (int g = 0; g < 4; g++) {
        uint32_t ka = ((uint32_t)(g * 32) + aColSel) ^ xorv;
        uint32_t kb = ((uint32_t)(g * 32) + bColSel) ^ xorv;
        uint32_t af[2][4];
        ldsm4(af[0], aT + aOff[0] + ka);
        ldsm4(af[1], aT + aOff[1] + ka);
#pragma unroll
        for (int p = 0; p < 4; p++) {
            uint32_t bf[4];
            ldsm4(bf, bT + bOff[p] + kb);
            mma16816(acc[0][2 * p],     af[0], bf);
            mma16816(acc[0][2 * p + 1], af[0], bf + 2);
            mma16816(acc[1][2 * p],     af[1], bf);
            mma16816(acc[1][2 * p + 1], af[1], bf + 2);
        }
    }
}

#define MMA_PRECOMP16() \
    const int lane = tid & 31, wid = tid >> 5; \
    const int wm = wid >> 1, wn = wid & 1; \
    const int j8 = lane >> 3, rr = lane & 7; \
    const uint32_t xorv = rr * 16; \
    const uint32_t aColSel = (j8 >> 1) * 16; \
    const uint32_t bColSel = (j8 & 1) * 16; \
    uint32_t aOff[2], bOff[4]; \
    aOff[0] = (wm * 32 +      (j8 & 1) * 8 + rr) * 128; \
    aOff[1] = aOff[0] + 16 * 128; \
    bOff[0] = (wn * 64 +      (j8 >> 1) * 8 + rr) * 128; \
    bOff[1] = bOff[0] + 16 * 128; \
    bOff[2] = bOff[0] + 32 * 128; \
    bOff[3] = bOff[0] + 48 * 128; \
    const int col8 = tid & 7; \
    const int row0 = tid >> 3; \
    float acc[2][8][4]; \
_Pragma("unroll") \
    for (int i_ = 0; i_ < 2; i_++) \
_Pragma("unroll") \
        for (int j_ = 0; j_ < 8; j_++) \
_Pragma("unroll") \
            for (int e_ = 0; e_ < 4; e_++) acc[i_][j_][e_] = 0.f;

#define TILES_SETUP() \
    uint32_t tilesAddr = (sb + 1024 + 1023) & ~1023u; \
    uint32_t stA[NSTAGE], stB[NSTAGE]; \
_Pragma("unroll") \
    for (int s_ = 0; s_ < NSTAGE; s_++) { \
        stA[s_] = tilesAddr + s_ * 2 * TILE16; \
        stB[s_] = stA[s_] + TILE16; \
    }

// 3-stage mainloop: keep up to 2 loads in flight (wait_group 1)
#define TC_MAINLOOP(NC) \
_Pragma("unroll") \
    for (int s_ = 0; s_ < NSTAGE - 1; s_++) { \
        if (s_ < (NC)) issueLoads(s_, s_); \
        CP_COMMIT(); \
    } \
    for (int ci = 0; ci < (NC); ci++) { \
        CP_WAIT1(); \
        __syncthreads(); \
        int nci_ = ci + NSTAGE - 1; \
        if (nci_ < (NC)) issueLoads(nci_, nci_ % NSTAGE); \
        CP_COMMIT(); \
        int st_ = ci % NSTAGE; \
        mma_chunk16(stA[st_], stB[st_], aOff, bOff, aColSel, bColSel, xorv, acc); \
    }

#define STAGE_ROWSTRIDE 136

// ========== tc_attn ==========
template<int RADIUS, bool OUT_T>
__global__ __launch_bounds__(256, 2) void tc_attn(
    const __half* __restrict__ A, const __half* __restrict__ P,
    const float* __restrict__ invsum, const float* __restrict__ gammaPtr,
    const float* __restrict__ Res, float* __restrict__ OutF, __half* __restrict__ OutT)
{
    extern __shared__ char smem[];
    uint32_t sb = smem_u32(smem);
    float* smf = (float*)smem;
    const int tid = threadIdx.x;
    const int bz = blockIdx.z;
    const __half* Ap = A + (size_t)bz * CDIM * NTOT;
    const __half* Pp = P + (size_t)bz * NTOT * NTOT;
    const float* Rp = Res + (size_t)bz * CDIM * NTOT;
    const int rowBase = blockIdx.y * TCM;
    const int colBase = blockIdx.x * TCN;

    TILES_SETUP();
    MMA_PRECOMP16();

    if (tid < TCN) smf[tid] = invsum[(size_t)bz * NTOT + colBase + tid];

    int kStart = 0, kEnd = NTOT;
    if (RADIUS >= 0) {
        int rmLo = colBase / HW, rmHi = (colBase + TCN - 1) / HW;
        int rlo = rmLo - RADIUS; if (rlo < 0) rlo = 0;
        int rhi = rmHi + RADIUS; if (rhi > HW - 1) rhi = HW - 1;
        kStart = (rlo * HW) & ~(TCK - 1);
        kEnd = ((rhi + 1) * HW + TCK - 1) & ~(TCK - 1);
        if (kEnd > NTOT) kEnd = NTOT;
    }
    const int NC = (kEnd - kStart) / TCK;

    auto issueLoads = [&](int ci, int st) {
        const int k0 = kStart + ci * TCK;
#pragma unroll
        for (int s = 0; s < 4; s++) {
            int row = row0 + s * 32;
            uint32_t sw = SWZ(row * 128 + col8 * 16);
            CP_A16(stA[st] + sw, &Ap[(size_t)(rowBase + row) * NTOT + k0 + col8 * 8]);
            CP_A16(stB[st] + sw, &Pp[(size_t)(colBase + row) * NTOT + k0 + col8 * 8]);
        }
    };

    TC_MAINLOOP(NC);

    const float g = *gammaPtr;
    if (OUT_T) {
        CP_WAIT0();
        __syncthreads();
        __half* sm16 = (__half*)(smem + (tilesAddr - sb));
        __half* OpT = OutT + (size_t)bz * NTOT * CDIM;
#pragma unroll
        for (int mt = 0; mt < 2; mt++) {
            int mloc = wm * 32 + mt * 16 + (lane >> 2);
#pragma unroll
            for (int half = 0; half < 2; half++) {
                int cc = mloc + half * 8;
                int c = rowBase + cc;
                size_t ro = (size_t)c * NTOT;
#pragma unroll
                for (int nt = 0; nt < 8; nt++) {
                    int nl = wn * 64 + nt * 8 + (lane & 3) * 2;
                    int n = colBase + nl;
                    float2 res = *(const float2*)&Rp[ro + n];
                    float ox = acc[mt][nt][half * 2 + 0] * (g * smf[nl])     + res.x;
                    float oy = acc[mt][nt][half * 2 + 1] * (g * smf[nl + 1]) + res.y;
                    sm16[nl * STAGE_ROWSTRIDE + cc]       = __float2half_rn(ox);
                    sm16[(nl + 1) * STAGE_ROWSTRIDE + cc] = __float2half_rn(oy);
                }
            }
        }
        __syncthreads();
#pragma unroll
        for (int r = 0; r < 8; r++) {
            int row = r * 16 + (tid >> 4);
            int c8 = (tid & 15) * 8;
            uint4 u = *(const uint4*)&sm16[row * STAGE_ROWSTRIDE + c8];
            *(uint4*)&OpT[(size_t)(colBase + row) * CDIM + rowBase + c8] = u;
        }
    } else {
        float* OpF = OutF + (size_t)bz * CDIM * NTOT;
#pragma unroll
        for (int mt = 0; mt < 2; mt++) {
            int mloc = wm * 32 + mt * 16 + (lane >> 2);
#pragma unroll
            for (int half = 0; half < 2; half++) {
                int c = rowBase + mloc + half * 8;
                size_t ro = (size_t)c * NTOT;
#pragma unroll
                for (int nt = 0; nt < 8; nt++) {
                    int nl = wn * 64 + nt * 8 + (lane & 3) * 2;
                    int n = colBase + nl;
                    float2 res = *(const float2*)&Rp[ro + n];
                    float2 o;
                    o.x = acc[mt][nt][half * 2 + 0] * (g * smf[nl])     + res.x;
                    o.y = acc[mt][nt][half * 2 + 1] * (g * smf[nl + 1]) + res.y;
                    *(float2*)&OpF[ro + n] = o;
                }
            }
        }
    }
}

// ========== tc_conv ==========
__global__ __launch_bounds__(256, 2) void tc_conv(
    const __half* __restrict__ Wr, const __half* __restrict__ Xt,
    const float* __restrict__ bnw, const float* __restrict__ bnb,
    const float* __restrict__ bnm, const float* __restrict__ bnv,
    float* __restrict__ Out, __half* __restrict__ OutT)
{
    extern __shared__ char smem[];
    uint32_t sb = smem_u32(smem);
    const int tid = threadIdx.x;
    const __half* Xp = Xt + (size_t)blockIdx.z * NTOT * CDIM;
    float* Op = Out + (size_t)blockIdx.z * CDIM * NTOT;
    __half* OpT = OutT + (size_t)blockIdx.z * NTOT * CDIM;
    const int rowBase = blockIdx.y * TCM;
    const int colBase = blockIdx.x * TCN;

    TILES_SETUP();
    MMA_PRECOMP16();

    int pys[4], pxs[4];
#pragma unroll
    for (int s = 0; s < 4; s++) {
        int pix = colBase + row0 + s * 32;
        pys[s] = pix / HW; pxs[s] = pix - pys[s] * HW;
    }

    const int NC = KCONV / TCK;   // 72

    auto issueLoads = [&](int ci, int st) {
        const int k0 = ci * TCK;
        const int tap = ci >> 3;
        const int icb = (ci & 7) * TCK;
        const int ky = tap / 3, kx = tap - ky * 3;
#pragma unroll
        for (int s = 0; s < 4; s++) {
            int row = row0 + s * 32;
            uint32_t sw = SWZ(row * 128 + col8 * 16);
            CP_A16(stA[st] + sw, &Wr[(size_t)(rowBase + row) * KCONV + k0 + col8 * 8]);
            int iy = pys[s] + ky - 1, ix = pxs[s] + kx - 1;
            bool ok = (unsigned)iy < HW && (unsigned)ix < HW;
            const __half* src = ok ? &Xp[(size_t)(iy * HW + ix) * CDIM + icb + col8 * 8] : Xp;
            CP_A16Z(stB[st] + sw, src, ok ? 16u : 0u);
        }
    };

    TC_MAINLOOP(NC);

    CP_WAIT0();
    __syncthreads();
    __half* sm16 = (__half*)(smem + (tilesAddr - sb));
#pragma unroll
    for (int mt = 0; mt < 2; mt++) {
        int mloc = wm * 32 + mt * 16 + (lane >> 2);
#pragma unroll
        for (int half = 0; half < 2; half++) {
            int cc = mloc + half * 8;
            int oc = rowBase + cc;
            float scale = bnw[oc] * rsqrtf(bnv[oc] + 1e-5f);
            float shift = bnb[oc] - bnm[oc] * scale;
            size_t ro = (size_t)oc * NTOT;
#pragma unroll
            for (int nt = 0; nt < 8; nt++) {
                int nl = wn * 64 + nt * 8 + (lane & 3) * 2;
                int n = colBase + nl;
                float ox = fmaxf(acc[mt][nt][half * 2 + 0] * scale + shift, 0.f);
                float oy = fmaxf(acc[mt][nt][half * 2 + 1] * scale + shift, 0.f);
                float2 o; o.x = ox; o.y = oy;
                *(float2*)&Op[ro + n] = o;
                sm16[nl * STAGE_ROWSTRIDE + cc]       = __float2half_rn(ox);
                sm16[(nl + 1) * STAGE_ROWSTRIDE + cc] = __float2half_rn(oy);
            }
        }
    }
    __syncthreads();
#pragma unroll
    for (int r = 0; r < 8; r++) {
        int row = r * 16 + (tid >> 4);
        int c8 = (tid & 15) * 8;
        uint4 u = *(const uint4*)&sm16[row * STAGE_ROWSTRIDE + c8];
        *(uint4*)&OpT[(size_t)(colBase + row) * CDIM + rowBase + c8] = u;
    }
}

// ====== tc_nn ======
__global__ __launch_bounds__(256, 2) void tc_nn(
    const __half* __restrict__ W16, const __half* __restrict__ Bt,
    const float* __restrict__ bias, const float* __restrict__ gateSrc,
    __half* __restrict__ Out)
{
    extern __shared__ char smem[];
    uint32_t sb = smem_u32(smem);
    const int tid = threadIdx.x;
    const __half* Bp = Bt + (size_t)blockIdx.z * NTOT * CDIM;
    const float* Gp = gateSrc ? gateSrc + (size_t)blockIdx.z * CDIM * NTOT : (const float*)0;
    __half* Op = Out + (size_t)blockIdx.z * CDIM * NTOT;
    const int rowBase = blockIdx.y * TCM;
    const int colBase = blockIdx.x * TCN;

    TILES_SETUP();
    MMA_PRECOMP16();

    const int NC = CDIM / TCK;   // 8

    auto issueLoads = [&](int ci, int st) {
        const int k0 = ci * TCK;
#pragma unroll
        for (int s = 0; s < 4; s++) {
            int row = row0 + s * 32;
            uint32_t sw = SWZ(row * 128 + col8 * 16);
            CP_A16(stA[st] + sw, &W16[(size_t)(rowBase + row) * CDIM + k0 + col8 * 8]);
            CP_A16(stB[st] + sw, &Bp[(size_t)(colBase + row) * CDIM + k0 + col8 * 8]);
        }
    };

    TC_MAINLOOP(NC);

#pragma unroll
    for (int mt = 0; mt < 2; mt++) {
        int mloc = wm * 32 + mt * 16 + (lane >> 2);
#pragma unroll
        for (int half = 0; half < 2; half++) {
            int d = rowBase + mloc + half * 8;
            float bv = bias[d];
            size_t ro = (size_t)d * NTOT;
#pragma unroll
            for (int nt = 0; nt < 8; nt++) {
                int n = colBase + wn * 64 + nt * 8 + (lane & 3) * 2;
                float ox = acc[mt][nt][half * 2 + 0] + bv;
                float oy = acc[mt][nt][half * 2 + 1] + bv;
                if (Gp) {
                    float2 gv = *(const float2*)&Gp[ro + n];
                    ox = gv.x * (1.f / (1.f + __expf(-ox)));
                    oy = gv.y * (1.f / (1.f + __expf(-oy)));
                }
                *(__half2*)&Op[ro + n] = __floats2half2_rn(ox, oy);
            }
        }
    }
}

// ====== tc_qk ======
__global__ __launch_bounds__(256, 2) void tc_qk(
    const __half* __restrict__ Wqk, const __half* __restrict__ Xqk,
    const float* __restrict__ bq, const float* __restrict__ bk,
    __half* __restrict__ Qh, __half* __restrict__ Kh)
{
    extern __shared__ char smem[];
    uint32_t sb = smem_u32(smem);
    const int tid = threadIdx.x;
    const int bz = blockIdx.z;
    const __half* Bp = Xqk + (size_t)bz * NTOT * KQK;
    __half* qh = Qh + (size_t)bz * NTOT * 128;
    __half* kh = Kh + (size_t)bz * NTOT * 128;
    const int colBase = blockIdx.x * TCN;

    TILES_SETUP();
    MMA_PRECOMP16();

    const int NC = KQK / TCK;   // 24

    auto issueLoads = [&](int ci, int st) {
        const int k0 = ci * TCK;
#pragma unroll
        for (int s = 0; s < 4; s++) {
            int row = row0 + s * 32;
            uint32_t sw = SWZ(row * 128 + col8 * 16);
            CP_A16(stA[st] + sw, &Wqk[(size_t)row * KQK + k0 + col8 * 8]);
            CP_A16(stB[st] + sw, &Bp[(size_t)(colBase + row) * KQK + k0 + col8 * 8]);
        }
    };

    TC_MAINLOOP(NC);

#pragma unroll
    for (int mt = 0; mt < 2; mt++) {
        int mloc = wm * 32 + mt * 16 + (lane >> 2);
#pragma unroll
        for (int half = 0; half < 2; half++) {
            int d = mloc + half * 8;
            bool isQ = d < 64;
            float bv = isQ ? bq[d] : bk[d - 64];
            __half* dst = isQ ? qh : kh;
            int ch = d & 63;
#pragma unroll
            for (int nt = 0; nt < 8; nt++) {
                int n = colBase + wn * 64 + nt * 8 + (lane & 3) * 2;
#pragma unroll
                for (int e = 0; e < 2; e++) {
                    float val = acc[mt][nt][half * 2 + e] + bv;
                    __half hi = __float2half_rn(val);
                    __half lo = __float2half_rn(val - __half2float(hi));
                    dst[(size_t)(n + e) * 128 + ch]      = hi;
                    dst[(size_t)(n + e) * 128 + 64 + ch] = lo;
                }
            }
        }
    }
}

// ====== tc_energy ======
__global__ __launch_bounds__(256, 2) void tc_energy(
    const __half* __restrict__ Qh, const __half* __restrict__ Kh,
    float* __restrict__ E)
{
    extern __shared__ char smem[];
    uint32_t sb = smem_u32(smem);
    const int tid = threadIdx.x;
    const __half* Ap = Qh + (size_t)blockIdx.z * NTOT * 128;
    const __half* Bp = Kh + (size_t)blockIdx.z * NTOT * 128;
    float* Ep = E + (size_t)blockIdx.z * NTOT * NTOT;
    const int rowBase = blockIdx.y * TCM;
    const int colBase = blockIdx.x * TCN;

    TILES_SETUP();
    MMA_PRECOMP16();

    const int NC = 2;

    auto issueLoads = [&](int ci, int st) {
        const int k0 = ci * TCK;
#pragma unroll
        for (int s = 0; s < 4; s++) {
            int row = row0 + s * 32;
            uint32_t sw = SWZ(row * 128 + col8 * 16);
            CP_A16(stA[st] + sw, &Ap[(size_t)(rowBase + row) * 128 + k0 + col8 * 8]);
            CP_A16(stB[st] + sw, &Bp[(size_t)(colBase + row) * 128 + k0 + col8 * 8]);
        }
    };

    TC_MAINLOOP(NC);

#pragma unroll
    for (int mt = 0; mt < 2; mt++) {
        int mloc = wm * 32 + mt * 16 + (lane >> 2);
#pragma unroll
        for (int half = 0; half < 2; half++) {
            int m = rowBase + mloc + half * 8;
            size_t ro = (size_t)m * NTOT;
#pragma unroll
            for (int nt = 0; nt < 8; nt++) {
                int n = colBase + wn * 64 + nt * 8 + (lane & 3) * 2;
                float2 o;
                o.x = acc[mt][nt][half * 2 + 0];
                o.y = acc[mt][nt][half * 2 + 1];
                *(float2*)&Ep[ro + n] = o;
            }
        }
    }
}

// ---------------- transpose: fp32 [C][N] -> xt fp16 [N][C] + xqk [N][1536] ----------------
__global__ __launch_bounds__(256) void transpose_c2n(
    const float* __restrict__ X, __half* __restrict__ Xt, __half* __restrict__ Xqk)
{
    __shared__ float tile[32][33];
    const int b = blockIdx.z;
    const int n0 = blockIdx.x * 32, c0 = blockIdx.y * 32;
    const int tx = threadIdx.x & 31, ty = threadIdx.x >> 5;
    const float* Xp = X + (size_t)b * CDIM * NTOT;
    __half* Tp = Xt + (size_t)b * NTOT * CDIM;
    __half* Qp = Xqk + (size_t)b * NTOT * KQK;
#pragma unroll
    for (int k = 0; k < 4; k++)
        tile[ty + 8 * k][tx] = Xp[(size_t)(c0 + ty + 8 * k) * NTOT + n0 + tx];
    __syncthreads();
#pragma unroll
    for (int k = 0; k < 4; k++) {
        float val = tile[tx][ty + 8 * k];
        __half hi = __float2half_rn(val);
        __half lo = __float2half_rn(val - __half2float(hi));
        int n = n0 + ty + 8 * k, c = c0 + tx;
        Tp[(size_t)n * CDIM + c] = hi;
        size_t qb = (size_t)n * KQK + c;
        Qp[qb] = hi;
        Qp[qb + 512] = lo;
        Qp[qb + 1024] = hi;
    }
}

// ---------------- prep: all weight conversions in one launch ----------------
__global__ __launch_bounds__(256) void prep_all(
    const float* __restrict__ conv1_w, const float* __restrict__ conv2_w,
    const float* __restrict__ Wv, const float* __restrict__ sig1_w,
    const float* __restrict__ sig2_w,
    const float* __restrict__ Wq, const float* __restrict__ Wk,
    __half* __restrict__ w1r, __half* __restrict__ w2r,
    __half* __restrict__ wv16, __half* __restrict__ ws1, __half* __restrict__ ws2,
    __half* __restrict__ wqk)
{
    const int seg = blockIdx.y;
    const int idx = blockIdx.x * 256 + threadIdx.x;
    if (seg < 2) {
        if (idx < CDIM * KCONV) {
            const float* W = seg == 0 ? conv1_w : conv2_w;
            __half* Wr = seg == 0 ? w1r : w2r;
            int oc = idx / KCONV, kk = idx - oc * KCONV;
            int tap = kk >> 9, ic = kk & 511;
            Wr[idx] = __float2half_rn(W[(size_t)oc * KCONV + ic * 9 + tap]);
        }
    } else if (seg < 5) {
        if (idx < CDIM * CDIM) {
            const float* W = seg == 2 ? Wv : (seg == 3 ? sig1_w : sig2_w);
            __half* O = seg == 2 ? wv16 : (seg == 3 ? ws1 : ws2);
            O[idx] = __float2half_rn(W[idx]);
        }
    } else {
        if (idx < 128 * 512) {
            int d = idx >> 9, c = idx & 511;
            float w = d < 64 ? Wq[(size_t)d * CDIM + c] : Wk[(size_t)(d - 64) * CDIM + c];
            __half hi = __float2half_rn(w);
            __half lo = __float2half_rn(w - __half2float(hi));
            size_t base = (size_t)d * KQK + c;
            wqk[base] = hi;
            wqk[base + 512] = hi;
            wqk[base + 1024] = lo;
        }
    }
}

// ---- softmax: 3 shifts, band-limited ph1/ph2 writes ----
__global__ __launch_bounds__(256) void softmax_rows3(
    const float* __restrict__ P,
    __half* __restrict__ Ph0, __half* __restrict__ Ph1, __half* __restrict__ Ph2,
    float* __restrict__ inv0, float* __restrict__ inv1, float* __restrict__ inv2)
{
    __shared__ float rowv[NTOT];
    __shared__ float red[256];
    const int row = blockIdx.x, b = blockIdx.y, tid = threadIdx.x;
    const size_t roff = ((size_t)b * NTOT + row) * NTOT;
    const float* p = P + roff;

    for (int i = tid; i < NTOT / 4; i += 256)
        ((float4*)rowv)[i] = ((const float4*)p)[i];
    __syncthreads();

    const int rm = row / HW, cm = row - rm * HW;
    int w1lo = (rm - 6 - 4) * HW;  w1lo = w1lo < 0 ? 0 : (w1lo & ~63);
    int w1hi = ((rm + 6 + 5) * HW + 63) & ~63; if (w1hi > NTOT) w1hi = NTOT;
    int w2lo = (rm - 12 - 4) * HW; w2lo = w2lo < 0 ? 0 : (w2lo & ~63);
    int w2hi = ((rm + 12 + 5) * HW + 63) & ~63; if (w2hi > NTOT) w2hi = NTOT;

    float m0 = -1e30f, m6 = -1e30f, m12 = -1e30f;
    for (int i = tid; i < NTOT / 4; i += 256) {
        float4 v4 = ((const float4*)rowv)[i];
        const float* v = (const float*)&v4;
        int n0 = i * 4;
#pragma unroll
        for (int e = 0; e < 4; e++) {
            int n = n0 + e;
            float v1 = v[e];
            m0 = fmaxf(m0, v1);
            int rn = n / HW, cn = n - rn * HW;
            int dr = rm - rn; dr = dr < 0 ? -dr : dr;
            int dc = cm - cn; dc = dc < 0 ? -dc : dc;
            int d = dr > dc ? dr : dc;
            if (d <= 12) { m12 = fmaxf(m12, v1); if (d <= 6) m6 = fmaxf(m6, v1); }
        }
    }
    red[tid] = m0; __syncthreads();
    for (int s = 128; s > 0; s >>= 1) { if (tid < s) red[tid] = fmaxf(red[tid], red[tid + s]); __syncthreads(); }
    m0 = red[0]; __syncthreads();
    red[tid] = m6; __syncthreads();
    for (int s = 128; s > 0; s >>= 1) { if (tid < s) red[tid] = fmaxf(red[tid], red[tid + s]); __syncthreads(); }
    m6 = red[0]; __syncthreads();
    red[tid] = m12; __syncthreads();
    for (int s = 128; s > 0; s >>= 1) { if (tid < s) red[tid] = fmaxf(red[tid], red[tid + s]); __syncthreads(); }
    m12 = red[0]; __syncthreads();

    float s0 = 0.f, s1 = 0.f, s2 = 0.f;
    for (int i = tid; i < NTOT / 4; i += 256) {
        float4 v4 = ((const float4*)rowv)[i];
        const float* v = (const float*)&v4;
        int n0 = i * 4;
        __half h0a[4], h1a[4], h2a[4];
#pragma unroll
        for (int e = 0; e < 4; e++) {
            int n = n0 + e;
            float v1 = v[e];
            __half h0 = __float2half_rn(__expf(v1 - m0));
            h0a[e] = h0;
            s0 += __half2float(h0);
            int rn = n / HW, cn = n - rn * HW;
            int dr = rm - rn; dr = dr < 0 ? -dr : dr;
            int dc = cm - cn; dc = dc < 0 ? -dc : dc;
            int d = dr > dc ? dr : dc;
            __half h1 = __ushort_as_half(0), h2 = __ushort_as_half(0);
            if (d <= 12) {
                h2 = __float2half_rn(__expf(v1 - m12));
                s2 += __half2float(h2);
                if (d <= 6) { h1 = __float2half_rn(__expf(v1 - m6)); s1 += __half2float(h1); }
            }
            h1a[e] = h1; h2a[e] = h2;
        }
        *(uint2*)&Ph0[roff + n0] = *(uint2*)h0a;
        if (n0 >= w1lo && n0 < w1hi) *(uint2*)&Ph1[roff + n0] = *(uint2*)h1a;
        if (n0 >= w2lo && n0 < w2hi) *(uint2*)&Ph2[roff + n0] = *(uint2*)h2a;
    }
    red[tid] = s0; __syncthreads();
    for (int s = 128; s > 0; s >>= 1) { if (tid < s) red[tid] += red[tid + s]; __syncthreads(); }
    if (tid == 0) inv0[(size_t)b * NTOT + row] = 1.f / red[0];
    __syncthreads();
    red[tid] = s1; __syncthreads();
    for (int s = 128; s > 0; s >>= 1) { if (tid < s) red[tid] += red[tid + s]; __syncthreads(); }
    if (tid == 0) inv1[(size_t)b * NTOT + row] = 1.f / red[0];
    __syncthreads();
    red[tid] = s2; __syncthreads();
    for (int s = 128; s > 0; s >>= 1) { if (tid < s) red[tid] += red[tid + s]; __syncthreads(); }
    if (tid == 0) inv2[(size_t)b * NTOT + row] = 1.f / red[0];
}

// ---------------- launch ----------------
extern "C" void kernel_launch(void* const* d_in, const int* in_sizes, int n_in,
                              void* d_out, int out_size)
{
    const float* x       = (const float*)d_in[0];
    const float* Wq      = (const float*)d_in[1];
    const float* bq      = (const float*)d_in[2];
    const float* Wk      = (const float*)d_in[3];
    const float* bk      = (const float*)d_in[4];
    const float* Wv      = (const float*)d_in[5];
    const float* bv      = (const float*)d_in[6];
    const float* conv1_w = (const float*)d_in[7];
    const float* bn1_w   = (const float*)d_in[8];
    const float* bn1_b   = (const float*)d_in[9];
    const float* bn1_m   = (const float*)d_in[10];
    const float* bn1_v   = (const float*)d_in[11];
    const float* conv2_w = (const float*)d_in[12];
    const float* bn2_w   = (const float*)d_in[13];
    const float* bn2_b   = (const float*)d_in[14];
    const float* bn2_m   = (const float*)d_in[15];
    const float* bn2_v   = (const float*)d_in[16];
    const float* sig1_w  = (const float*)d_in[17];
    const float* sig1_b  = (const float*)d_in[18];
    const float* sig2_w  = (const float*)d_in[19];
    const float* sig2_b  = (const float*)d_in[20];
    const float* gamma   = (const float*)d_in[21];
    const float* gamma1  = (const float*)d_in[22];
    const float* gamma2  = (const float*)d_in[23];

    float *p, *i0, *i1, *i2, *t1, *t2;
    __half *qh, *kh, *ph0, *ph1, *ph2, *v, *s, *xt, *xqk, *yt, *t1t, *t2t;
    __half *w1r, *w2r, *wv16, *ws1, *ws2, *wqk;
    cudaGetSymbolAddress((void**)&qh,  g_qh);
    cudaGetSymbolAddress((void**)&kh,  g_kh);
    cudaGetSymbolAddress((void**)&p,   g_p);
    cudaGetSymbolAddress((void**)&ph0, g_ph0);
    cudaGetSymbolAddress((void**)&ph1, g_ph1);
    cudaGetSymbolAddress((void**)&ph2, g_ph2);
    cudaGetSymbolAddress((void**)&v,   g_v);
    cudaGetSymbolAddress((void**)&s,   g_s);
    cudaGetSymbolAddress((void**)&i0,  g_inv0);
    cudaGetSymbolAddress((void**)&i1,  g_inv1);
    cudaGetSymbolAddress((void**)&i2,  g_inv2);
    cudaGetSymbolAddress((void**)&xt,  g_xt);
    cudaGetSymbolAddress((void**)&xqk, g_xqk);
    cudaGetSymbolAddress((void**)&yt,  g_yt);
    cudaGetSymbolAddress((void**)&t1,  g_t1);
    cudaGetSymbolAddress((void**)&t1t, g_t1t);
    cudaGetSymbolAddress((void**)&t2,  g_t2);
    cudaGetSymbolAddress((void**)&t2t, g_t2t);
    cudaGetSymbolAddress((void**)&w1r, g_w1r);
    cudaGetSymbolAddress((void**)&w2r, g_w2r);
    cudaGetSymbolAddress((void**)&wv16, g_wv16);
    cudaGetSymbolAddress((void**)&ws1, g_ws1);
    cudaGetSymbolAddress((void**)&ws2, g_ws2);
    cudaGetSymbolAddress((void**)&wqk, g_wqk);

    cudaFuncSetAttribute((const void*)tc_attn<-1, true>,  cudaFuncAttributeMaxDynamicSharedMemorySize, SMEM_TC_SZ);
    cudaFuncSetAttribute((const void*)tc_attn<6, true>,   cudaFuncAttributeMaxDynamicSharedMemorySize, SMEM_TC_SZ);
    cudaFuncSetAttribute((const void*)tc_attn<12, false>, cudaFuncAttributeMaxDynamicSharedMemorySize, SMEM_TC_SZ);
    cudaFuncSetAttribute((const void*)tc_conv,            cudaFuncAttributeMaxDynamicSharedMemorySize, SMEM_TC_SZ);
    cudaFuncSetAttribute((const void*)tc_nn,              cudaFuncAttributeMaxDynamicSharedMemorySize, SMEM_TC_SZ);
    cudaFuncSetAttribute((const void*)tc_qk,              cudaFuncAttributeMaxDynamicSharedMemorySize, SMEM_TC_SZ);
    cudaFuncSetAttribute((const void*)tc_energy,          cudaFuncAttributeMaxDynamicSharedMemorySize, SMEM_TC_SZ);

    const dim3 blk(256);
    const dim3 gTC(NTOT / TCN, CDIM / TCM, BDIM);    // (18, 4, 4)
    const dim3 gQK(NTOT / TCN, 1, BDIM);
    const dim3 gEn(NTOT / TCN, NTOT / TCM, BDIM);    // (18, 18, 4)
    const dim3 gTr(NTOT / 32, CDIM / 32, BDIM);
    const dim3 gPrep((CDIM * KCONV + 255) / 256, 6);

    // prep
    transpose_c2n<<<gTr, blk>>>(x, xt, xqk);
    prep_all<<<gPrep, blk>>>(conv1_w, conv2_w, Wv, sig1_w, sig2_w, Wq, Wk,
                             w1r, w2r, wv16, ws1, ws2, wqk);

    // q/k (tensor, double hi/lo), v
    tc_qk<<<gQK, blk, SMEM_TC_SZ>>>(wqk, xqk, bq, bk, qh, kh);
    tc_nn<<<gTC, blk, SMEM_TC_SZ>>>(wv16, xt, bv, (const float*)0, v);

    // energy + 3-shift softmax
    tc_energy<<<gEn, blk, SMEM_TC_SZ>>>(qh, kh, p);
    softmax_rows3<<<dim3(NTOT, BDIM), blk>>>(p, ph0, ph1, ph2, i0, i1, i2);

    // stage 0
    tc_attn<-1, true><<<gTC, blk, SMEM_TC_SZ>>>(v, ph0, i0, gamma, x, (float*)0, yt);
    tc_conv<<<gTC, blk, SMEM_TC_SZ>>>(w1r, yt, bn1_w, bn1_b, bn1_m, bn1_v, t1, t1t);

    // stage 1
    tc_nn<<<gTC, blk, SMEM_TC_SZ>>>(ws1, t1t, sig1_b, t1, s);
    tc_attn<6, true><<<gTC, blk, SMEM_TC_SZ>>>(s, ph1, i1, gamma1, t1, (float*)0, yt);
    tc_conv<<<gTC, blk, SMEM_TC_SZ>>>(w2r, yt, bn2_w, bn2_b, bn2_m, bn2_v, t2, t2t);

    // stage 2
    tc_nn<<<gTC, blk, SMEM_TC_SZ>>>(ws2, t2t, sig2_b, t2, s);
    tc_attn<12, false><<<gTC, blk, SMEM_TC_SZ>>>(s, ph2, i2, gamma2, t2, (float*)d_out, (__half*)0);
}